// round 8
// baseline (speedup 1.0000x reference)
#include <cuda_runtime.h>
#include <cuda_bf16.h>
#include <cstdint>

#define SEQ   2048
#define EMB   768
#define NH    12
#define HD    64
#define BATCH 2
#define MROWS (BATCH * SEQ)   // 4096
#define NQKV  (3 * EMB)       // 2304

typedef __nv_bfloat16 bf16;

// ---------------- scratch (static device arrays; no allocation) -------------
__device__ bf16 g_xhi[MROWS * EMB], g_xlo[MROWS * EMB];
__device__ bf16 g_whi[4][EMB * EMB], g_wlo[4][EMB * EMB];   // q,k,v,o
__device__ bf16 g_qhi[BATCH * NH * SEQ * HD], g_qlo[BATCH * NH * SEQ * HD];
__device__ bf16 g_khi[BATCH * NH * SEQ * HD], g_klo[BATCH * NH * SEQ * HD];
__device__ bf16 g_vhi[BATCH * NH * SEQ * HD], g_vlo[BATCH * NH * SEQ * HD];
__device__ bf16 g_aohi[MROWS * EMB], g_aolo[MROWS * EMB];

// ---------------- small helpers ----------------
__device__ __forceinline__ uint32_t cvt_bf2(float lo, float hi) {
    uint32_t r;
    asm("cvt.rn.bf16x2.f32 %0, %1, %2;" : "=r"(r) : "f"(hi), "f"(lo));
    return r;
}
__device__ __forceinline__ float bflo(uint32_t p) { return __uint_as_float(p << 16); }
__device__ __forceinline__ float bfhi(uint32_t p) { return __uint_as_float(p & 0xffff0000u); }
__device__ __forceinline__ float ex2f(float x) {
    float y;
    asm("ex2.approx.ftz.f32 %0, %1;" : "=f"(y) : "f"(x));
    return y;
}
__device__ __forceinline__ void ldsm4(uint32_t& r0, uint32_t& r1,
                                      uint32_t& r2, uint32_t& r3, uint32_t addr)
{
    asm volatile("ldmatrix.sync.aligned.m8n8.x4.shared.b16 {%0,%1,%2,%3}, [%4];"
                 : "=r"(r0), "=r"(r1), "=r"(r2), "=r"(r3) : "r"(addr));
}
__device__ __forceinline__ void ldsm4t(uint32_t& r0, uint32_t& r1,
                                       uint32_t& r2, uint32_t& r3, uint32_t addr)
{
    asm volatile("ldmatrix.sync.aligned.m8n8.x4.trans.shared.b16 {%0,%1,%2,%3}, [%4];"
                 : "=r"(r0), "=r"(r1), "=r"(r2), "=r"(r3) : "r"(addr));
}
__device__ __forceinline__ void mma16816(float c[4], const uint32_t a[4],
                                         uint32_t b0, uint32_t b1)
{
    asm volatile(
        "mma.sync.aligned.m16n8k16.row.col.f32.bf16.bf16.f32 "
        "{%0,%1,%2,%3}, {%4,%5,%6,%7}, {%8,%9}, {%0,%1,%2,%3};"
        : "+f"(c[0]), "+f"(c[1]), "+f"(c[2]), "+f"(c[3])
        : "r"(a[0]), "r"(a[1]), "r"(a[2]), "r"(a[3]), "r"(b0), "r"(b1));
}
__device__ __forceinline__ void cp16(uint32_t saddr, const void* gaddr)
{
    asm volatile("cp.async.cg.shared.global [%0], [%1], 16;"
                 :: "r"(saddr), "l"(gaddr));
}
template<int N>
__device__ __forceinline__ void cp_wait()
{
    asm volatile("cp.async.wait_group %0;" :: "n"(N));
}

// =================================================================
// fp32 -> bf16 hi/lo split conversions (float4 vectorized)
// =================================================================
__global__ __launch_bounds__(256) void split4_kernel(
    const float4* __restrict__ src, uint2* __restrict__ hi,
    uint2* __restrict__ lo, int n4)
{
    int i = blockIdx.x * 256 + threadIdx.x;
    if (i < n4) {
        float4 v = src[i];
        uint32_t h0 = cvt_bf2(v.x, v.y);
        uint32_t h1 = cvt_bf2(v.z, v.w);
        uint32_t l0 = cvt_bf2(v.x - bflo(h0), v.y - bfhi(h0));
        uint32_t l1 = cvt_bf2(v.z - bflo(h1), v.w - bfhi(h1));
        hi[i] = make_uint2(h0, h1);
        lo[i] = make_uint2(l0, l1);
    }
}

__global__ __launch_bounds__(256) void split_w4_kernel(
    const float* __restrict__ wq, const float* __restrict__ wk,
    const float* __restrict__ wv, const float* __restrict__ wo)
{
    int z = blockIdx.z;
    const float4* src = (const float4*)((z == 0) ? wq : (z == 1) ? wk :
                                        (z == 2) ? wv : wo);
    uint2* hi = (uint2*)g_whi[z];
    uint2* lo = (uint2*)g_wlo[z];
    int i = blockIdx.x * 256 + threadIdx.x;
    if (i < EMB * EMB / 4) {
        float4 v = src[i];
        uint32_t h0 = cvt_bf2(v.x, v.y);
        uint32_t h1 = cvt_bf2(v.z, v.w);
        uint32_t l0 = cvt_bf2(v.x - bflo(h0), v.y - bfhi(h0));
        uint32_t l1 = cvt_bf2(v.z - bflo(h1), v.w - bfhi(h1));
        hi[i] = make_uint2(h0, h1);
        lo[i] = make_uint2(l0, l1);
    }
}

// =================================================================
// bf16-split MMA GEMM (BK=32, 3-stage cp.async ring, one sync/iter)
// — round-6 configuration, verified.
// =================================================================
#define BM 128
#define BN 128
#define BK 32
#define LDSK 40
#define NKB (EMB / BK)   // 24
#define NIT (3 * NKB)    // 72
#define BUF_ELEMS (BM * LDSK)        // 5120 bf16
#define GSTAGE_B (BUF_ELEMS * 2)     // 10240 bytes per matrix per stage
#define GEMM_SMEM (6 * GSTAGE_B)     // 61440

__device__ __forceinline__ void gemm_issue(
    int it, int buf,
    const bf16* __restrict__ Ahi, const bf16* __restrict__ Alo,
    const bf16* __restrict__ Bhi, const bf16* __restrict__ Blo,
    uint32_t asb, uint32_t bsb, int m0, int n0, int srow, int schk)
{
    int s_ = it / NKB;
    int k0_ = (it - s_ * NKB) * BK;
    const bf16* Ap = (s_ == 2) ? Alo : Ahi;
    const bf16* Bp = (s_ == 1) ? Blo : Bhi;
    uint32_t sa = asb + (uint32_t)buf * GSTAGE_B;
    uint32_t sb = bsb + (uint32_t)buf * GSTAGE_B;
    cp16(sa + (srow * LDSK + schk) * 2,
         Ap + (size_t)(m0 + srow) * EMB + k0_ + schk);
    cp16(sa + ((srow + 64) * LDSK + schk) * 2,
         Ap + (size_t)(m0 + srow + 64) * EMB + k0_ + schk);
    cp16(sb + (srow * LDSK + schk) * 2,
         Bp + (size_t)(n0 + srow) * EMB + k0_ + schk);
    cp16(sb + ((srow + 64) * LDSK + schk) * 2,
         Bp + (size_t)(n0 + srow + 64) * EMB + k0_ + schk);
    asm volatile("cp.async.commit_group;");
}

template<int REMAP>
__device__ __forceinline__ void mma_gemm_body(
    const bf16* __restrict__ Ahi, const bf16* __restrict__ Alo,
    const bf16* __restrict__ Bhi, const bf16* __restrict__ Blo,
    const float* __restrict__ bias, float* __restrict__ C,
    bf16* __restrict__ Chi, bf16* __restrict__ Clo,
    int m0, int n0, float scale)
{
    extern __shared__ char dsm[];
    const uint32_t asb = (uint32_t)__cvta_generic_to_shared(dsm);
    const uint32_t bsb = asb + 3 * GSTAGE_B;

    const int tid = threadIdx.x;
    const int lane = tid & 31;
    const int wid = tid >> 5;
    const int wm = wid >> 2;
    const int wn = wid & 3;

    float acc[4][4][4];
#pragma unroll
    for (int i = 0; i < 4; i++)
#pragma unroll
        for (int j = 0; j < 4; j++)
#pragma unroll
            for (int t = 0; t < 4; t++) acc[i][j][t] = 0.f;

    const int srow = tid >> 2;
    const int schk = (tid & 3) * 8;

    const int laRow = wm * 64 + (lane & 15);
    const int laCol = (lane >> 4) * 8;
    const int lbRow = wn * 32 + ((lane >> 4) << 3) + (lane & 7);
    const int lbCol = ((lane >> 3) & 1) * 8;

    gemm_issue(0, 0, Ahi, Alo, Bhi, Blo, asb, bsb, m0, n0, srow, schk);
    gemm_issue(1, 1, Ahi, Alo, Bhi, Blo, asb, bsb, m0, n0, srow, schk);

    int st = 0;
    for (int it = 0; it < NIT; it++) {
        if (it + 1 < NIT) cp_wait<1>(); else cp_wait<0>();
        __syncthreads();
        if (it + 2 < NIT) {
            int b2 = st + 2; if (b2 >= 3) b2 -= 3;
            gemm_issue(it + 2, b2, Ahi, Alo, Bhi, Blo, asb, bsb,
                       m0, n0, srow, schk);
        }

        const uint32_t sa = asb + (uint32_t)st * GSTAGE_B;
        const uint32_t sb = bsb + (uint32_t)st * GSTAGE_B;

#pragma unroll
        for (int ks = 0; ks < 2; ks++) {
            uint32_t a[4][4];
#pragma unroll
            for (int mt = 0; mt < 4; mt++)
                ldsm4(a[mt][0], a[mt][1], a[mt][2], a[mt][3],
                      sa + (uint32_t)(((laRow + mt * 16) * LDSK) + ks * 16 + laCol) * 2);
            uint32_t b[2][4];
#pragma unroll
            for (int p = 0; p < 2; p++)
                ldsm4(b[p][0], b[p][1], b[p][2], b[p][3],
                      sb + (uint32_t)(((lbRow + p * 16) * LDSK) + ks * 16 + lbCol) * 2);
#pragma unroll
            for (int mt = 0; mt < 4; mt++)
#pragma unroll
                for (int nt = 0; nt < 4; nt++)
                    mma16816(acc[mt][nt], a[mt],
                             b[nt >> 1][(nt & 1) * 2], b[nt >> 1][(nt & 1) * 2 + 1]);
        }
        st = (st + 1 == 3) ? 0 : st + 1;
    }

    const int er = lane >> 2;
    const int ec = (lane & 3) * 2;
#pragma unroll
    for (int mt = 0; mt < 4; mt++) {
        int m = m0 + wm * 64 + mt * 16 + er;
#pragma unroll
        for (int nt = 0; nt < 4; nt++) {
            int n = n0 + wn * 32 + nt * 8 + ec;
            float b0 = bias[n], b1 = bias[n + 1];
            float v00 = (acc[mt][nt][0] + b0) * scale;
            float v01 = (acc[mt][nt][1] + b1) * scale;
            float v10 = (acc[mt][nt][2] + b0) * scale;
            float v11 = (acc[mt][nt][3] + b1) * scale;
            if (REMAP) {
                int h = n >> 6, d = n & 63;
                int bb0 = m >> 11, s0 = m & 2047;
                int bb1 = (m + 8) >> 11, s1 = (m + 8) & 2047;
                size_t p0 = (((size_t)(bb0 * NH + h)) * SEQ + s0) * HD + d;
                size_t p1 = (((size_t)(bb1 * NH + h)) * SEQ + s1) * HD + d;
                uint32_t hp = cvt_bf2(v00, v01);
                uint32_t lp = cvt_bf2(v00 - bflo(hp), v01 - bfhi(hp));
                *(uint32_t*)&Chi[p0] = hp;
                *(uint32_t*)&Clo[p0] = lp;
                hp = cvt_bf2(v10, v11);
                lp = cvt_bf2(v10 - bflo(hp), v11 - bfhi(hp));
                *(uint32_t*)&Chi[p1] = hp;
                *(uint32_t*)&Clo[p1] = lp;
            } else {
                *(float2*)&C[(size_t)m * EMB + n] = make_float2(v00, v01);
                *(float2*)&C[(size_t)(m + 8) * EMB + n] = make_float2(v10, v11);
            }
        }
    }
}

__global__ __launch_bounds__(256, 2) void qkv_mma(
    const float* __restrict__ bq, const float* __restrict__ bk,
    const float* __restrict__ bv)
{
    int m0 = blockIdx.y * BM;
    int ng = blockIdx.x * BN;
    int sel = ng / EMB;
    int n0 = ng - sel * EMB;
    const bf16* Bhi = g_whi[sel];
    const bf16* Blo = g_wlo[sel];
    const float* bias = (sel == 0) ? bq : (sel == 1) ? bk : bv;
    bf16* Chi = (sel == 0) ? g_qhi : (sel == 1) ? g_khi : g_vhi;
    bf16* Clo = (sel == 0) ? g_qlo : (sel == 1) ? g_klo : g_vlo;
    float scale = (sel == 0) ? 0.125f * 1.4426950408889634f : 1.0f;
    mma_gemm_body<1>(g_xhi, g_xlo, Bhi, Blo, bias, nullptr, Chi, Clo,
                     m0, n0, scale);
}

__global__ __launch_bounds__(256, 2) void out_mma(
    const float* __restrict__ bo, float* __restrict__ out)
{
    mma_gemm_body<0>(g_aohi, g_aolo, g_whi[3], g_wlo[3], bo, out,
                     nullptr, nullptr, blockIdx.y * BM, blockIdx.x * BN, 1.0f);
}

// =================================================================
// Tensor-core flash attention, fixed-base softmax — round-7
// configuration, verified 129us / tensor 53.6%.
// =================================================================
#define STR 72
#define KV_STAGE_B (256 * STR * 2)       // 36864
#define ATT_SMEM (3 * KV_STAGE_B)        // 110592

__device__ __forceinline__ void kv_issue(uint32_t sb, int buf, int kbase,
                                         const bf16* const kvsrc[4], int tid)
{
    uint32_t base = sb + (uint32_t)buf * KV_STAGE_B;
#pragma unroll
    for (int i = 0; i < 8; i++) {
        int c = i * 256 + tid;
        int row = (c >> 3) & 63;
        int ch = (c & 7) * 8;
        cp16(base + (uint32_t)(((i >> 1) * 64 + row) * STR + ch) * 2,
             kvsrc[i >> 1] + (size_t)(kbase + row) * HD + ch);
    }
    asm volatile("cp.async.commit_group;");
}

__global__ __launch_bounds__(256, 2) void attn_mma(
    const bf16* __restrict__ Qhi_g, const bf16* __restrict__ Qlo_g,
    const bf16* __restrict__ Khi_g, const bf16* __restrict__ Klo_g,
    const bf16* __restrict__ Vhi_g, const bf16* __restrict__ Vlo_g,
    bf16* __restrict__ AOhi, bf16* __restrict__ AOlo)
{
    extern __shared__ char dsm[];
    const uint32_t sb = (uint32_t)__cvta_generic_to_shared(dsm);

    const int bid = blockIdx.x;
    const int qt = (SEQ / 128) - 1 - bid / (BATCH * NH);
    const int bh = bid % (BATCH * NH);
    const int qbase = qt * 128;
    const int nkt = 2 * qt + 2;

    const int tid = threadIdx.x;
    const int lane = tid & 31;
    const int wid = tid >> 5;
    const int wr = wid * 16;

    const size_t hoff = (size_t)bh * SEQ * HD;
    const bf16* qsrc[2] = {Qhi_g + hoff, Qlo_g + hoff};
    const bf16* kvsrc[4] = {Khi_g + hoff, Klo_g + hoff, Vhi_g + hoff, Vlo_g + hoff};

#pragma unroll
    for (int i = 0; i < 8; i++) {
        int c = i * 256 + tid;
        int row = (c >> 3) & 127;
        int ch = (c & 7) * 8;
        cp16(sb + (uint32_t)(((i >> 2) * 128 + row) * STR + ch) * 2,
             qsrc[i >> 2] + (size_t)(qbase + row) * HD + ch);
    }
    asm volatile("cp.async.commit_group;");
    cp_wait<0>();
    __syncthreads();

    uint32_t qh[4][4], ql[4][4];
    {
        int arow = wr + (lane & 15);
        int acol = (lane >> 4) * 8;
#pragma unroll
        for (int ks = 0; ks < 4; ks++) {
            ldsm4(qh[ks][0], qh[ks][1], qh[ks][2], qh[ks][3],
                  sb + (uint32_t)(arow * STR + ks * 16 + acol) * 2);
            ldsm4(ql[ks][0], ql[ks][1], ql[ks][2], ql[ks][3],
                  sb + (uint32_t)((128 + arow) * STR + ks * 16 + acol) * 2);
        }
    }
    __syncthreads();

    float o[8][4];
#pragma unroll
    for (int i = 0; i < 8; i++)
#pragma unroll
        for (int j = 0; j < 4; j++) o[i][j] = 0.f;
    float rs0 = 0.f, rs1 = 0.f;

    kv_issue(sb, 0, 0, kvsrc, tid);
    kv_issue(sb, 1, 64, kvsrc, tid);

    const int brow = (lane & 7) + ((lane >> 4) << 3);
    const int bcol = ((lane >> 3) & 1) * 8;
    const int vrow = (lane & 7) + (((lane >> 3) & 1) << 3);
    const int vcol = (lane >> 4) * 8;

    int st = 0;
    for (int kt = 0; kt < nkt; kt++) {
        if (kt + 1 < nkt) cp_wait<1>(); else cp_wait<0>();
        __syncthreads();
        if (kt + 2 < nkt) {
            int b2 = st + 2; if (b2 >= 3) b2 -= 3;
            kv_issue(sb, b2, (kt + 2) * 64, kvsrc, tid);
        }

        const uint32_t kvb = sb + (uint32_t)st * KV_STAGE_B;
        const uint32_t Khi_s = kvb;
        const uint32_t Klo_s = kvb + 64 * STR * 2;
        const uint32_t Vhi_s = kvb + 128 * STR * 2;
        const uint32_t Vlo_s = kvb + 192 * STR * 2;
        const int kbase = kt * 64;

        float s[8][4];
#pragma unroll
        for (int i = 0; i < 8; i++)
#pragma unroll
            for (int j = 0; j < 4; j++) s[i][j] = 0.f;

#pragma unroll
        for (int ks = 0; ks < 4; ks++) {
            uint32_t bb[4][4];
#pragma unroll
            for (int ng = 0; ng < 4; ng++)
                ldsm4(bb[ng][0], bb[ng][1], bb[ng][2], bb[ng][3],
                      Khi_s + (uint32_t)((16 * ng + brow) * STR + 16 * ks + bcol) * 2);
#pragma unroll
            for (int ng = 0; ng < 4; ng++) {
                mma16816(s[2 * ng], qh[ks], bb[ng][0], bb[ng][1]);
                mma16816(s[2 * ng + 1], qh[ks], bb[ng][2], bb[ng][3]);
                mma16816(s[2 * ng], ql[ks], bb[ng][0], bb[ng][1]);
                mma16816(s[2 * ng + 1], ql[ks], bb[ng][2], bb[ng][3]);
            }
#pragma unroll
            for (int ng = 0; ng < 4; ng++)
                ldsm4(bb[ng][0], bb[ng][1], bb[ng][2], bb[ng][3],
                      Klo_s + (uint32_t)((16 * ng + brow) * STR + 16 * ks + bcol) * 2);
#pragma unroll
            for (int ng = 0; ng < 4; ng++) {
                mma16816(s[2 * ng], qh[ks], bb[ng][0], bb[ng][1]);
                mma16816(s[2 * ng + 1], qh[ks], bb[ng][2], bb[ng][3]);
            }
        }

        if (kbase + 63 > qbase + wr) {
            int row0 = qbase + wr + (lane >> 2);
            int colb = kbase + 2 * (lane & 3);
#pragma unroll
            for (int nt = 0; nt < 8; nt++) {
                int c0 = colb + nt * 8;
                if (c0 > row0) s[nt][0] = -1e30f;
                if (c0 + 1 > row0) s[nt][1] = -1e30f;
                if (c0 > row0 + 8) s[nt][2] = -1e30f;
                if (c0 + 1 > row0 + 8) s[nt][3] = -1e30f;
            }
        }

        // fixed-base softmax: P = exp2(s) directly
#pragma unroll
        for (int nt = 0; nt < 8; nt++) {
            s[nt][0] = ex2f(s[nt][0]); rs0 += s[nt][0];
            s[nt][1] = ex2f(s[nt][1]); rs0 += s[nt][1];
            s[nt][2] = ex2f(s[nt][2]); rs1 += s[nt][2];
            s[nt][3] = ex2f(s[nt][3]); rs1 += s[nt][3];
        }

        uint32_t phi[4][4], plo[4][4];
#pragma unroll
        for (int t = 0; t < 4; t++) {
#pragma unroll
            for (int half = 0; half < 2; half++) {
                const float* sp = s[2 * t + half];
                int i0 = half * 2, i1 = half * 2 + 1;
                uint32_t h0 = cvt_bf2(sp[0], sp[1]);
                phi[t][i0] = h0;
                plo[t][i0] = cvt_bf2(sp[0] - bflo(h0), sp[1] - bfhi(h0));
                uint32_t h1 = cvt_bf2(sp[2], sp[3]);
                phi[t][i1] = h1;
                plo[t][i1] = cvt_bf2(sp[2] - bflo(h1), sp[3] - bfhi(h1));
            }
        }

#pragma unroll
        for (int t = 0; t < 4; t++) {
            uint32_t vb[4][4];
#pragma unroll
            for (int g = 0; g < 4; g++)
                ldsm4t(vb[g][0], vb[g][1], vb[g][2], vb[g][3],
                       Vhi_s + (uint32_t)((16 * t + vrow) * STR + 16 * g + vcol) * 2);
#pragma unroll
            for (int g = 0; g < 4; g++) {
                mma16816(o[2 * g], phi[t], vb[g][0], vb[g][1]);
                mma16816(o[2 * g + 1], phi[t], vb[g][2], vb[g][3]);
                mma16816(o[2 * g], plo[t], vb[g][0], vb[g][1]);
                mma16816(o[2 * g + 1], plo[t], vb[g][2], vb[g][3]);
            }
#pragma unroll
            for (int g = 0; g < 4; g++)
                ldsm4t(vb[g][0], vb[g][1], vb[g][2], vb[g][3],
                       Vlo_s + (uint32_t)((16 * t + vrow) * STR + 16 * g + vcol) * 2);
#pragma unroll
            for (int g = 0; g < 4; g++) {
                mma16816(o[2 * g], phi[t], vb[g][0], vb[g][1]);
                mma16816(o[2 * g + 1], phi[t], vb[g][2], vb[g][3]);
            }
        }

        st = (st + 1 == 3) ? 0 : st + 1;
    }

    rs0 += __shfl_xor_sync(0xffffffffu, rs0, 1);
    rs0 += __shfl_xor_sync(0xffffffffu, rs0, 2);
    rs1 += __shfl_xor_sync(0xffffffffu, rs1, 1);
    rs1 += __shfl_xor_sync(0xffffffffu, rs1, 2);
    float inv0 = 1.f / rs0, inv1 = 1.f / rs1;
    int b = bh / NH, h = bh % NH;
    int row0 = qbase + wr + (lane >> 2);
    size_t off0 = ((size_t)b * SEQ + row0) * EMB + h * HD + 2 * (lane & 3);
    size_t off1 = off0 + 8 * (size_t)EMB;
#pragma unroll
    for (int nd = 0; nd < 8; nd++) {
        float f0 = o[nd][0] * inv0, f1 = o[nd][1] * inv0;
        uint32_t hp = cvt_bf2(f0, f1);
        uint32_t lp = cvt_bf2(f0 - bflo(hp), f1 - bfhi(hp));
        *(uint32_t*)&AOhi[off0 + nd * 8] = hp;
        *(uint32_t*)&AOlo[off0 + nd * 8] = lp;
        float g0 = o[nd][2] * inv1, g1 = o[nd][3] * inv1;
        uint32_t hq = cvt_bf2(g0, g1);
        uint32_t lq = cvt_bf2(g0 - bflo(hq), g1 - bfhi(hq));
        *(uint32_t*)&AOhi[off1 + nd * 8] = hq;
        *(uint32_t*)&AOlo[off1 + nd * 8] = lq;
    }
}

// =================================================================
// launch
// =================================================================
extern "C" void kernel_launch(void* const* d_in, const int* in_sizes, int n_in,
                              void* d_out, int out_size)
{
    const float* x    = (const float*)d_in[0];
    const float* wq_b = (const float*)d_in[2];
    const float* wk_b = (const float*)d_in[4];
    const float* wv_b = (const float*)d_in[6];
    const float* wo_b = (const float*)d_in[8];
    float* out = (float*)d_out;

    bf16 *xhi, *xlo;
    bf16 *qhi, *qlo, *khi, *klo, *vhi, *vlo, *aohi, *aolo;
    cudaGetSymbolAddress((void**)&xhi, g_xhi);
    cudaGetSymbolAddress((void**)&xlo, g_xlo);
    cudaGetSymbolAddress((void**)&qhi, g_qhi);
    cudaGetSymbolAddress((void**)&qlo, g_qlo);
    cudaGetSymbolAddress((void**)&khi, g_khi);
    cudaGetSymbolAddress((void**)&klo, g_klo);
    cudaGetSymbolAddress((void**)&vhi, g_vhi);
    cudaGetSymbolAddress((void**)&vlo, g_vlo);
    cudaGetSymbolAddress((void**)&aohi, g_aohi);
    cudaGetSymbolAddress((void**)&aolo, g_aolo);

    cudaFuncSetAttribute(attn_mma,
                         cudaFuncAttributeMaxDynamicSharedMemorySize, ATT_SMEM);
    cudaFuncSetAttribute(qkv_mma,
                         cudaFuncAttributeMaxDynamicSharedMemorySize, GEMM_SMEM);
    cudaFuncSetAttribute(out_mma,
                         cudaFuncAttributeMaxDynamicSharedMemorySize, GEMM_SMEM);

    const int nx4 = MROWS * EMB / 4;
    split4_kernel<<<(nx4 + 255) / 256, 256>>>((const float4*)x,
                                              (uint2*)xhi, (uint2*)xlo, nx4);
    dim3 gw((EMB * EMB / 4 + 255) / 256, 1, 4);
    split_w4_kernel<<<gw, 256>>>((const float*)d_in[1], (const float*)d_in[3],
                                 (const float*)d_in[5], (const float*)d_in[7]);

    dim3 gqkv(NQKV / BN, MROWS / BM);              // 18 x 32 = 576
    qkv_mma<<<gqkv, 256, GEMM_SMEM>>>(wq_b, wk_b, wv_b);

    attn_mma<<<(SEQ / 128) * BATCH * NH, 256, ATT_SMEM>>>(
        qhi, qlo, khi, klo, vhi, vlo, aohi, aolo);

    dim3 go(EMB / BN, MROWS / BM);                 // 6 x 32
    out_mma<<<go, 256, GEMM_SMEM>>>(wo_b, out);
}

// round 10
// speedup vs baseline: 1.6941x; 1.6941x over previous
#include <cuda_runtime.h>
#include <cuda_bf16.h>
#include <cstdint>

#define SEQ   2048
#define EMB   768
#define NH    12
#define HD    64
#define BATCH 2
#define MROWS (BATCH * SEQ)   // 4096
#define NQKV  (3 * EMB)       // 2304

typedef __nv_bfloat16 bf16;

// ---------------- scratch (static device arrays; no allocation) -------------
__device__ bf16 g_xhi[MROWS * EMB], g_xlo[MROWS * EMB];
__device__ bf16 g_whi[4][EMB * EMB], g_wlo[4][EMB * EMB];   // q,k,v,o
__device__ bf16 g_qhi[BATCH * NH * SEQ * HD], g_qlo[BATCH * NH * SEQ * HD];
__device__ bf16 g_khi[BATCH * NH * SEQ * HD], g_klo[BATCH * NH * SEQ * HD];
__device__ bf16 g_vhi[BATCH * NH * SEQ * HD], g_vlo[BATCH * NH * SEQ * HD];
__device__ bf16 g_aohi[MROWS * EMB], g_aolo[MROWS * EMB];

// ---------------- small helpers ----------------
__device__ __forceinline__ uint32_t cvt_bf2(float lo, float hi) {
    uint32_t r;
    asm("cvt.rn.bf16x2.f32 %0, %1, %2;" : "=r"(r) : "f"(hi), "f"(lo));
    return r;
}
__device__ __forceinline__ float bflo(uint32_t p) { return __uint_as_float(p << 16); }
__device__ __forceinline__ float bfhi(uint32_t p) { return __uint_as_float(p & 0xffff0000u); }
__device__ __forceinline__ float ex2f(float x) {
    float y;
    asm("ex2.approx.ftz.f32 %0, %1;" : "=f"(y) : "f"(x));
    return y;
}
__device__ __forceinline__ void ldsm4(uint32_t& r0, uint32_t& r1,
                                      uint32_t& r2, uint32_t& r3, uint32_t addr)
{
    asm volatile("ldmatrix.sync.aligned.m8n8.x4.shared.b16 {%0,%1,%2,%3}, [%4];"
                 : "=r"(r0), "=r"(r1), "=r"(r2), "=r"(r3) : "r"(addr));
}
__device__ __forceinline__ void ldsm4t(uint32_t& r0, uint32_t& r1,
                                       uint32_t& r2, uint32_t& r3, uint32_t addr)
{
    asm volatile("ldmatrix.sync.aligned.m8n8.x4.trans.shared.b16 {%0,%1,%2,%3}, [%4];"
                 : "=r"(r0), "=r"(r1), "=r"(r2), "=r"(r3) : "r"(addr));
}
__device__ __forceinline__ void mma16816(float c[4], const uint32_t a[4],
                                         uint32_t b0, uint32_t b1)
{
    asm volatile(
        "mma.sync.aligned.m16n8k16.row.col.f32.bf16.bf16.f32 "
        "{%0,%1,%2,%3}, {%4,%5,%6,%7}, {%8,%9}, {%0,%1,%2,%3};"
        : "+f"(c[0]), "+f"(c[1]), "+f"(c[2]), "+f"(c[3])
        : "r"(a[0]), "r"(a[1]), "r"(a[2]), "r"(a[3]), "r"(b0), "r"(b1));
}
__device__ __forceinline__ void cp16(uint32_t saddr, const void* gaddr)
{
    asm volatile("cp.async.cg.shared.global [%0], [%1], 16;"
                 :: "r"(saddr), "l"(gaddr));
}
template<int N>
__device__ __forceinline__ void cp_wait()
{
    asm volatile("cp.async.wait_group %0;" :: "n"(N));
}

// =================================================================
// fp32 -> bf16 hi/lo split conversions (float4 vectorized)
// =================================================================
__global__ __launch_bounds__(256) void split4_kernel(
    const float4* __restrict__ src, uint2* __restrict__ hi,
    uint2* __restrict__ lo, int n4)
{
    int i = blockIdx.x * 256 + threadIdx.x;
    if (i < n4) {
        float4 v = src[i];
        uint32_t h0 = cvt_bf2(v.x, v.y);
        uint32_t h1 = cvt_bf2(v.z, v.w);
        uint32_t l0 = cvt_bf2(v.x - bflo(h0), v.y - bfhi(h0));
        uint32_t l1 = cvt_bf2(v.z - bflo(h1), v.w - bfhi(h1));
        hi[i] = make_uint2(h0, h1);
        lo[i] = make_uint2(l0, l1);
    }
}

__global__ __launch_bounds__(256) void split_w4_kernel(
    const float* __restrict__ wq, const float* __restrict__ wk,
    const float* __restrict__ wv, const float* __restrict__ wo)
{
    int z = blockIdx.z;
    const float4* src = (const float4*)((z == 0) ? wq : (z == 1) ? wk :
                                        (z == 2) ? wv : wo);
    uint2* hi = (uint2*)g_whi[z];
    uint2* lo = (uint2*)g_wlo[z];
    int i = blockIdx.x * 256 + threadIdx.x;
    if (i < EMB * EMB / 4) {
        float4 v = src[i];
        uint32_t h0 = cvt_bf2(v.x, v.y);
        uint32_t h1 = cvt_bf2(v.z, v.w);
        uint32_t l0 = cvt_bf2(v.x - bflo(h0), v.y - bfhi(h0));
        uint32_t l1 = cvt_bf2(v.z - bflo(h1), v.w - bfhi(h1));
        hi[i] = make_uint2(h0, h1);
        lo[i] = make_uint2(l0, l1);
    }
}

// =================================================================
// FUSED bf16-split MMA GEMM: per k-block stage Ahi,Alo,Bhi,Blo once;
// run all 3 split passes (hi*hi, lo*hi, hi*lo) against one staging.
// 24 iterations. 2-stage ring with the PROVEN round-4 protocol:
// issue(it+1 -> buf^1) BEFORE wait<1>; trailing sync guards buf^1
// against the next iteration's issue. (Round-9 bug: issued it+2 into
// the SAME buffer being read -> race.)
// =================================================================
#define BM 128
#define BN 128
#define BK 32
#define LDSK 40
#define NKB (EMB / BK)                 // 24 iterations
#define TILE_B (BM * LDSK * 2)         // 10240 bytes, one hi or lo tile
#define GSTAGE_B (2 * TILE_B)          // 20480: hi tile then lo tile
#define GEMM_SMEM (4 * GSTAGE_B)       // 81920 (A:2 stages, B:2 stages)

__device__ __forceinline__ void gemm_issue(
    int kb, int buf,
    const bf16* __restrict__ Ahi, const bf16* __restrict__ Alo,
    const bf16* __restrict__ Bhi, const bf16* __restrict__ Blo,
    uint32_t asb, uint32_t bsb, int m0, int n0, int srow, int schk)
{
    int k0 = kb * BK;
    uint32_t sa = asb + (uint32_t)buf * GSTAGE_B;
    uint32_t sb = bsb + (uint32_t)buf * GSTAGE_B;
    uint32_t o0 = (srow * LDSK + schk) * 2;
    uint32_t o1 = ((srow + 64) * LDSK + schk) * 2;
    size_t g0 = (size_t)(m0 + srow) * EMB + k0 + schk;
    size_t g1 = (size_t)(m0 + srow + 64) * EMB + k0 + schk;
    size_t h0 = (size_t)(n0 + srow) * EMB + k0 + schk;
    size_t h1 = (size_t)(n0 + srow + 64) * EMB + k0 + schk;
    cp16(sa + o0, Ahi + g0);
    cp16(sa + o1, Ahi + g1);
    cp16(sa + TILE_B + o0, Alo + g0);
    cp16(sa + TILE_B + o1, Alo + g1);
    cp16(sb + o0, Bhi + h0);
    cp16(sb + o1, Bhi + h1);
    cp16(sb + TILE_B + o0, Blo + h0);
    cp16(sb + TILE_B + o1, Blo + h1);
    asm volatile("cp.async.commit_group;");
}

template<int REMAP>
__device__ __forceinline__ void mma_gemm_body(
    const bf16* __restrict__ Ahi, const bf16* __restrict__ Alo,
    const bf16* __restrict__ Bhi, const bf16* __restrict__ Blo,
    const float* __restrict__ bias, float* __restrict__ C,
    bf16* __restrict__ Chi, bf16* __restrict__ Clo,
    int m0, int n0, float scale)
{
    extern __shared__ char dsm[];
    const uint32_t asb = (uint32_t)__cvta_generic_to_shared(dsm);
    const uint32_t bsb = asb + 2 * GSTAGE_B;

    const int tid = threadIdx.x;
    const int lane = tid & 31;
    const int wid = tid >> 5;
    const int wm = wid >> 2;
    const int wn = wid & 3;

    float acc[4][4][4];
#pragma unroll
    for (int i = 0; i < 4; i++)
#pragma unroll
        for (int j = 0; j < 4; j++)
#pragma unroll
            for (int t = 0; t < 4; t++) acc[i][j][t] = 0.f;

    const int srow = tid >> 2;
    const int schk = (tid & 3) * 8;

    const int laRow = wm * 64 + (lane & 15);
    const int laCol = (lane >> 4) * 8;
    const int lbRow = wn * 32 + ((lane >> 4) << 3) + (lane & 7);
    const int lbCol = ((lane >> 3) & 1) * 8;

    gemm_issue(0, 0, Ahi, Alo, Bhi, Blo, asb, bsb, m0, n0, srow, schk);

    for (int it = 0; it < NKB; it++) {
        const int buf = it & 1;
        if (it + 1 < NKB) {
            gemm_issue(it + 1, buf ^ 1, Ahi, Alo, Bhi, Blo, asb, bsb,
                       m0, n0, srow, schk);
            cp_wait<1>();
        } else {
            cp_wait<0>();
        }
        __syncthreads();

        const uint32_t sa = asb + (uint32_t)buf * GSTAGE_B;
        const uint32_t sb = bsb + (uint32_t)buf * GSTAGE_B;

#pragma unroll
        for (int ks = 0; ks < 2; ks++) {
            const uint32_t aoff = (uint32_t)(ks * 16 + laCol) * 2;
            const uint32_t boff = (uint32_t)(ks * 16 + lbCol) * 2;
            // --- hi*hi ---
            uint32_t a[4][4], a2[4][4], b[2][4];
#pragma unroll
            for (int mt = 0; mt < 4; mt++)
                ldsm4(a[mt][0], a[mt][1], a[mt][2], a[mt][3],
                      sa + (uint32_t)((laRow + mt * 16) * LDSK) * 2 + aoff);
#pragma unroll
            for (int p = 0; p < 2; p++)
                ldsm4(b[p][0], b[p][1], b[p][2], b[p][3],
                      sb + (uint32_t)((lbRow + p * 16) * LDSK) * 2 + boff);
#pragma unroll
            for (int mt = 0; mt < 4; mt++)
#pragma unroll
                for (int nt = 0; nt < 4; nt++)
                    mma16816(acc[mt][nt], a[mt],
                             b[nt >> 1][(nt & 1) * 2], b[nt >> 1][(nt & 1) * 2 + 1]);
            // --- lo*hi (b still Bhi) ---
#pragma unroll
            for (int mt = 0; mt < 4; mt++)
                ldsm4(a2[mt][0], a2[mt][1], a2[mt][2], a2[mt][3],
                      sa + TILE_B + (uint32_t)((laRow + mt * 16) * LDSK) * 2 + aoff);
#pragma unroll
            for (int mt = 0; mt < 4; mt++)
#pragma unroll
                for (int nt = 0; nt < 4; nt++)
                    mma16816(acc[mt][nt], a2[mt],
                             b[nt >> 1][(nt & 1) * 2], b[nt >> 1][(nt & 1) * 2 + 1]);
            // --- hi*lo (a still Ahi) ---
#pragma unroll
            for (int p = 0; p < 2; p++)
                ldsm4(b[p][0], b[p][1], b[p][2], b[p][3],
                      sb + TILE_B + (uint32_t)((lbRow + p * 16) * LDSK) * 2 + boff);
#pragma unroll
            for (int mt = 0; mt < 4; mt++)
#pragma unroll
                for (int nt = 0; nt < 4; nt++)
                    mma16816(acc[mt][nt], a[mt],
                             b[nt >> 1][(nt & 1) * 2], b[nt >> 1][(nt & 1) * 2 + 1]);
        }
        __syncthreads();   // protect buf^1 (read this iter? no: protects
                           // next iteration's issue into buf^1 after our reads)
    }

    const int er = lane >> 2;
    const int ec = (lane & 3) * 2;
#pragma unroll
    for (int mt = 0; mt < 4; mt++) {
        int m = m0 + wm * 64 + mt * 16 + er;
#pragma unroll
        for (int nt = 0; nt < 4; nt++) {
            int n = n0 + wn * 32 + nt * 8 + ec;
            float b0 = bias[n], b1 = bias[n + 1];
            float v00 = (acc[mt][nt][0] + b0) * scale;
            float v01 = (acc[mt][nt][1] + b1) * scale;
            float v10 = (acc[mt][nt][2] + b0) * scale;
            float v11 = (acc[mt][nt][3] + b1) * scale;
            if (REMAP) {
                int h = n >> 6, d = n & 63;
                int bb0 = m >> 11, s0 = m & 2047;
                int bb1 = (m + 8) >> 11, s1 = (m + 8) & 2047;
                size_t p0 = (((size_t)(bb0 * NH + h)) * SEQ + s0) * HD + d;
                size_t p1 = (((size_t)(bb1 * NH + h)) * SEQ + s1) * HD + d;
                uint32_t hp = cvt_bf2(v00, v01);
                uint32_t lp = cvt_bf2(v00 - bflo(hp), v01 - bfhi(hp));
                *(uint32_t*)&Chi[p0] = hp;
                *(uint32_t*)&Clo[p0] = lp;
                hp = cvt_bf2(v10, v11);
                lp = cvt_bf2(v10 - bflo(hp), v11 - bfhi(hp));
                *(uint32_t*)&Chi[p1] = hp;
                *(uint32_t*)&Clo[p1] = lp;
            } else {
                *(float2*)&C[(size_t)m * EMB + n] = make_float2(v00, v01);
                *(float2*)&C[(size_t)(m + 8) * EMB + n] = make_float2(v10, v11);
            }
        }
    }
}

__global__ __launch_bounds__(256, 2) void qkv_mma(
    const float* __restrict__ bq, const float* __restrict__ bk,
    const float* __restrict__ bv)
{
    int m0 = blockIdx.y * BM;
    int ng = blockIdx.x * BN;
    int sel = ng / EMB;
    int n0 = ng - sel * EMB;
    const bf16* Bhi = g_whi[sel];
    const bf16* Blo = g_wlo[sel];
    const float* bias = (sel == 0) ? bq : (sel == 1) ? bk : bv;
    bf16* Chi = (sel == 0) ? g_qhi : (sel == 1) ? g_khi : g_vhi;
    bf16* Clo = (sel == 0) ? g_qlo : (sel == 1) ? g_klo : g_vlo;
    float scale = (sel == 0) ? 0.125f * 1.4426950408889634f : 1.0f;
    mma_gemm_body<1>(g_xhi, g_xlo, Bhi, Blo, bias, nullptr, Chi, Clo,
                     m0, n0, scale);
}

__global__ __launch_bounds__(256, 2) void out_mma(
    const float* __restrict__ bo, float* __restrict__ out)
{
    mma_gemm_body<0>(g_aohi, g_aolo, g_whi[3], g_wlo[3], bo, out,
                     nullptr, nullptr, blockIdx.y * BM, blockIdx.x * BN, 1.0f);
}

// =================================================================
// Tensor-core flash attention, fixed-base softmax — round-7 config,
// byte-identical (best measured 129us @ tensor 53.6%).
// =================================================================
#define STR 72
#define KV_STAGE_B (256 * STR * 2)       // 36864
#define ATT_SMEM (3 * KV_STAGE_B)        // 110592

__device__ __forceinline__ void kv_issue(uint32_t sb, int buf, int kbase,
                                         const bf16* const kvsrc[4], int tid)
{
    uint32_t base = sb + (uint32_t)buf * KV_STAGE_B;
#pragma unroll
    for (int i = 0; i < 8; i++) {
        int c = i * 256 + tid;
        int row = (c >> 3) & 63;
        int ch = (c & 7) * 8;
        cp16(base + (uint32_t)(((i >> 1) * 64 + row) * STR + ch) * 2,
             kvsrc[i >> 1] + (size_t)(kbase + row) * HD + ch);
    }
    asm volatile("cp.async.commit_group;");
}

__global__ __launch_bounds__(256, 2) void attn_mma(
    const bf16* __restrict__ Qhi_g, const bf16* __restrict__ Qlo_g,
    const bf16* __restrict__ Khi_g, const bf16* __restrict__ Klo_g,
    const bf16* __restrict__ Vhi_g, const bf16* __restrict__ Vlo_g,
    bf16* __restrict__ AOhi, bf16* __restrict__ AOlo)
{
    extern __shared__ char dsm[];
    const uint32_t sb = (uint32_t)__cvta_generic_to_shared(dsm);

    const int bid = blockIdx.x;
    const int qt = (SEQ / 128) - 1 - bid / (BATCH * NH);
    const int bh = bid % (BATCH * NH);
    const int qbase = qt * 128;
    const int nkt = 2 * qt + 2;

    const int tid = threadIdx.x;
    const int lane = tid & 31;
    const int wid = tid >> 5;
    const int wr = wid * 16;

    const size_t hoff = (size_t)bh * SEQ * HD;
    const bf16* qsrc[2] = {Qhi_g + hoff, Qlo_g + hoff};
    const bf16* kvsrc[4] = {Khi_g + hoff, Klo_g + hoff, Vhi_g + hoff, Vlo_g + hoff};

#pragma unroll
    for (int i = 0; i < 8; i++) {
        int c = i * 256 + tid;
        int row = (c >> 3) & 127;
        int ch = (c & 7) * 8;
        cp16(sb + (uint32_t)(((i >> 2) * 128 + row) * STR + ch) * 2,
             qsrc[i >> 2] + (size_t)(qbase + row) * HD + ch);
    }
    asm volatile("cp.async.commit_group;");
    cp_wait<0>();
    __syncthreads();

    uint32_t qh[4][4], ql[4][4];
    {
        int arow = wr + (lane & 15);
        int acol = (lane >> 4) * 8;
#pragma unroll
        for (int ks = 0; ks < 4; ks++) {
            ldsm4(qh[ks][0], qh[ks][1], qh[ks][2], qh[ks][3],
                  sb + (uint32_t)(arow * STR + ks * 16 + acol) * 2);
            ldsm4(ql[ks][0], ql[ks][1], ql[ks][2], ql[ks][3],
                  sb + (uint32_t)((128 + arow) * STR + ks * 16 + acol) * 2);
        }
    }
    __syncthreads();

    float o[8][4];
#pragma unroll
    for (int i = 0; i < 8; i++)
#pragma unroll
        for (int j = 0; j < 4; j++) o[i][j] = 0.f;
    float rs0 = 0.f, rs1 = 0.f;

    kv_issue(sb, 0, 0, kvsrc, tid);
    kv_issue(sb, 1, 64, kvsrc, tid);

    const int brow = (lane & 7) + ((lane >> 4) << 3);
    const int bcol = ((lane >> 3) & 1) * 8;
    const int vrow = (lane & 7) + (((lane >> 3) & 1) << 3);
    const int vcol = (lane >> 4) * 8;

    int st = 0;
    for (int kt = 0; kt < nkt; kt++) {
        if (kt + 1 < nkt) cp_wait<1>(); else cp_wait<0>();
        __syncthreads();
        if (kt + 2 < nkt) {
            int b2 = st + 2; if (b2 >= 3) b2 -= 3;
            kv_issue(sb, b2, (kt + 2) * 64, kvsrc, tid);
        }

        const uint32_t kvb = sb + (uint32_t)st * KV_STAGE_B;
        const uint32_t Khi_s = kvb;
        const uint32_t Klo_s = kvb + 64 * STR * 2;
        const uint32_t Vhi_s = kvb + 128 * STR * 2;
        const uint32_t Vlo_s = kvb + 192 * STR * 2;
        const int kbase = kt * 64;

        float s[8][4];
#pragma unroll
        for (int i = 0; i < 8; i++)
#pragma unroll
            for (int j = 0; j < 4; j++) s[i][j] = 0.f;

#pragma unroll
        for (int ks = 0; ks < 4; ks++) {
            uint32_t bb[4][4];
#pragma unroll
            for (int ng = 0; ng < 4; ng++)
                ldsm4(bb[ng][0], bb[ng][1], bb[ng][2], bb[ng][3],
                      Khi_s + (uint32_t)((16 * ng + brow) * STR + 16 * ks + bcol) * 2);
#pragma unroll
            for (int ng = 0; ng < 4; ng++) {
                mma16816(s[2 * ng], qh[ks], bb[ng][0], bb[ng][1]);
                mma16816(s[2 * ng + 1], qh[ks], bb[ng][2], bb[ng][3]);
                mma16816(s[2 * ng], ql[ks], bb[ng][0], bb[ng][1]);
                mma16816(s[2 * ng + 1], ql[ks], bb[ng][2], bb[ng][3]);
            }
#pragma unroll
            for (int ng = 0; ng < 4; ng++)
                ldsm4(bb[ng][0], bb[ng][1], bb[ng][2], bb[ng][3],
                      Klo_s + (uint32_t)((16 * ng + brow) * STR + 16 * ks + bcol) * 2);
#pragma unroll
            for (int ng = 0; ng < 4; ng++) {
                mma16816(s[2 * ng], qh[ks], bb[ng][0], bb[ng][1]);
                mma16816(s[2 * ng + 1], qh[ks], bb[ng][2], bb[ng][3]);
            }
        }

        if (kbase + 63 > qbase + wr) {
            int row0 = qbase + wr + (lane >> 2);
            int colb = kbase + 2 * (lane & 3);
#pragma unroll
            for (int nt = 0; nt < 8; nt++) {
                int c0 = colb + nt * 8;
                if (c0 > row0) s[nt][0] = -1e30f;
                if (c0 + 1 > row0) s[nt][1] = -1e30f;
                if (c0 > row0 + 8) s[nt][2] = -1e30f;
                if (c0 + 1 > row0 + 8) s[nt][3] = -1e30f;
            }
        }

        // fixed-base softmax: P = exp2(s) directly
#pragma unroll
        for (int nt = 0; nt < 8; nt++) {
            s[nt][0] = ex2f(s[nt][0]); rs0 += s[nt][0];
            s[nt][1] = ex2f(s[nt][1]); rs0 += s[nt][1];
            s[nt][2] = ex2f(s[nt][2]); rs1 += s[nt][2];
            s[nt][3] = ex2f(s[nt][3]); rs1 += s[nt][3];
        }

        uint32_t phi[4][4], plo[4][4];
#pragma unroll
        for (int t = 0; t < 4; t++) {
#pragma unroll
            for (int half = 0; half < 2; half++) {
                const float* sp = s[2 * t + half];
                int i0 = half * 2, i1 = half * 2 + 1;
                uint32_t h0 = cvt_bf2(sp[0], sp[1]);
                phi[t][i0] = h0;
                plo[t][i0] = cvt_bf2(sp[0] - bflo(h0), sp[1] - bfhi(h0));
                uint32_t h1 = cvt_bf2(sp[2], sp[3]);
                phi[t][i1] = h1;
                plo[t][i1] = cvt_bf2(sp[2] - bflo(h1), sp[3] - bfhi(h1));
            }
        }

#pragma unroll
        for (int t = 0; t < 4; t++) {
            uint32_t vb[4][4];
#pragma unroll
            for (int g = 0; g < 4; g++)
                ldsm4t(vb[g][0], vb[g][1], vb[g][2], vb[g][3],
                       Vhi_s + (uint32_t)((16 * t + vrow) * STR + 16 * g + vcol) * 2);
#pragma unroll
            for (int g = 0; g < 4; g++) {
                mma16816(o[2 * g], phi[t], vb[g][0], vb[g][1]);
                mma16816(o[2 * g + 1], phi[t], vb[g][2], vb[g][3]);
                mma16816(o[2 * g], plo[t], vb[g][0], vb[g][1]);
                mma16816(o[2 * g + 1], plo[t], vb[g][2], vb[g][3]);
            }
#pragma unroll
            for (int g = 0; g < 4; g++)
                ldsm4t(vb[g][0], vb[g][1], vb[g][2], vb[g][3],
                       Vlo_s + (uint32_t)((16 * t + vrow) * STR + 16 * g + vcol) * 2);
#pragma unroll
            for (int g = 0; g < 4; g++) {
                mma16816(o[2 * g], phi[t], vb[g][0], vb[g][1]);
                mma16816(o[2 * g + 1], phi[t], vb[g][2], vb[g][3]);
            }
        }

        st = (st + 1 == 3) ? 0 : st + 1;
    }

    rs0 += __shfl_xor_sync(0xffffffffu, rs0, 1);
    rs0 += __shfl_xor_sync(0xffffffffu, rs0, 2);
    rs1 += __shfl_xor_sync(0xffffffffu, rs1, 1);
    rs1 += __shfl_xor_sync(0xffffffffu, rs1, 2);
    float inv0 = 1.f / rs0, inv1 = 1.f / rs1;
    int b = bh / NH, h = bh % NH;
    int row0 = qbase + wr + (lane >> 2);
    size_t off0 = ((size_t)b * SEQ + row0) * EMB + h * HD + 2 * (lane & 3);
    size_t off1 = off0 + 8 * (size_t)EMB;
#pragma unroll
    for (int nd = 0; nd < 8; nd++) {
        float f0 = o[nd][0] * inv0, f1 = o[nd][1] * inv0;
        uint32_t hp = cvt_bf2(f0, f1);
        uint32_t lp = cvt_bf2(f0 - bflo(hp), f1 - bfhi(hp));
        *(uint32_t*)&AOhi[off0 + nd * 8] = hp;
        *(uint32_t*)&AOlo[off0 + nd * 8] = lp;
        float g0 = o[nd][2] * inv1, g1 = o[nd][3] * inv1;
        uint32_t hq = cvt_bf2(g0, g1);
        uint32_t lq = cvt_bf2(g0 - bflo(hq), g1 - bfhi(hq));
        *(uint32_t*)&AOhi[off1 + nd * 8] = hq;
        *(uint32_t*)&AOlo[off1 + nd * 8] = lq;
    }
}

// =================================================================
// launch
// =================================================================
extern "C" void kernel_launch(void* const* d_in, const int* in_sizes, int n_in,
                              void* d_out, int out_size)
{
    const float* x    = (const float*)d_in[0];
    const float* wq_b = (const float*)d_in[2];
    const float* wk_b = (const float*)d_in[4];
    const float* wv_b = (const float*)d_in[6];
    const float* wo_b = (const float*)d_in[8];
    float* out = (float*)d_out;

    bf16 *xhi, *xlo;
    bf16 *qhi, *qlo, *khi, *klo, *vhi, *vlo, *aohi, *aolo;
    cudaGetSymbolAddress((void**)&xhi, g_xhi);
    cudaGetSymbolAddress((void**)&xlo, g_xlo);
    cudaGetSymbolAddress((void**)&qhi, g_qhi);
    cudaGetSymbolAddress((void**)&qlo, g_qlo);
    cudaGetSymbolAddress((void**)&khi, g_khi);
    cudaGetSymbolAddress((void**)&klo, g_klo);
    cudaGetSymbolAddress((void**)&vhi, g_vhi);
    cudaGetSymbolAddress((void**)&vlo, g_vlo);
    cudaGetSymbolAddress((void**)&aohi, g_aohi);
    cudaGetSymbolAddress((void**)&aolo, g_aolo);

    cudaFuncSetAttribute(attn_mma,
                         cudaFuncAttributeMaxDynamicSharedMemorySize, ATT_SMEM);
    cudaFuncSetAttribute(qkv_mma,
                         cudaFuncAttributeMaxDynamicSharedMemorySize, GEMM_SMEM);
    cudaFuncSetAttribute(out_mma,
                         cudaFuncAttributeMaxDynamicSharedMemorySize, GEMM_SMEM);

    const int nx4 = MROWS * EMB / 4;
    split4_kernel<<<(nx4 + 255) / 256, 256>>>((const float4*)x,
                                              (uint2*)xhi, (uint2*)xlo, nx4);
    dim3 gw((EMB * EMB / 4 + 255) / 256, 1, 4);
    split_w4_kernel<<<gw, 256>>>((const float*)d_in[1], (const float*)d_in[3],
                                 (const float*)d_in[5], (const float*)d_in[7]);

    dim3 gqkv(NQKV / BN, MROWS / BM);              // 18 x 32 = 576
    qkv_mma<<<gqkv, 256, GEMM_SMEM>>>(wq_b, wk_b, wv_b);

    attn_mma<<<(SEQ / 128) * BATCH * NH, 256, ATT_SMEM>>>(
        qhi, qlo, khi, klo, vhi, vlo, aohi, aolo);

    dim3 go(EMB / BN, MROWS / BM);                 // 6 x 32
    out_mma<<<go, 256, GEMM_SMEM>>>(wo_b, out);
}

// round 11
// speedup vs baseline: 1.7288x; 1.0204x over previous
#include <cuda_runtime.h>
#include <cuda_bf16.h>
#include <cstdint>

#define SEQ   2048
#define EMB   768
#define NH    12
#define HD    64
#define BATCH 2
#define MROWS (BATCH * SEQ)   // 4096
#define NQKV  (3 * EMB)       // 2304

typedef __nv_bfloat16 bf16;

// ---------------- scratch (static device arrays; no allocation) -------------
__device__ bf16 g_xhi[MROWS * EMB], g_xlo[MROWS * EMB];
__device__ bf16 g_whi[4][EMB * EMB], g_wlo[4][EMB * EMB];   // q,k,v,o
__device__ bf16 g_qhi[BATCH * NH * SEQ * HD], g_qlo[BATCH * NH * SEQ * HD];
__device__ bf16 g_khi[BATCH * NH * SEQ * HD], g_klo[BATCH * NH * SEQ * HD];
__device__ bf16 g_vhi[BATCH * NH * SEQ * HD], g_vlo[BATCH * NH * SEQ * HD];
__device__ bf16 g_aohi[MROWS * EMB], g_aolo[MROWS * EMB];
// split-KV partials: 24 bh x 8 split q-tiles x 2 halves
__device__ float g_po[24 * 8 * 2 * 128 * 64];
__device__ float g_pl[24 * 8 * 2 * 128];

// heavy-first unit schedule: 16 split halves (qt 8..15) + 8 unsplit (qt 0..7)
// UHF: 0/1 = KV half, 2 = unsplit
__constant__ int8_t UQT[24] = {15,15,7,14,14,13,13,6,12,12,11,11,5,10,10,9,9,4,8,8,3,2,1,0};
__constant__ int8_t UHF[24] = {0,1,2,0,1,0,1,2,0,1,0,1,2,0,1,0,1,2,0,1,2,2,2,2};

// ---------------- small helpers ----------------
__device__ __forceinline__ uint32_t cvt_bf2(float lo, float hi) {
    uint32_t r;
    asm("cvt.rn.bf16x2.f32 %0, %1, %2;" : "=r"(r) : "f"(hi), "f"(lo));
    return r;
}
__device__ __forceinline__ float bflo(uint32_t p) { return __uint_as_float(p << 16); }
__device__ __forceinline__ float bfhi(uint32_t p) { return __uint_as_float(p & 0xffff0000u); }
__device__ __forceinline__ float ex2f(float x) {
    float y;
    asm("ex2.approx.ftz.f32 %0, %1;" : "=f"(y) : "f"(x));
    return y;
}
__device__ __forceinline__ void ldsm4(uint32_t& r0, uint32_t& r1,
                                      uint32_t& r2, uint32_t& r3, uint32_t addr)
{
    asm volatile("ldmatrix.sync.aligned.m8n8.x4.shared.b16 {%0,%1,%2,%3}, [%4];"
                 : "=r"(r0), "=r"(r1), "=r"(r2), "=r"(r3) : "r"(addr));
}
__device__ __forceinline__ void ldsm4t(uint32_t& r0, uint32_t& r1,
                                       uint32_t& r2, uint32_t& r3, uint32_t addr)
{
    asm volatile("ldmatrix.sync.aligned.m8n8.x4.trans.shared.b16 {%0,%1,%2,%3}, [%4];"
                 : "=r"(r0), "=r"(r1), "=r"(r2), "=r"(r3) : "r"(addr));
}
__device__ __forceinline__ void mma16816(float c[4], const uint32_t a[4],
                                         uint32_t b0, uint32_t b1)
{
    asm volatile(
        "mma.sync.aligned.m16n8k16.row.col.f32.bf16.bf16.f32 "
        "{%0,%1,%2,%3}, {%4,%5,%6,%7}, {%8,%9}, {%0,%1,%2,%3};"
        : "+f"(c[0]), "+f"(c[1]), "+f"(c[2]), "+f"(c[3])
        : "r"(a[0]), "r"(a[1]), "r"(a[2]), "r"(a[3]), "r"(b0), "r"(b1));
}
__device__ __forceinline__ void cp16(uint32_t saddr, const void* gaddr)
{
    asm volatile("cp.async.cg.shared.global [%0], [%1], 16;"
                 :: "r"(saddr), "l"(gaddr));
}
template<int N>
__device__ __forceinline__ void cp_wait()
{
    asm volatile("cp.async.wait_group %0;" :: "n"(N));
}

// =================================================================
// fp32 -> bf16 hi/lo split conversions (float4 vectorized)
// =================================================================
__global__ __launch_bounds__(256) void split4_kernel(
    const float4* __restrict__ src, uint2* __restrict__ hi,
    uint2* __restrict__ lo, int n4)
{
    int i = blockIdx.x * 256 + threadIdx.x;
    if (i < n4) {
        float4 v = src[i];
        uint32_t h0 = cvt_bf2(v.x, v.y);
        uint32_t h1 = cvt_bf2(v.z, v.w);
        uint32_t l0 = cvt_bf2(v.x - bflo(h0), v.y - bfhi(h0));
        uint32_t l1 = cvt_bf2(v.z - bflo(h1), v.w - bfhi(h1));
        hi[i] = make_uint2(h0, h1);
        lo[i] = make_uint2(l0, l1);
    }
}

__global__ __launch_bounds__(256) void split_w4_kernel(
    const float* __restrict__ wq, const float* __restrict__ wk,
    const float* __restrict__ wv, const float* __restrict__ wo)
{
    int z = blockIdx.z;
    const float4* src = (const float4*)((z == 0) ? wq : (z == 1) ? wk :
                                        (z == 2) ? wv : wo);
    uint2* hi = (uint2*)g_whi[z];
    uint2* lo = (uint2*)g_wlo[z];
    int i = blockIdx.x * 256 + threadIdx.x;
    if (i < EMB * EMB / 4) {
        float4 v = src[i];
        uint32_t h0 = cvt_bf2(v.x, v.y);
        uint32_t h1 = cvt_bf2(v.z, v.w);
        uint32_t l0 = cvt_bf2(v.x - bflo(h0), v.y - bfhi(h0));
        uint32_t l1 = cvt_bf2(v.z - bflo(h1), v.w - bfhi(h1));
        hi[i] = make_uint2(h0, h1);
        lo[i] = make_uint2(l0, l1);
    }
}

// =================================================================
// FUSED bf16-split MMA GEMM (round-10 config, verified 330us run)
// =================================================================
#define BM 128
#define BN 128
#define BK 32
#define LDSK 40
#define NKB (EMB / BK)                 // 24 iterations
#define TILE_B (BM * LDSK * 2)         // 10240 bytes, one hi or lo tile
#define GSTAGE_B (2 * TILE_B)          // 20480: hi tile then lo tile
#define GEMM_SMEM (4 * GSTAGE_B)       // 81920 (A:2 stages, B:2 stages)

__device__ __forceinline__ void gemm_issue(
    int kb, int buf,
    const bf16* __restrict__ Ahi, const bf16* __restrict__ Alo,
    const bf16* __restrict__ Bhi, const bf16* __restrict__ Blo,
    uint32_t asb, uint32_t bsb, int m0, int n0, int srow, int schk)
{
    int k0 = kb * BK;
    uint32_t sa = asb + (uint32_t)buf * GSTAGE_B;
    uint32_t sb = bsb + (uint32_t)buf * GSTAGE_B;
    uint32_t o0 = (srow * LDSK + schk) * 2;
    uint32_t o1 = ((srow + 64) * LDSK + schk) * 2;
    size_t g0 = (size_t)(m0 + srow) * EMB + k0 + schk;
    size_t g1 = (size_t)(m0 + srow + 64) * EMB + k0 + schk;
    size_t h0 = (size_t)(n0 + srow) * EMB + k0 + schk;
    size_t h1 = (size_t)(n0 + srow + 64) * EMB + k0 + schk;
    cp16(sa + o0, Ahi + g0);
    cp16(sa + o1, Ahi + g1);
    cp16(sa + TILE_B + o0, Alo + g0);
    cp16(sa + TILE_B + o1, Alo + g1);
    cp16(sb + o0, Bhi + h0);
    cp16(sb + o1, Bhi + h1);
    cp16(sb + TILE_B + o0, Blo + h0);
    cp16(sb + TILE_B + o1, Blo + h1);
    asm volatile("cp.async.commit_group;");
}

template<int REMAP>
__device__ __forceinline__ void mma_gemm_body(
    const bf16* __restrict__ Ahi, const bf16* __restrict__ Alo,
    const bf16* __restrict__ Bhi, const bf16* __restrict__ Blo,
    const float* __restrict__ bias, float* __restrict__ C,
    bf16* __restrict__ Chi, bf16* __restrict__ Clo,
    int m0, int n0, float scale)
{
    extern __shared__ char dsm[];
    const uint32_t asb = (uint32_t)__cvta_generic_to_shared(dsm);
    const uint32_t bsb = asb + 2 * GSTAGE_B;

    const int tid = threadIdx.x;
    const int lane = tid & 31;
    const int wid = tid >> 5;
    const int wm = wid >> 2;
    const int wn = wid & 3;

    float acc[4][4][4];
#pragma unroll
    for (int i = 0; i < 4; i++)
#pragma unroll
        for (int j = 0; j < 4; j++)
#pragma unroll
            for (int t = 0; t < 4; t++) acc[i][j][t] = 0.f;

    const int srow = tid >> 2;
    const int schk = (tid & 3) * 8;

    const int laRow = wm * 64 + (lane & 15);
    const int laCol = (lane >> 4) * 8;
    const int lbRow = wn * 32 + ((lane >> 4) << 3) + (lane & 7);
    const int lbCol = ((lane >> 3) & 1) * 8;

    gemm_issue(0, 0, Ahi, Alo, Bhi, Blo, asb, bsb, m0, n0, srow, schk);

    for (int it = 0; it < NKB; it++) {
        const int buf = it & 1;
        if (it + 1 < NKB) {
            gemm_issue(it + 1, buf ^ 1, Ahi, Alo, Bhi, Blo, asb, bsb,
                       m0, n0, srow, schk);
            cp_wait<1>();
        } else {
            cp_wait<0>();
        }
        __syncthreads();

        const uint32_t sa = asb + (uint32_t)buf * GSTAGE_B;
        const uint32_t sb = bsb + (uint32_t)buf * GSTAGE_B;

#pragma unroll
        for (int ks = 0; ks < 2; ks++) {
            const uint32_t aoff = (uint32_t)(ks * 16 + laCol) * 2;
            const uint32_t boff = (uint32_t)(ks * 16 + lbCol) * 2;
            uint32_t a[4][4], a2[4][4], b[2][4];
#pragma unroll
            for (int mt = 0; mt < 4; mt++)
                ldsm4(a[mt][0], a[mt][1], a[mt][2], a[mt][3],
                      sa + (uint32_t)((laRow + mt * 16) * LDSK) * 2 + aoff);
#pragma unroll
            for (int p = 0; p < 2; p++)
                ldsm4(b[p][0], b[p][1], b[p][2], b[p][3],
                      sb + (uint32_t)((lbRow + p * 16) * LDSK) * 2 + boff);
#pragma unroll
            for (int mt = 0; mt < 4; mt++)
#pragma unroll
                for (int nt = 0; nt < 4; nt++)
                    mma16816(acc[mt][nt], a[mt],
                             b[nt >> 1][(nt & 1) * 2], b[nt >> 1][(nt & 1) * 2 + 1]);
#pragma unroll
            for (int mt = 0; mt < 4; mt++)
                ldsm4(a2[mt][0], a2[mt][1], a2[mt][2], a2[mt][3],
                      sa + TILE_B + (uint32_t)((laRow + mt * 16) * LDSK) * 2 + aoff);
#pragma unroll
            for (int mt = 0; mt < 4; mt++)
#pragma unroll
                for (int nt = 0; nt < 4; nt++)
                    mma16816(acc[mt][nt], a2[mt],
                             b[nt >> 1][(nt & 1) * 2], b[nt >> 1][(nt & 1) * 2 + 1]);
#pragma unroll
            for (int p = 0; p < 2; p++)
                ldsm4(b[p][0], b[p][1], b[p][2], b[p][3],
                      sb + TILE_B + (uint32_t)((lbRow + p * 16) * LDSK) * 2 + boff);
#pragma unroll
            for (int mt = 0; mt < 4; mt++)
#pragma unroll
                for (int nt = 0; nt < 4; nt++)
                    mma16816(acc[mt][nt], a[mt],
                             b[nt >> 1][(nt & 1) * 2], b[nt >> 1][(nt & 1) * 2 + 1]);
        }
        __syncthreads();
    }

    const int er = lane >> 2;
    const int ec = (lane & 3) * 2;
#pragma unroll
    for (int mt = 0; mt < 4; mt++) {
        int m = m0 + wm * 64 + mt * 16 + er;
#pragma unroll
        for (int nt = 0; nt < 4; nt++) {
            int n = n0 + wn * 32 + nt * 8 + ec;
            float b0 = bias[n], b1 = bias[n + 1];
            float v00 = (acc[mt][nt][0] + b0) * scale;
            float v01 = (acc[mt][nt][1] + b1) * scale;
            float v10 = (acc[mt][nt][2] + b0) * scale;
            float v11 = (acc[mt][nt][3] + b1) * scale;
            if (REMAP) {
                int h = n >> 6, d = n & 63;
                int bb0 = m >> 11, s0 = m & 2047;
                int bb1 = (m + 8) >> 11, s1 = (m + 8) & 2047;
                size_t p0 = (((size_t)(bb0 * NH + h)) * SEQ + s0) * HD + d;
                size_t p1 = (((size_t)(bb1 * NH + h)) * SEQ + s1) * HD + d;
                uint32_t hp = cvt_bf2(v00, v01);
                uint32_t lp = cvt_bf2(v00 - bflo(hp), v01 - bfhi(hp));
                *(uint32_t*)&Chi[p0] = hp;
                *(uint32_t*)&Clo[p0] = lp;
                hp = cvt_bf2(v10, v11);
                lp = cvt_bf2(v10 - bflo(hp), v11 - bfhi(hp));
                *(uint32_t*)&Chi[p1] = hp;
                *(uint32_t*)&Clo[p1] = lp;
            } else {
                *(float2*)&C[(size_t)m * EMB + n] = make_float2(v00, v01);
                *(float2*)&C[(size_t)(m + 8) * EMB + n] = make_float2(v10, v11);
            }
        }
    }
}

__global__ __launch_bounds__(256, 2) void qkv_mma(
    const float* __restrict__ bq, const float* __restrict__ bk,
    const float* __restrict__ bv)
{
    int m0 = blockIdx.y * BM;
    int ng = blockIdx.x * BN;
    int sel = ng / EMB;
    int n0 = ng - sel * EMB;
    const bf16* Bhi = g_whi[sel];
    const bf16* Blo = g_wlo[sel];
    const float* bias = (sel == 0) ? bq : (sel == 1) ? bk : bv;
    bf16* Chi = (sel == 0) ? g_qhi : (sel == 1) ? g_khi : g_vhi;
    bf16* Clo = (sel == 0) ? g_qlo : (sel == 1) ? g_klo : g_vlo;
    float scale = (sel == 0) ? 0.125f * 1.4426950408889634f : 1.0f;
    mma_gemm_body<1>(g_xhi, g_xlo, Bhi, Blo, bias, nullptr, Chi, Clo,
                     m0, n0, scale);
}

__global__ __launch_bounds__(256, 2) void out_mma(
    const float* __restrict__ bo, float* __restrict__ out)
{
    mma_gemm_body<0>(g_aohi, g_aolo, g_whi[3], g_wlo[3], bo, out,
                     nullptr, nullptr, blockIdx.y * BM, blockIdx.x * BN, 1.0f);
}

// =================================================================
// Tensor-core flash attention, fixed-base softmax + SPLIT-KV.
// Fixed-base softmax => split-KV partials merge by pure addition
// (o = o_a + o_b, l = l_a + l_b) -- no max rescaling.
// q-tiles qt>=8 split into 2 KV halves; 576 units heavy-first.
// =================================================================
#define STR 72
#define KV_STAGE_B (256 * STR * 2)       // 36864
#define ATT_SMEM (3 * KV_STAGE_B)        // 110592

__device__ __forceinline__ void kv_issue(uint32_t sb, int buf, int kbase,
                                         const bf16* const kvsrc[4], int tid)
{
    uint32_t base = sb + (uint32_t)buf * KV_STAGE_B;
#pragma unroll
    for (int i = 0; i < 8; i++) {
        int c = i * 256 + tid;
        int row = (c >> 3) & 63;
        int ch = (c & 7) * 8;
        cp16(base + (uint32_t)(((i >> 1) * 64 + row) * STR + ch) * 2,
             kvsrc[i >> 1] + (size_t)(kbase + row) * HD + ch);
    }
    asm volatile("cp.async.commit_group;");
}

__global__ __launch_bounds__(256, 2) void attn_mma(
    const bf16* __restrict__ Qhi_g, const bf16* __restrict__ Qlo_g,
    const bf16* __restrict__ Khi_g, const bf16* __restrict__ Klo_g,
    const bf16* __restrict__ Vhi_g, const bf16* __restrict__ Vlo_g,
    bf16* __restrict__ AOhi, bf16* __restrict__ AOlo,
    float* __restrict__ PO, float* __restrict__ PL)
{
    extern __shared__ char dsm[];
    const uint32_t sb = (uint32_t)__cvta_generic_to_shared(dsm);

    const int bid = blockIdx.x;
    const int unit = bid / (BATCH * NH);
    const int bh = bid % (BATCH * NH);
    const int qt = UQT[unit];
    const int hf = UHF[unit];
    const int qbase = qt * 128;
    int kstart, nktl;
    if (hf == 2) { kstart = 0; nktl = 2 * qt + 2; }
    else         { nktl = qt + 1; kstart = hf * nktl; }

    const int tid = threadIdx.x;
    const int lane = tid & 31;
    const int wid = tid >> 5;
    const int wr = wid * 16;

    const size_t hoff = (size_t)bh * SEQ * HD;
    const bf16* qsrc[2] = {Qhi_g + hoff, Qlo_g + hoff};
    const bf16* kvsrc[4] = {Khi_g + hoff, Klo_g + hoff, Vhi_g + hoff, Vlo_g + hoff};

    // stage Q into ring[0] (hi rows 0..127, lo rows 128..255)
#pragma unroll
    for (int i = 0; i < 8; i++) {
        int c = i * 256 + tid;
        int row = (c >> 3) & 127;
        int ch = (c & 7) * 8;
        cp16(sb + (uint32_t)(((i >> 2) * 128 + row) * STR + ch) * 2,
             qsrc[i >> 2] + (size_t)(qbase + row) * HD + ch);
    }
    asm volatile("cp.async.commit_group;");
    cp_wait<0>();
    __syncthreads();

    uint32_t qh[4][4], ql[4][4];
    {
        int arow = wr + (lane & 15);
        int acol = (lane >> 4) * 8;
#pragma unroll
        for (int ks = 0; ks < 4; ks++) {
            ldsm4(qh[ks][0], qh[ks][1], qh[ks][2], qh[ks][3],
                  sb + (uint32_t)(arow * STR + ks * 16 + acol) * 2);
            ldsm4(ql[ks][0], ql[ks][1], ql[ks][2], ql[ks][3],
                  sb + (uint32_t)((128 + arow) * STR + ks * 16 + acol) * 2);
        }
    }
    __syncthreads();

    float o[8][4];
#pragma unroll
    for (int i = 0; i < 8; i++)
#pragma unroll
        for (int j = 0; j < 4; j++) o[i][j] = 0.f;
    float rs0 = 0.f, rs1 = 0.f;

    kv_issue(sb, 0, kstart * 64, kvsrc, tid);
    kv_issue(sb, 1, (kstart + 1) * 64, kvsrc, tid);

    const int brow = (lane & 7) + ((lane >> 4) << 3);
    const int bcol = ((lane >> 3) & 1) * 8;
    const int vrow = (lane & 7) + (((lane >> 3) & 1) << 3);
    const int vcol = (lane >> 4) * 8;

    int st = 0;
    for (int kt = 0; kt < nktl; kt++) {
        if (kt + 1 < nktl) cp_wait<1>(); else cp_wait<0>();
        __syncthreads();
        if (kt + 2 < nktl) {
            int b2 = st + 2; if (b2 >= 3) b2 -= 3;
            kv_issue(sb, b2, (kstart + kt + 2) * 64, kvsrc, tid);
        }

        const uint32_t kvb = sb + (uint32_t)st * KV_STAGE_B;
        const uint32_t Khi_s = kvb;
        const uint32_t Klo_s = kvb + 64 * STR * 2;
        const uint32_t Vhi_s = kvb + 128 * STR * 2;
        const uint32_t Vlo_s = kvb + 192 * STR * 2;
        const int kbase = (kstart + kt) * 64;

        float s[8][4];
#pragma unroll
        for (int i = 0; i < 8; i++)
#pragma unroll
            for (int j = 0; j < 4; j++) s[i][j] = 0.f;

#pragma unroll
        for (int ks = 0; ks < 4; ks++) {
            uint32_t bb[4][4];
#pragma unroll
            for (int ng = 0; ng < 4; ng++)
                ldsm4(bb[ng][0], bb[ng][1], bb[ng][2], bb[ng][3],
                      Khi_s + (uint32_t)((16 * ng + brow) * STR + 16 * ks + bcol) * 2);
#pragma unroll
            for (int ng = 0; ng < 4; ng++) {
                mma16816(s[2 * ng], qh[ks], bb[ng][0], bb[ng][1]);
                mma16816(s[2 * ng + 1], qh[ks], bb[ng][2], bb[ng][3]);
                mma16816(s[2 * ng], ql[ks], bb[ng][0], bb[ng][1]);
                mma16816(s[2 * ng + 1], ql[ks], bb[ng][2], bb[ng][3]);
            }
#pragma unroll
            for (int ng = 0; ng < 4; ng++)
                ldsm4(bb[ng][0], bb[ng][1], bb[ng][2], bb[ng][3],
                      Klo_s + (uint32_t)((16 * ng + brow) * STR + 16 * ks + bcol) * 2);
#pragma unroll
            for (int ng = 0; ng < 4; ng++) {
                mma16816(s[2 * ng], qh[ks], bb[ng][0], bb[ng][1]);
                mma16816(s[2 * ng + 1], qh[ks], bb[ng][2], bb[ng][3]);
            }
        }

        if (kbase + 63 > qbase + wr) {
            int row0 = qbase + wr + (lane >> 2);
            int colb = kbase + 2 * (lane & 3);
#pragma unroll
            for (int nt = 0; nt < 8; nt++) {
                int c0 = colb + nt * 8;
                if (c0 > row0) s[nt][0] = -1e30f;
                if (c0 + 1 > row0) s[nt][1] = -1e30f;
                if (c0 > row0 + 8) s[nt][2] = -1e30f;
                if (c0 + 1 > row0 + 8) s[nt][3] = -1e30f;
            }
        }

        // fixed-base softmax: P = exp2(s) directly
#pragma unroll
        for (int nt = 0; nt < 8; nt++) {
            s[nt][0] = ex2f(s[nt][0]); rs0 += s[nt][0];
            s[nt][1] = ex2f(s[nt][1]); rs0 += s[nt][1];
            s[nt][2] = ex2f(s[nt][2]); rs1 += s[nt][2];
            s[nt][3] = ex2f(s[nt][3]); rs1 += s[nt][3];
        }

        uint32_t phi[4][4], plo[4][4];
#pragma unroll
        for (int t = 0; t < 4; t++) {
#pragma unroll
            for (int half = 0; half < 2; half++) {
                const float* sp = s[2 * t + half];
                int i0 = half * 2, i1 = half * 2 + 1;
                uint32_t h0 = cvt_bf2(sp[0], sp[1]);
                phi[t][i0] = h0;
                plo[t][i0] = cvt_bf2(sp[0] - bflo(h0), sp[1] - bfhi(h0));
                uint32_t h1 = cvt_bf2(sp[2], sp[3]);
                phi[t][i1] = h1;
                plo[t][i1] = cvt_bf2(sp[2] - bflo(h1), sp[3] - bfhi(h1));
            }
        }

#pragma unroll
        for (int t = 0; t < 4; t++) {
            uint32_t vb[4][4];
#pragma unroll
            for (int g = 0; g < 4; g++)
                ldsm4t(vb[g][0], vb[g][1], vb[g][2], vb[g][3],
                       Vhi_s + (uint32_t)((16 * t + vrow) * STR + 16 * g + vcol) * 2);
#pragma unroll
            for (int g = 0; g < 4; g++) {
                mma16816(o[2 * g], phi[t], vb[g][0], vb[g][1]);
                mma16816(o[2 * g + 1], phi[t], vb[g][2], vb[g][3]);
                mma16816(o[2 * g], plo[t], vb[g][0], vb[g][1]);
                mma16816(o[2 * g + 1], plo[t], vb[g][2], vb[g][3]);
            }
#pragma unroll
            for (int g = 0; g < 4; g++)
                ldsm4t(vb[g][0], vb[g][1], vb[g][2], vb[g][3],
                       Vlo_s + (uint32_t)((16 * t + vrow) * STR + 16 * g + vcol) * 2);
#pragma unroll
            for (int g = 0; g < 4; g++) {
                mma16816(o[2 * g], phi[t], vb[g][0], vb[g][1]);
                mma16816(o[2 * g + 1], phi[t], vb[g][2], vb[g][3]);
            }
        }

        st = (st + 1 == 3) ? 0 : st + 1;
    }

    // l reduction within the 4-lane row group
    rs0 += __shfl_xor_sync(0xffffffffu, rs0, 1);
    rs0 += __shfl_xor_sync(0xffffffffu, rs0, 2);
    rs1 += __shfl_xor_sync(0xffffffffu, rs1, 1);
    rs1 += __shfl_xor_sync(0xffffffffu, rs1, 2);

    if (hf != 2) {
        // ---- split: write fp32 partials (undivided o, partial l) ----
        int sidx = (bh * 8 + (qt - 8)) * 2 + hf;
        float* po = PO + (size_t)sidx * (128 * 64);
        float* pl = PL + (size_t)sidx * 128;
        int rl = wr + (lane >> 2);
        int cb = 2 * (lane & 3);
#pragma unroll
        for (int nd = 0; nd < 8; nd++) {
            *(float2*)&po[rl * 64 + cb + nd * 8] = make_float2(o[nd][0], o[nd][1]);
            *(float2*)&po[(rl + 8) * 64 + cb + nd * 8] = make_float2(o[nd][2], o[nd][3]);
        }
        if ((lane & 3) == 0) { pl[rl] = rs0; pl[rl + 8] = rs1; }
        return;
    }

    // ---- unsplit: normalize and write ao hi/lo directly ----
    float inv0 = 1.f / rs0, inv1 = 1.f / rs1;
    int b = bh / NH, h = bh % NH;
    int row0 = qbase + wr + (lane >> 2);
    size_t off0 = ((size_t)b * SEQ + row0) * EMB + h * HD + 2 * (lane & 3);
    size_t off1 = off0 + 8 * (size_t)EMB;
#pragma unroll
    for (int nd = 0; nd < 8; nd++) {
        float f0 = o[nd][0] * inv0, f1 = o[nd][1] * inv0;
        uint32_t hp = cvt_bf2(f0, f1);
        uint32_t lp = cvt_bf2(f0 - bflo(hp), f1 - bfhi(hp));
        *(uint32_t*)&AOhi[off0 + nd * 8] = hp;
        *(uint32_t*)&AOlo[off0 + nd * 8] = lp;
        float g0 = o[nd][2] * inv1, g1 = o[nd][3] * inv1;
        uint32_t hq = cvt_bf2(g0, g1);
        uint32_t lq = cvt_bf2(g0 - bflo(hq), g1 - bfhi(hq));
        *(uint32_t*)&AOhi[off1 + nd * 8] = hq;
        *(uint32_t*)&AOlo[off1 + nd * 8] = lq;
    }
}

// =================================================================
// combine split-KV partials: o = o0+o1, l = l0+l1, ao = o/l (hi/lo)
// grid = 24 bh * 8 split q-tiles = 192 blocks
// =================================================================
__global__ __launch_bounds__(256) void attn_combine(
    const float* __restrict__ PO, const float* __restrict__ PL,
    bf16* __restrict__ AOhi, bf16* __restrict__ AOlo)
{
    int blk = blockIdx.x;
    int bh = blk >> 3;
    int qidx = blk & 7;
    int qt = qidx + 8;
    int qbase = qt * 128;
    int b = bh / NH, h = bh % NH;

    size_t s0 = ((size_t)(bh * 8 + qidx) * 2) * (128 * 64);
    const float* po0 = PO + s0;
    const float* po1 = po0 + 128 * 64;
    const float* pl0 = PL + ((size_t)(bh * 8 + qidx) * 2) * 128;
    const float* pl1 = pl0 + 128;

    int t = threadIdx.x;
    int r = t >> 1;
    int c0 = (t & 1) * 32;
    float inv = 1.f / (pl0[r] + pl1[r]);
    size_t go = ((size_t)b * SEQ + qbase + r) * EMB + h * HD + c0;
    int ro = r * 64 + c0;
#pragma unroll
    for (int c = 0; c < 32; c += 4) {
        float4 x0 = *(const float4*)&po0[ro + c];
        float4 x1 = *(const float4*)&po1[ro + c];
        float f0 = (x0.x + x1.x) * inv;
        float f1 = (x0.y + x1.y) * inv;
        float f2 = (x0.z + x1.z) * inv;
        float f3 = (x0.w + x1.w) * inv;
        uint32_t h0 = cvt_bf2(f0, f1), h1 = cvt_bf2(f2, f3);
        uint32_t l0 = cvt_bf2(f0 - bflo(h0), f1 - bfhi(h0));
        uint32_t l1 = cvt_bf2(f2 - bflo(h1), f3 - bfhi(h1));
        *(uint2*)&AOhi[go + c] = make_uint2(h0, h1);
        *(uint2*)&AOlo[go + c] = make_uint2(l0, l1);
    }
}

// =================================================================
// launch
// =================================================================
extern "C" void kernel_launch(void* const* d_in, const int* in_sizes, int n_in,
                              void* d_out, int out_size)
{
    const float* x    = (const float*)d_in[0];
    const float* wq_b = (const float*)d_in[2];
    const float* wk_b = (const float*)d_in[4];
    const float* wv_b = (const float*)d_in[6];
    const float* wo_b = (const float*)d_in[8];
    float* out = (float*)d_out;

    bf16 *xhi, *xlo;
    bf16 *qhi, *qlo, *khi, *klo, *vhi, *vlo, *aohi, *aolo;
    float *po, *pl;
    cudaGetSymbolAddress((void**)&xhi, g_xhi);
    cudaGetSymbolAddress((void**)&xlo, g_xlo);
    cudaGetSymbolAddress((void**)&qhi, g_qhi);
    cudaGetSymbolAddress((void**)&qlo, g_qlo);
    cudaGetSymbolAddress((void**)&khi, g_khi);
    cudaGetSymbolAddress((void**)&klo, g_klo);
    cudaGetSymbolAddress((void**)&vhi, g_vhi);
    cudaGetSymbolAddress((void**)&vlo, g_vlo);
    cudaGetSymbolAddress((void**)&aohi, g_aohi);
    cudaGetSymbolAddress((void**)&aolo, g_aolo);
    cudaGetSymbolAddress((void**)&po, g_po);
    cudaGetSymbolAddress((void**)&pl, g_pl);

    cudaFuncSetAttribute(attn_mma,
                         cudaFuncAttributeMaxDynamicSharedMemorySize, ATT_SMEM);
    cudaFuncSetAttribute(qkv_mma,
                         cudaFuncAttributeMaxDynamicSharedMemorySize, GEMM_SMEM);
    cudaFuncSetAttribute(out_mma,
                         cudaFuncAttributeMaxDynamicSharedMemorySize, GEMM_SMEM);

    const int nx4 = MROWS * EMB / 4;
    split4_kernel<<<(nx4 + 255) / 256, 256>>>((const float4*)x,
                                              (uint2*)xhi, (uint2*)xlo, nx4);
    dim3 gw((EMB * EMB / 4 + 255) / 256, 1, 4);
    split_w4_kernel<<<gw, 256>>>((const float*)d_in[1], (const float*)d_in[3],
                                 (const float*)d_in[5], (const float*)d_in[7]);

    dim3 gqkv(NQKV / BN, MROWS / BM);              // 18 x 32 = 576
    qkv_mma<<<gqkv, 256, GEMM_SMEM>>>(wq_b, wk_b, wv_b);

    // 24 units (16 split halves + 8 unsplit) x 24 bh, heavy-first
    attn_mma<<<24 * BATCH * NH, 256, ATT_SMEM>>>(
        qhi, qlo, khi, klo, vhi, vlo, aohi, aolo, po, pl);
    attn_combine<<<192, 256>>>(po, pl, aohi, aolo);

    dim3 go(EMB / BN, MROWS / BM);                 // 6 x 32
    out_mma<<<go, 256, GEMM_SMEM>>>(wo_b, out);
}

// round 12
// speedup vs baseline: 1.7422x; 1.0078x over previous
#include <cuda_runtime.h>
#include <cuda_bf16.h>
#include <cstdint>

#define SEQ   2048
#define EMB   768
#define NH    12
#define HD    64
#define BATCH 2
#define MROWS (BATCH * SEQ)   // 4096
#define NQKV  (3 * EMB)       // 2304

typedef __nv_bfloat16 bf16;

// ---------------- scratch (static device arrays; no allocation) -------------
__device__ bf16 g_xhi[MROWS * EMB], g_xlo[MROWS * EMB];
__device__ bf16 g_whi[4][EMB * EMB], g_wlo[4][EMB * EMB];   // q,k,v,o
__device__ bf16 g_qhi[BATCH * NH * SEQ * HD], g_qlo[BATCH * NH * SEQ * HD];
__device__ bf16 g_khi[BATCH * NH * SEQ * HD], g_klo[BATCH * NH * SEQ * HD];
__device__ bf16 g_vhi[BATCH * NH * SEQ * HD], g_vlo[BATCH * NH * SEQ * HD];
__device__ bf16 g_aohi[MROWS * EMB], g_aolo[MROWS * EMB];
// split-KV partials: 24 bh x 8 split q-tiles x 2 halves
__device__ float g_po[24 * 8 * 2 * 128 * 64];
__device__ float g_pl[24 * 8 * 2 * 128];

// heavy-first unit schedule: 16 split halves (qt 8..15) + 8 unsplit (qt 0..7)
__constant__ int8_t UQT[24] = {15,15,7,14,14,13,13,6,12,12,11,11,5,10,10,9,9,4,8,8,3,2,1,0};
__constant__ int8_t UHF[24] = {0,1,2,0,1,0,1,2,0,1,0,1,2,0,1,0,1,2,0,1,2,2,2,2};

// ---------------- small helpers ----------------
__device__ __forceinline__ uint32_t cvt_bf2(float lo, float hi) {
    uint32_t r;
    asm("cvt.rn.bf16x2.f32 %0, %1, %2;" : "=r"(r) : "f"(hi), "f"(lo));
    return r;
}
__device__ __forceinline__ float bflo(uint32_t p) { return __uint_as_float(p << 16); }
__device__ __forceinline__ float bfhi(uint32_t p) { return __uint_as_float(p & 0xffff0000u); }
__device__ __forceinline__ float ex2f(float x) {
    float y;
    asm("ex2.approx.ftz.f32 %0, %1;" : "=f"(y) : "f"(x));
    return y;
}
__device__ __forceinline__ void ldsm4(uint32_t& r0, uint32_t& r1,
                                      uint32_t& r2, uint32_t& r3, uint32_t addr)
{
    asm volatile("ldmatrix.sync.aligned.m8n8.x4.shared.b16 {%0,%1,%2,%3}, [%4];"
                 : "=r"(r0), "=r"(r1), "=r"(r2), "=r"(r3) : "r"(addr));
}
__device__ __forceinline__ void ldsm4t(uint32_t& r0, uint32_t& r1,
                                       uint32_t& r2, uint32_t& r3, uint32_t addr)
{
    asm volatile("ldmatrix.sync.aligned.m8n8.x4.trans.shared.b16 {%0,%1,%2,%3}, [%4];"
                 : "=r"(r0), "=r"(r1), "=r"(r2), "=r"(r3) : "r"(addr));
}
__device__ __forceinline__ void mma16816(float c[4], const uint32_t a[4],
                                         uint32_t b0, uint32_t b1)
{
    asm volatile(
        "mma.sync.aligned.m16n8k16.row.col.f32.bf16.bf16.f32 "
        "{%0,%1,%2,%3}, {%4,%5,%6,%7}, {%8,%9}, {%0,%1,%2,%3};"
        : "+f"(c[0]), "+f"(c[1]), "+f"(c[2]), "+f"(c[3])
        : "r"(a[0]), "r"(a[1]), "r"(a[2]), "r"(a[3]), "r"(b0), "r"(b1));
}
__device__ __forceinline__ void cp16(uint32_t saddr, const void* gaddr)
{
    asm volatile("cp.async.cg.shared.global [%0], [%1], 16;"
                 :: "r"(saddr), "l"(gaddr));
}
template<int N>
__device__ __forceinline__ void cp_wait()
{
    asm volatile("cp.async.wait_group %0;" :: "n"(N));
}

// =================================================================
// fp32 -> bf16 hi/lo split conversions (float4 vectorized)
// =================================================================
__global__ __launch_bounds__(256) void split4_kernel(
    const float4* __restrict__ src, uint2* __restrict__ hi,
    uint2* __restrict__ lo, int n4)
{
    int i = blockIdx.x * 256 + threadIdx.x;
    if (i < n4) {
        float4 v = src[i];
        uint32_t h0 = cvt_bf2(v.x, v.y);
        uint32_t h1 = cvt_bf2(v.z, v.w);
        uint32_t l0 = cvt_bf2(v.x - bflo(h0), v.y - bfhi(h0));
        uint32_t l1 = cvt_bf2(v.z - bflo(h1), v.w - bfhi(h1));
        hi[i] = make_uint2(h0, h1);
        lo[i] = make_uint2(l0, l1);
    }
}

__global__ __launch_bounds__(256) void split_w4_kernel(
    const float* __restrict__ wq, const float* __restrict__ wk,
    const float* __restrict__ wv, const float* __restrict__ wo)
{
    int z = blockIdx.z;
    const float4* src = (const float4*)((z == 0) ? wq : (z == 1) ? wk :
                                        (z == 2) ? wv : wo);
    uint2* hi = (uint2*)g_whi[z];
    uint2* lo = (uint2*)g_wlo[z];
    int i = blockIdx.x * 256 + threadIdx.x;
    if (i < EMB * EMB / 4) {
        float4 v = src[i];
        uint32_t h0 = cvt_bf2(v.x, v.y);
        uint32_t h1 = cvt_bf2(v.z, v.w);
        uint32_t l0 = cvt_bf2(v.x - bflo(h0), v.y - bfhi(h0));
        uint32_t l1 = cvt_bf2(v.z - bflo(h1), v.w - bfhi(h1));
        hi[i] = make_uint2(h0, h1);
        lo[i] = make_uint2(l0, l1);
    }
}

// =================================================================
// FUSED bf16-split MMA GEMM. Single-sync 2-stage ring:
//   wait<0>; sync; issue(it+1 -> buf^1); compute(buf)
// The sync proves all prior readers of buf^1 finished -> issue safe.
// =================================================================
#define BM 128
#define BN 128
#define BK 32
#define LDSK 40
#define NKB (EMB / BK)                 // 24 iterations
#define TILE_B (BM * LDSK * 2)         // 10240 bytes, one hi or lo tile
#define GSTAGE_B (2 * TILE_B)          // 20480: hi tile then lo tile
#define GEMM_SMEM (4 * GSTAGE_B)       // 81920

__device__ __forceinline__ void gemm_issue(
    int kb, int buf,
    const bf16* __restrict__ Ahi, const bf16* __restrict__ Alo,
    const bf16* __restrict__ Bhi, const bf16* __restrict__ Blo,
    uint32_t asb, uint32_t bsb, int m0, int n0, int srow, int schk)
{
    int k0 = kb * BK;
    uint32_t sa = asb + (uint32_t)buf * GSTAGE_B;
    uint32_t sb = bsb + (uint32_t)buf * GSTAGE_B;
    uint32_t o0 = (srow * LDSK + schk) * 2;
    uint32_t o1 = ((srow + 64) * LDSK + schk) * 2;
    size_t g0 = (size_t)(m0 + srow) * EMB + k0 + schk;
    size_t g1 = (size_t)(m0 + srow + 64) * EMB + k0 + schk;
    size_t h0 = (size_t)(n0 + srow) * EMB + k0 + schk;
    size_t h1 = (size_t)(n0 + srow + 64) * EMB + k0 + schk;
    cp16(sa + o0, Ahi + g0);
    cp16(sa + o1, Ahi + g1);
    cp16(sa + TILE_B + o0, Alo + g0);
    cp16(sa + TILE_B + o1, Alo + g1);
    cp16(sb + o0, Bhi + h0);
    cp16(sb + o1, Bhi + h1);
    cp16(sb + TILE_B + o0, Blo + h0);
    cp16(sb + TILE_B + o1, Blo + h1);
    asm volatile("cp.async.commit_group;");
}

template<int REMAP>
__device__ __forceinline__ void mma_gemm_body(
    const bf16* __restrict__ Ahi, const bf16* __restrict__ Alo,
    const bf16* __restrict__ Bhi, const bf16* __restrict__ Blo,
    const float* __restrict__ bias, float* __restrict__ C,
    bf16* __restrict__ Chi, bf16* __restrict__ Clo,
    int m0, int n0, float scale)
{
    extern __shared__ char dsm[];
    const uint32_t asb = (uint32_t)__cvta_generic_to_shared(dsm);
    const uint32_t bsb = asb + 2 * GSTAGE_B;

    const int tid = threadIdx.x;
    const int lane = tid & 31;
    const int wid = tid >> 5;
    const int wm = wid >> 2;
    const int wn = wid & 3;

    float acc[4][4][4];
#pragma unroll
    for (int i = 0; i < 4; i++)
#pragma unroll
        for (int j = 0; j < 4; j++)
#pragma unroll
            for (int t = 0; t < 4; t++) acc[i][j][t] = 0.f;

    const int srow = tid >> 2;
    const int schk = (tid & 3) * 8;

    const int laRow = wm * 64 + (lane & 15);
    const int laCol = (lane >> 4) * 8;
    const int lbRow = wn * 32 + ((lane >> 4) << 3) + (lane & 7);
    const int lbCol = ((lane >> 3) & 1) * 8;

    gemm_issue(0, 0, Ahi, Alo, Bhi, Blo, asb, bsb, m0, n0, srow, schk);

    for (int it = 0; it < NKB; it++) {
        const int buf = it & 1;
        cp_wait<0>();
        __syncthreads();
        if (it + 1 < NKB)
            gemm_issue(it + 1, buf ^ 1, Ahi, Alo, Bhi, Blo, asb, bsb,
                       m0, n0, srow, schk);

        const uint32_t sa = asb + (uint32_t)buf * GSTAGE_B;
        const uint32_t sb = bsb + (uint32_t)buf * GSTAGE_B;

#pragma unroll
        for (int ks = 0; ks < 2; ks++) {
            const uint32_t aoff = (uint32_t)(ks * 16 + laCol) * 2;
            const uint32_t boff = (uint32_t)(ks * 16 + lbCol) * 2;
            uint32_t a[4][4], a2[4][4], b[2][4];
#pragma unroll
            for (int mt = 0; mt < 4; mt++)
                ldsm4(a[mt][0], a[mt][1], a[mt][2], a[mt][3],
                      sa + (uint32_t)((laRow + mt * 16) * LDSK) * 2 + aoff);
#pragma unroll
            for (int p = 0; p < 2; p++)
                ldsm4(b[p][0], b[p][1], b[p][2], b[p][3],
                      sb + (uint32_t)((lbRow + p * 16) * LDSK) * 2 + boff);
#pragma unroll
            for (int mt = 0; mt < 4; mt++)
#pragma unroll
                for (int nt = 0; nt < 4; nt++)
                    mma16816(acc[mt][nt], a[mt],
                             b[nt >> 1][(nt & 1) * 2], b[nt >> 1][(nt & 1) * 2 + 1]);
#pragma unroll
            for (int mt = 0; mt < 4; mt++)
                ldsm4(a2[mt][0], a2[mt][1], a2[mt][2], a2[mt][3],
                      sa + TILE_B + (uint32_t)((laRow + mt * 16) * LDSK) * 2 + aoff);
#pragma unroll
            for (int mt = 0; mt < 4; mt++)
#pragma unroll
                for (int nt = 0; nt < 4; nt++)
                    mma16816(acc[mt][nt], a2[mt],
                             b[nt >> 1][(nt & 1) * 2], b[nt >> 1][(nt & 1) * 2 + 1]);
#pragma unroll
            for (int p = 0; p < 2; p++)
                ldsm4(b[p][0], b[p][1], b[p][2], b[p][3],
                      sb + TILE_B + (uint32_t)((lbRow + p * 16) * LDSK) * 2 + boff);
#pragma unroll
            for (int mt = 0; mt < 4; mt++)
#pragma unroll
                for (int nt = 0; nt < 4; nt++)
                    mma16816(acc[mt][nt], a[mt],
                             b[nt >> 1][(nt & 1) * 2], b[nt >> 1][(nt & 1) * 2 + 1]);
        }
    }

    const int er = lane >> 2;
    const int ec = (lane & 3) * 2;
#pragma unroll
    for (int mt = 0; mt < 4; mt++) {
        int m = m0 + wm * 64 + mt * 16 + er;
#pragma unroll
        for (int nt = 0; nt < 4; nt++) {
            int n = n0 + wn * 32 + nt * 8 + ec;
            float b0 = bias[n], b1 = bias[n + 1];
            float v00 = (acc[mt][nt][0] + b0) * scale;
            float v01 = (acc[mt][nt][1] + b1) * scale;
            float v10 = (acc[mt][nt][2] + b0) * scale;
            float v11 = (acc[mt][nt][3] + b1) * scale;
            if (REMAP) {
                int h = n >> 6, d = n & 63;
                int bb0 = m >> 11, s0 = m & 2047;
                int bb1 = (m + 8) >> 11, s1 = (m + 8) & 2047;
                size_t p0 = (((size_t)(bb0 * NH + h)) * SEQ + s0) * HD + d;
                size_t p1 = (((size_t)(bb1 * NH + h)) * SEQ + s1) * HD + d;
                uint32_t hp = cvt_bf2(v00, v01);
                uint32_t lp = cvt_bf2(v00 - bflo(hp), v01 - bfhi(hp));
                *(uint32_t*)&Chi[p0] = hp;
                *(uint32_t*)&Clo[p0] = lp;
                hp = cvt_bf2(v10, v11);
                lp = cvt_bf2(v10 - bflo(hp), v11 - bfhi(hp));
                *(uint32_t*)&Chi[p1] = hp;
                *(uint32_t*)&Clo[p1] = lp;
            } else {
                *(float2*)&C[(size_t)m * EMB + n] = make_float2(v00, v01);
                *(float2*)&C[(size_t)(m + 8) * EMB + n] = make_float2(v10, v11);
            }
        }
    }
}

__global__ __launch_bounds__(256, 2) void qkv_mma(
    const float* __restrict__ bq, const float* __restrict__ bk,
    const float* __restrict__ bv)
{
    int m0 = blockIdx.y * BM;
    int ng = blockIdx.x * BN;
    int sel = ng / EMB;
    int n0 = ng - sel * EMB;
    const bf16* Bhi = g_whi[sel];
    const bf16* Blo = g_wlo[sel];
    const float* bias = (sel == 0) ? bq : (sel == 1) ? bk : bv;
    bf16* Chi = (sel == 0) ? g_qhi : (sel == 1) ? g_khi : g_vhi;
    bf16* Clo = (sel == 0) ? g_qlo : (sel == 1) ? g_klo : g_vlo;
    float scale = (sel == 0) ? 0.125f * 1.4426950408889634f : 1.0f;
    mma_gemm_body<1>(g_xhi, g_xlo, Bhi, Blo, bias, nullptr, Chi, Clo,
                     m0, n0, scale);
}

__global__ __launch_bounds__(256, 2) void out_mma(
    const float* __restrict__ bo, float* __restrict__ out)
{
    mma_gemm_body<0>(g_aohi, g_aolo, g_whi[3], g_wlo[3], bo, out,
                     nullptr, nullptr, blockIdx.y * BM, blockIdx.x * BN, 1.0f);
}

// =================================================================
// Tensor-core flash attention, fixed-base softmax + split-KV.
// NEW: softmax/exp interleaved with PV at 16-KV-chunk granularity
// so MUFU bursts are sandwiched between HMMA issue (tensor pipe
// stays fed through the scalar phase).
// =================================================================
#define STR 72
#define KV_STAGE_B (256 * STR * 2)       // 36864
#define ATT_SMEM (3 * KV_STAGE_B)        // 110592

__device__ __forceinline__ void kv_issue(uint32_t sb, int buf, int kbase,
                                         const bf16* const kvsrc[4], int tid)
{
    uint32_t base = sb + (uint32_t)buf * KV_STAGE_B;
#pragma unroll
    for (int i = 0; i < 8; i++) {
        int c = i * 256 + tid;
        int row = (c >> 3) & 63;
        int ch = (c & 7) * 8;
        cp16(base + (uint32_t)(((i >> 1) * 64 + row) * STR + ch) * 2,
             kvsrc[i >> 1] + (size_t)(kbase + row) * HD + ch);
    }
    asm volatile("cp.async.commit_group;");
}

__global__ __launch_bounds__(256, 2) void attn_mma(
    const bf16* __restrict__ Qhi_g, const bf16* __restrict__ Qlo_g,
    const bf16* __restrict__ Khi_g, const bf16* __restrict__ Klo_g,
    const bf16* __restrict__ Vhi_g, const bf16* __restrict__ Vlo_g,
    bf16* __restrict__ AOhi, bf16* __restrict__ AOlo,
    float* __restrict__ PO, float* __restrict__ PL)
{
    extern __shared__ char dsm[];
    const uint32_t sb = (uint32_t)__cvta_generic_to_shared(dsm);

    const int bid = blockIdx.x;
    const int unit = bid / (BATCH * NH);
    const int bh = bid % (BATCH * NH);
    const int qt = UQT[unit];
    const int hf = UHF[unit];
    const int qbase = qt * 128;
    int kstart, nktl;
    if (hf == 2) { kstart = 0; nktl = 2 * qt + 2; }
    else         { nktl = qt + 1; kstart = hf * nktl; }

    const int tid = threadIdx.x;
    const int lane = tid & 31;
    const int wid = tid >> 5;
    const int wr = wid * 16;

    const size_t hoff = (size_t)bh * SEQ * HD;
    const bf16* qsrc[2] = {Qhi_g + hoff, Qlo_g + hoff};
    const bf16* kvsrc[4] = {Khi_g + hoff, Klo_g + hoff, Vhi_g + hoff, Vlo_g + hoff};

#pragma unroll
    for (int i = 0; i < 8; i++) {
        int c = i * 256 + tid;
        int row = (c >> 3) & 127;
        int ch = (c & 7) * 8;
        cp16(sb + (uint32_t)(((i >> 2) * 128 + row) * STR + ch) * 2,
             qsrc[i >> 2] + (size_t)(qbase + row) * HD + ch);
    }
    asm volatile("cp.async.commit_group;");
    cp_wait<0>();
    __syncthreads();

    uint32_t qh[4][4], ql[4][4];
    {
        int arow = wr + (lane & 15);
        int acol = (lane >> 4) * 8;
#pragma unroll
        for (int ks = 0; ks < 4; ks++) {
            ldsm4(qh[ks][0], qh[ks][1], qh[ks][2], qh[ks][3],
                  sb + (uint32_t)(arow * STR + ks * 16 + acol) * 2);
            ldsm4(ql[ks][0], ql[ks][1], ql[ks][2], ql[ks][3],
                  sb + (uint32_t)((128 + arow) * STR + ks * 16 + acol) * 2);
        }
    }
    __syncthreads();

    float o[8][4];
#pragma unroll
    for (int i = 0; i < 8; i++)
#pragma unroll
        for (int j = 0; j < 4; j++) o[i][j] = 0.f;
    float rs0 = 0.f, rs1 = 0.f;

    kv_issue(sb, 0, kstart * 64, kvsrc, tid);
    kv_issue(sb, 1, (kstart + 1) * 64, kvsrc, tid);

    const int brow = (lane & 7) + ((lane >> 4) << 3);
    const int bcol = ((lane >> 3) & 1) * 8;
    const int vrow = (lane & 7) + (((lane >> 3) & 1) << 3);
    const int vcol = (lane >> 4) * 8;

    int st = 0;
    for (int kt = 0; kt < nktl; kt++) {
        if (kt + 1 < nktl) cp_wait<1>(); else cp_wait<0>();
        __syncthreads();
        if (kt + 2 < nktl) {
            int b2 = st + 2; if (b2 >= 3) b2 -= 3;
            kv_issue(sb, b2, (kstart + kt + 2) * 64, kvsrc, tid);
        }

        const uint32_t kvb = sb + (uint32_t)st * KV_STAGE_B;
        const uint32_t Khi_s = kvb;
        const uint32_t Klo_s = kvb + 64 * STR * 2;
        const uint32_t Vhi_s = kvb + 128 * STR * 2;
        const uint32_t Vlo_s = kvb + 192 * STR * 2;
        const int kbase = (kstart + kt) * 64;

        // ---- S = Q K^T (3-pass split) ----
        float s[8][4];
#pragma unroll
        for (int i = 0; i < 8; i++)
#pragma unroll
            for (int j = 0; j < 4; j++) s[i][j] = 0.f;

#pragma unroll
        for (int ks = 0; ks < 4; ks++) {
            uint32_t bb[4][4];
#pragma unroll
            for (int ng = 0; ng < 4; ng++)
                ldsm4(bb[ng][0], bb[ng][1], bb[ng][2], bb[ng][3],
                      Khi_s + (uint32_t)((16 * ng + brow) * STR + 16 * ks + bcol) * 2);
#pragma unroll
            for (int ng = 0; ng < 4; ng++) {
                mma16816(s[2 * ng], qh[ks], bb[ng][0], bb[ng][1]);
                mma16816(s[2 * ng + 1], qh[ks], bb[ng][2], bb[ng][3]);
                mma16816(s[2 * ng], ql[ks], bb[ng][0], bb[ng][1]);
                mma16816(s[2 * ng + 1], ql[ks], bb[ng][2], bb[ng][3]);
            }
#pragma unroll
            for (int ng = 0; ng < 4; ng++)
                ldsm4(bb[ng][0], bb[ng][1], bb[ng][2], bb[ng][3],
                      Klo_s + (uint32_t)((16 * ng + brow) * STR + 16 * ks + bcol) * 2);
#pragma unroll
            for (int ng = 0; ng < 4; ng++) {
                mma16816(s[2 * ng], qh[ks], bb[ng][0], bb[ng][1]);
                mma16816(s[2 * ng + 1], qh[ks], bb[ng][2], bb[ng][3]);
            }
        }

        // ---- interleaved softmax + PV per 16-KV chunk t ----
        const bool diag = (kbase + 63 > qbase + wr);
        const int row0q = qbase + wr + (lane >> 2);
        const int colbq = kbase + 2 * (lane & 3);

#pragma unroll
        for (int t = 0; t < 4; t++) {
            if (diag) {
#pragma unroll
                for (int h2 = 0; h2 < 2; h2++) {
                    int nt = 2 * t + h2;
                    int c0 = colbq + nt * 8;
                    if (c0 > row0q) s[nt][0] = -1e30f;
                    if (c0 + 1 > row0q) s[nt][1] = -1e30f;
                    if (c0 > row0q + 8) s[nt][2] = -1e30f;
                    if (c0 + 1 > row0q + 8) s[nt][3] = -1e30f;
                }
            }
            uint32_t phi[4], plo[4];
#pragma unroll
            for (int h2 = 0; h2 < 2; h2++) {
                float* sp = s[2 * t + h2];
                sp[0] = ex2f(sp[0]); rs0 += sp[0];
                sp[1] = ex2f(sp[1]); rs0 += sp[1];
                sp[2] = ex2f(sp[2]); rs1 += sp[2];
                sp[3] = ex2f(sp[3]); rs1 += sp[3];
                uint32_t h0 = cvt_bf2(sp[0], sp[1]);
                phi[h2 * 2] = h0;
                plo[h2 * 2] = cvt_bf2(sp[0] - bflo(h0), sp[1] - bfhi(h0));
                uint32_t h1 = cvt_bf2(sp[2], sp[3]);
                phi[h2 * 2 + 1] = h1;
                plo[h2 * 2 + 1] = cvt_bf2(sp[2] - bflo(h1), sp[3] - bfhi(h1));
            }
            // PV for chunk t (V rows 16t..16t+15)
            uint32_t vb[4][4];
#pragma unroll
            for (int g = 0; g < 4; g++)
                ldsm4t(vb[g][0], vb[g][1], vb[g][2], vb[g][3],
                       Vhi_s + (uint32_t)((16 * t + vrow) * STR + 16 * g + vcol) * 2);
#pragma unroll
            for (int g = 0; g < 4; g++) {
                mma16816(o[2 * g], phi, vb[g][0], vb[g][1]);
                mma16816(o[2 * g + 1], phi, vb[g][2], vb[g][3]);
                mma16816(o[2 * g], plo, vb[g][0], vb[g][1]);
                mma16816(o[2 * g + 1], plo, vb[g][2], vb[g][3]);
            }
#pragma unroll
            for (int g = 0; g < 4; g++)
                ldsm4t(vb[g][0], vb[g][1], vb[g][2], vb[g][3],
                       Vlo_s + (uint32_t)((16 * t + vrow) * STR + 16 * g + vcol) * 2);
#pragma unroll
            for (int g = 0; g < 4; g++) {
                mma16816(o[2 * g], phi, vb[g][0], vb[g][1]);
                mma16816(o[2 * g + 1], phi, vb[g][2], vb[g][3]);
            }
        }

        st = (st + 1 == 3) ? 0 : st + 1;
    }

    // l reduction within the 4-lane row group
    rs0 += __shfl_xor_sync(0xffffffffu, rs0, 1);
    rs0 += __shfl_xor_sync(0xffffffffu, rs0, 2);
    rs1 += __shfl_xor_sync(0xffffffffu, rs1, 1);
    rs1 += __shfl_xor_sync(0xffffffffu, rs1, 2);

    if (hf != 2) {
        int sidx = (bh * 8 + (qt - 8)) * 2 + hf;
        float* po = PO + (size_t)sidx * (128 * 64);
        float* pl = PL + (size_t)sidx * 128;
        int rl = wr + (lane >> 2);
        int cb = 2 * (lane & 3);
#pragma unroll
        for (int nd = 0; nd < 8; nd++) {
            *(float2*)&po[rl * 64 + cb + nd * 8] = make_float2(o[nd][0], o[nd][1]);
            *(float2*)&po[(rl + 8) * 64 + cb + nd * 8] = make_float2(o[nd][2], o[nd][3]);
        }
        if ((lane & 3) == 0) { pl[rl] = rs0; pl[rl + 8] = rs1; }
        return;
    }

    float inv0 = 1.f / rs0, inv1 = 1.f / rs1;
    int b = bh / NH, h = bh % NH;
    int row0 = qbase + wr + (lane >> 2);
    size_t off0 = ((size_t)b * SEQ + row0) * EMB + h * HD + 2 * (lane & 3);
    size_t off1 = off0 + 8 * (size_t)EMB;
#pragma unroll
    for (int nd = 0; nd < 8; nd++) {
        float f0 = o[nd][0] * inv0, f1 = o[nd][1] * inv0;
        uint32_t hp = cvt_bf2(f0, f1);
        uint32_t lp = cvt_bf2(f0 - bflo(hp), f1 - bfhi(hp));
        *(uint32_t*)&AOhi[off0 + nd * 8] = hp;
        *(uint32_t*)&AOlo[off0 + nd * 8] = lp;
        float g0 = o[nd][2] * inv1, g1 = o[nd][3] * inv1;
        uint32_t hq = cvt_bf2(g0, g1);
        uint32_t lq = cvt_bf2(g0 - bflo(hq), g1 - bfhi(hq));
        *(uint32_t*)&AOhi[off1 + nd * 8] = hq;
        *(uint32_t*)&AOlo[off1 + nd * 8] = lq;
    }
}

// =================================================================
// combine split-KV partials: o = o0+o1, l = l0+l1, ao = o/l (hi/lo)
// =================================================================
__global__ __launch_bounds__(256) void attn_combine(
    const float* __restrict__ PO, const float* __restrict__ PL,
    bf16* __restrict__ AOhi, bf16* __restrict__ AOlo)
{
    int blk = blockIdx.x;
    int bh = blk >> 3;
    int qidx = blk & 7;
    int qt = qidx + 8;
    int qbase = qt * 128;
    int b = bh / NH, h = bh % NH;

    size_t s0 = ((size_t)(bh * 8 + qidx) * 2) * (128 * 64);
    const float* po0 = PO + s0;
    const float* po1 = po0 + 128 * 64;
    const float* pl0 = PL + ((size_t)(bh * 8 + qidx) * 2) * 128;
    const float* pl1 = pl0 + 128;

    int t = threadIdx.x;
    int r = t >> 1;
    int c0 = (t & 1) * 32;
    float inv = 1.f / (pl0[r] + pl1[r]);
    size_t go = ((size_t)b * SEQ + qbase + r) * EMB + h * HD + c0;
    int ro = r * 64 + c0;
#pragma unroll
    for (int c = 0; c < 32; c += 4) {
        float4 x0 = *(const float4*)&po0[ro + c];
        float4 x1 = *(const float4*)&po1[ro + c];
        float f0 = (x0.x + x1.x) * inv;
        float f1 = (x0.y + x1.y) * inv;
        float f2 = (x0.z + x1.z) * inv;
        float f3 = (x0.w + x1.w) * inv;
        uint32_t h0 = cvt_bf2(f0, f1), h1 = cvt_bf2(f2, f3);
        uint32_t l0 = cvt_bf2(f0 - bflo(h0), f1 - bfhi(h0));
        uint32_t l1 = cvt_bf2(f2 - bflo(h1), f3 - bfhi(h1));
        *(uint2*)&AOhi[go + c] = make_uint2(h0, h1);
        *(uint2*)&AOlo[go + c] = make_uint2(l0, l1);
    }
}

// =================================================================
// launch
// =================================================================
extern "C" void kernel_launch(void* const* d_in, const int* in_sizes, int n_in,
                              void* d_out, int out_size)
{
    const float* x    = (const float*)d_in[0];
    const float* wq_b = (const float*)d_in[2];
    const float* wk_b = (const float*)d_in[4];
    const float* wv_b = (const float*)d_in[6];
    const float* wo_b = (const float*)d_in[8];
    float* out = (float*)d_out;

    bf16 *xhi, *xlo;
    bf16 *qhi, *qlo, *khi, *klo, *vhi, *vlo, *aohi, *aolo;
    float *po, *pl;
    cudaGetSymbolAddress((void**)&xhi, g_xhi);
    cudaGetSymbolAddress((void**)&xlo, g_xlo);
    cudaGetSymbolAddress((void**)&qhi, g_qhi);
    cudaGetSymbolAddress((void**)&qlo, g_qlo);
    cudaGetSymbolAddress((void**)&khi, g_khi);
    cudaGetSymbolAddress((void**)&klo, g_klo);
    cudaGetSymbolAddress((void**)&vhi, g_vhi);
    cudaGetSymbolAddress((void**)&vlo, g_vlo);
    cudaGetSymbolAddress((void**)&aohi, g_aohi);
    cudaGetSymbolAddress((void**)&aolo, g_aolo);
    cudaGetSymbolAddress((void**)&po, g_po);
    cudaGetSymbolAddress((void**)&pl, g_pl);

    cudaFuncSetAttribute(attn_mma,
                         cudaFuncAttributeMaxDynamicSharedMemorySize, ATT_SMEM);
    cudaFuncSetAttribute(qkv_mma,
                         cudaFuncAttributeMaxDynamicSharedMemorySize, GEMM_SMEM);
    cudaFuncSetAttribute(out_mma,
                         cudaFuncAttributeMaxDynamicSharedMemorySize, GEMM_SMEM);

    const int nx4 = MROWS * EMB / 4;
    split4_kernel<<<(nx4 + 255) / 256, 256>>>((const float4*)x,
                                              (uint2*)xhi, (uint2*)xlo, nx4);
    dim3 gw((EMB * EMB / 4 + 255) / 256, 1, 4);
    split_w4_kernel<<<gw, 256>>>((const float*)d_in[1], (const float*)d_in[3],
                                 (const float*)d_in[5], (const float*)d_in[7]);

    dim3 gqkv(NQKV / BN, MROWS / BM);              // 18 x 32 = 576
    qkv_mma<<<gqkv, 256, GEMM_SMEM>>>(wq_b, wk_b, wv_b);

    attn_mma<<<24 * BATCH * NH, 256, ATT_SMEM>>>(
        qhi, qlo, khi, klo, vhi, vlo, aohi, aolo, po, pl);
    attn_combine<<<192, 256>>>(po, pl, aohi, aolo);

    dim3 go(EMB / BN, MROWS / BM);                 // 6 x 32
    out_mma<<<go, 256, GEMM_SMEM>>>(wo_b, out);
}

// round 13
// speedup vs baseline: 1.7763x; 1.0196x over previous
#include <cuda_runtime.h>
#include <cuda_bf16.h>
#include <cstdint>

#define SEQ   2048
#define EMB   768
#define NH    12
#define HD    64
#define BATCH 2
#define MROWS (BATCH * SEQ)   // 4096
#define NQKV  (3 * EMB)       // 2304

typedef __nv_bfloat16 bf16;

// ---------------- scratch (static device arrays; no allocation) -------------
__device__ bf16 g_xhi[MROWS * EMB], g_xlo[MROWS * EMB];
__device__ bf16 g_whi[4][EMB * EMB], g_wlo[4][EMB * EMB];   // q,k,v,o
__device__ bf16 g_qhi[BATCH * NH * SEQ * HD], g_qlo[BATCH * NH * SEQ * HD];
__device__ bf16 g_khi[BATCH * NH * SEQ * HD], g_klo[BATCH * NH * SEQ * HD];
__device__ bf16 g_vhi[BATCH * NH * SEQ * HD], g_vlo[BATCH * NH * SEQ * HD];
__device__ bf16 g_aohi[MROWS * EMB], g_aolo[MROWS * EMB];
// split-KV partials: 24 bh x 8 split q-tiles x 2 halves
__device__ float g_po[24 * 8 * 2 * 128 * 64];
__device__ float g_pl[24 * 8 * 2 * 128];

// heavy-first unit schedule: 16 split halves (qt 8..15) + 8 unsplit (qt 0..7)
__constant__ int8_t UQT[24] = {15,15,7,14,14,13,13,6,12,12,11,11,5,10,10,9,9,4,8,8,3,2,1,0};
__constant__ int8_t UHF[24] = {0,1,2,0,1,0,1,2,0,1,0,1,2,0,1,0,1,2,0,1,2,2,2,2};

// ---------------- small helpers ----------------
__device__ __forceinline__ uint32_t cvt_bf2(float lo, float hi) {
    uint32_t r;
    asm("cvt.rn.bf16x2.f32 %0, %1, %2;" : "=r"(r) : "f"(hi), "f"(lo));
    return r;
}
__device__ __forceinline__ float bflo(uint32_t p) { return __uint_as_float(p << 16); }
__device__ __forceinline__ float bfhi(uint32_t p) { return __uint_as_float(p & 0xffff0000u); }
__device__ __forceinline__ float ex2f(float x) {
    float y;
    asm("ex2.approx.ftz.f32 %0, %1;" : "=f"(y) : "f"(x));
    return y;
}
__device__ __forceinline__ void ldsm4(uint32_t& r0, uint32_t& r1,
                                      uint32_t& r2, uint32_t& r3, uint32_t addr)
{
    asm volatile("ldmatrix.sync.aligned.m8n8.x4.shared.b16 {%0,%1,%2,%3}, [%4];"
                 : "=r"(r0), "=r"(r1), "=r"(r2), "=r"(r3) : "r"(addr));
}
__device__ __forceinline__ void ldsm4t(uint32_t& r0, uint32_t& r1,
                                       uint32_t& r2, uint32_t& r3, uint32_t addr)
{
    asm volatile("ldmatrix.sync.aligned.m8n8.x4.trans.shared.b16 {%0,%1,%2,%3}, [%4];"
                 : "=r"(r0), "=r"(r1), "=r"(r2), "=r"(r3) : "r"(addr));
}
__device__ __forceinline__ void mma16816(float c[4], const uint32_t a[4],
                                         uint32_t b0, uint32_t b1)
{
    asm volatile(
        "mma.sync.aligned.m16n8k16.row.col.f32.bf16.bf16.f32 "
        "{%0,%1,%2,%3}, {%4,%5,%6,%7}, {%8,%9}, {%0,%1,%2,%3};"
        : "+f"(c[0]), "+f"(c[1]), "+f"(c[2]), "+f"(c[3])
        : "r"(a[0]), "r"(a[1]), "r"(a[2]), "r"(a[3]), "r"(b0), "r"(b1));
}
__device__ __forceinline__ void cp16(uint32_t saddr, const void* gaddr)
{
    asm volatile("cp.async.cg.shared.global [%0], [%1], 16;"
                 :: "r"(saddr), "l"(gaddr));
}
template<int N>
__device__ __forceinline__ void cp_wait()
{
    asm volatile("cp.async.wait_group %0;" :: "n"(N));
}

// =================================================================
// fp32 -> bf16 hi/lo split: one launch, z=0..3 weights, z=4 x
// =================================================================
__global__ __launch_bounds__(256) void split_all_kernel(
    const float* __restrict__ x,
    const float* __restrict__ wq, const float* __restrict__ wk,
    const float* __restrict__ wv, const float* __restrict__ wo,
    bf16* __restrict__ xhi, bf16* __restrict__ xlo)
{
    int z = blockIdx.z;
    const float4* src;
    uint2 *hi, *lo;
    int n4;
    if (z == 4) {
        src = (const float4*)x;
        hi = (uint2*)xhi; lo = (uint2*)xlo;
        n4 = MROWS * EMB / 4;
    } else {
        src = (const float4*)((z == 0) ? wq : (z == 1) ? wk :
                              (z == 2) ? wv : wo);
        hi = (uint2*)g_whi[z]; lo = (uint2*)g_wlo[z];
        n4 = EMB * EMB / 4;
    }
    int i = blockIdx.x * 256 + threadIdx.x;
    if (i < n4) {
        float4 v = src[i];
        uint32_t h0 = cvt_bf2(v.x, v.y);
        uint32_t h1 = cvt_bf2(v.z, v.w);
        uint32_t l0 = cvt_bf2(v.x - bflo(h0), v.y - bfhi(h0));
        uint32_t l1 = cvt_bf2(v.z - bflo(h1), v.w - bfhi(h1));
        hi[i] = make_uint2(h0, h1);
        lo[i] = make_uint2(l0, l1);
    }
}

// =================================================================
// FUSED bf16-split MMA GEMM. Single-sync 2-stage ring.
// Template MT = M-tiles per warp (4 -> BM=128, 2 -> BM=64).
// =================================================================
#define BN 128
#define BK 32
#define LDSK 40
#define NKB (EMB / BK)                 // 24 iterations
#define TILE_B (128 * LDSK * 2)        // 10240 bytes (full 128-row layout)
#define GSTAGE_B (2 * TILE_B)          // 20480: hi tile then lo tile
#define GEMM_SMEM (4 * GSTAGE_B)       // 81920

template<int MT>
__device__ __forceinline__ void gemm_issue(
    int kb, int buf,
    const bf16* __restrict__ Ahi, const bf16* __restrict__ Alo,
    const bf16* __restrict__ Bhi, const bf16* __restrict__ Blo,
    uint32_t asb, uint32_t bsb, int m0, int n0, int srow, int schk)
{
    int k0 = kb * BK;
    uint32_t sa = asb + (uint32_t)buf * GSTAGE_B;
    uint32_t sb = bsb + (uint32_t)buf * GSTAGE_B;
    uint32_t o0 = (srow * LDSK + schk) * 2;
    uint32_t o1 = ((srow + 64) * LDSK + schk) * 2;
    size_t g0 = (size_t)(m0 + srow) * EMB + k0 + schk;
    size_t h0 = (size_t)(n0 + srow) * EMB + k0 + schk;
    size_t h1 = (size_t)(n0 + srow + 64) * EMB + k0 + schk;
    cp16(sa + o0, Ahi + g0);
    cp16(sa + TILE_B + o0, Alo + g0);
    if (MT == 4) {
        size_t g1 = (size_t)(m0 + srow + 64) * EMB + k0 + schk;
        cp16(sa + o1, Ahi + g1);
        cp16(sa + TILE_B + o1, Alo + g1);
    }
    cp16(sb + o0, Bhi + h0);
    cp16(sb + o1, Bhi + h1);
    cp16(sb + TILE_B + o0, Blo + h0);
    cp16(sb + TILE_B + o1, Blo + h1);
    asm volatile("cp.async.commit_group;");
}

template<int REMAP, int MT>
__device__ __forceinline__ void mma_gemm_body(
    const bf16* __restrict__ Ahi, const bf16* __restrict__ Alo,
    const bf16* __restrict__ Bhi, const bf16* __restrict__ Blo,
    const float* __restrict__ bias, float* __restrict__ C,
    bf16* __restrict__ Chi, bf16* __restrict__ Clo,
    int m0, int n0, float scale)
{
    extern __shared__ char dsm[];
    const uint32_t asb = (uint32_t)__cvta_generic_to_shared(dsm);
    const uint32_t bsb = asb + 2 * GSTAGE_B;

    const int tid = threadIdx.x;
    const int lane = tid & 31;
    const int wid = tid >> 5;
    const int wm = wid >> 2;
    const int wn = wid & 3;

    float acc[MT][4][4];
#pragma unroll
    for (int i = 0; i < MT; i++)
#pragma unroll
        for (int j = 0; j < 4; j++)
#pragma unroll
            for (int t = 0; t < 4; t++) acc[i][j][t] = 0.f;

    const int srow = tid >> 2;
    const int schk = (tid & 3) * 8;

    const int laRow = wm * (MT * 16) + (lane & 15);
    const int laCol = (lane >> 4) * 8;
    const int lbRow = wn * 32 + ((lane >> 4) << 3) + (lane & 7);
    const int lbCol = ((lane >> 3) & 1) * 8;

    gemm_issue<MT>(0, 0, Ahi, Alo, Bhi, Blo, asb, bsb, m0, n0, srow, schk);

    for (int it = 0; it < NKB; it++) {
        const int buf = it & 1;
        cp_wait<0>();
        __syncthreads();
        if (it + 1 < NKB)
            gemm_issue<MT>(it + 1, buf ^ 1, Ahi, Alo, Bhi, Blo, asb, bsb,
                           m0, n0, srow, schk);

        const uint32_t sa = asb + (uint32_t)buf * GSTAGE_B;
        const uint32_t sb = bsb + (uint32_t)buf * GSTAGE_B;

#pragma unroll
        for (int ks = 0; ks < 2; ks++) {
            const uint32_t aoff = (uint32_t)(ks * 16 + laCol) * 2;
            const uint32_t boff = (uint32_t)(ks * 16 + lbCol) * 2;
            uint32_t a[MT][4], a2[MT][4], b[2][4];
#pragma unroll
            for (int mt = 0; mt < MT; mt++)
                ldsm4(a[mt][0], a[mt][1], a[mt][2], a[mt][3],
                      sa + (uint32_t)((laRow + mt * 16) * LDSK) * 2 + aoff);
#pragma unroll
            for (int p = 0; p < 2; p++)
                ldsm4(b[p][0], b[p][1], b[p][2], b[p][3],
                      sb + (uint32_t)((lbRow + p * 16) * LDSK) * 2 + boff);
#pragma unroll
            for (int mt = 0; mt < MT; mt++)
#pragma unroll
                for (int nt = 0; nt < 4; nt++)
                    mma16816(acc[mt][nt], a[mt],
                             b[nt >> 1][(nt & 1) * 2], b[nt >> 1][(nt & 1) * 2 + 1]);
#pragma unroll
            for (int mt = 0; mt < MT; mt++)
                ldsm4(a2[mt][0], a2[mt][1], a2[mt][2], a2[mt][3],
                      sa + TILE_B + (uint32_t)((laRow + mt * 16) * LDSK) * 2 + aoff);
#pragma unroll
            for (int mt = 0; mt < MT; mt++)
#pragma unroll
                for (int nt = 0; nt < 4; nt++)
                    mma16816(acc[mt][nt], a2[mt],
                             b[nt >> 1][(nt & 1) * 2], b[nt >> 1][(nt & 1) * 2 + 1]);
#pragma unroll
            for (int p = 0; p < 2; p++)
                ldsm4(b[p][0], b[p][1], b[p][2], b[p][3],
                      sb + TILE_B + (uint32_t)((lbRow + p * 16) * LDSK) * 2 + boff);
#pragma unroll
            for (int mt = 0; mt < MT; mt++)
#pragma unroll
                for (int nt = 0; nt < 4; nt++)
                    mma16816(acc[mt][nt], a[mt],
                             b[nt >> 1][(nt & 1) * 2], b[nt >> 1][(nt & 1) * 2 + 1]);
        }
    }

    const int er = lane >> 2;
    const int ec = (lane & 3) * 2;
#pragma unroll
    for (int mt = 0; mt < MT; mt++) {
        int m = m0 + wm * (MT * 16) + mt * 16 + er;
#pragma unroll
        for (int nt = 0; nt < 4; nt++) {
            int n = n0 + wn * 32 + nt * 8 + ec;
            float b0 = bias[n], b1 = bias[n + 1];
            float v00 = (acc[mt][nt][0] + b0) * scale;
            float v01 = (acc[mt][nt][1] + b1) * scale;
            float v10 = (acc[mt][nt][2] + b0) * scale;
            float v11 = (acc[mt][nt][3] + b1) * scale;
            if (REMAP) {
                int h = n >> 6, d = n & 63;
                int bb0 = m >> 11, s0 = m & 2047;
                int bb1 = (m + 8) >> 11, s1 = (m + 8) & 2047;
                size_t p0 = (((size_t)(bb0 * NH + h)) * SEQ + s0) * HD + d;
                size_t p1 = (((size_t)(bb1 * NH + h)) * SEQ + s1) * HD + d;
                uint32_t hp = cvt_bf2(v00, v01);
                uint32_t lp = cvt_bf2(v00 - bflo(hp), v01 - bfhi(hp));
                *(uint32_t*)&Chi[p0] = hp;
                *(uint32_t*)&Clo[p0] = lp;
                hp = cvt_bf2(v10, v11);
                lp = cvt_bf2(v10 - bflo(hp), v11 - bfhi(hp));
                *(uint32_t*)&Chi[p1] = hp;
                *(uint32_t*)&Clo[p1] = lp;
            } else {
                *(float2*)&C[(size_t)m * EMB + n] = make_float2(v00, v01);
                *(float2*)&C[(size_t)(m + 8) * EMB + n] = make_float2(v10, v11);
            }
        }
    }
}

__global__ __launch_bounds__(256, 2) void qkv_mma(
    const float* __restrict__ bq, const float* __restrict__ bk,
    const float* __restrict__ bv)
{
    int m0 = blockIdx.y * 128;
    int ng = blockIdx.x * BN;
    int sel = ng / EMB;
    int n0 = ng - sel * EMB;
    const bf16* Bhi = g_whi[sel];
    const bf16* Blo = g_wlo[sel];
    const float* bias = (sel == 0) ? bq : (sel == 1) ? bk : bv;
    bf16* Chi = (sel == 0) ? g_qhi : (sel == 1) ? g_khi : g_vhi;
    bf16* Clo = (sel == 0) ? g_qlo : (sel == 1) ? g_klo : g_vlo;
    float scale = (sel == 0) ? 0.125f * 1.4426950408889634f : 1.0f;
    mma_gemm_body<1, 4>(g_xhi, g_xlo, Bhi, Blo, bias, nullptr, Chi, Clo,
                        m0, n0, scale);
}

// out projection: BM=64 tiles -> 384 CTAs for full-chip fill
__global__ __launch_bounds__(256, 2) void out_mma(
    const float* __restrict__ bo, float* __restrict__ out)
{
    mma_gemm_body<0, 2>(g_aohi, g_aolo, g_whi[3], g_wlo[3], bo, out,
                        nullptr, nullptr, blockIdx.y * 64, blockIdx.x * BN, 1.0f);
}

// =================================================================
// Tensor-core flash attention (round-12 config, verified 106us)
// =================================================================
#define STR 72
#define KV_STAGE_B (256 * STR * 2)       // 36864
#define ATT_SMEM (3 * KV_STAGE_B)        // 110592

__device__ __forceinline__ void kv_issue(uint32_t sb, int buf, int kbase,
                                         const bf16* const kvsrc[4], int tid)
{
    uint32_t base = sb + (uint32_t)buf * KV_STAGE_B;
#pragma unroll
    for (int i = 0; i < 8; i++) {
        int c = i * 256 + tid;
        int row = (c >> 3) & 63;
        int ch = (c & 7) * 8;
        cp16(base + (uint32_t)(((i >> 1) * 64 + row) * STR + ch) * 2,
             kvsrc[i >> 1] + (size_t)(kbase + row) * HD + ch);
    }
    asm volatile("cp.async.commit_group;");
}

__global__ __launch_bounds__(256, 2) void attn_mma(
    const bf16* __restrict__ Qhi_g, const bf16* __restrict__ Qlo_g,
    const bf16* __restrict__ Khi_g, const bf16* __restrict__ Klo_g,
    const bf16* __restrict__ Vhi_g, const bf16* __restrict__ Vlo_g,
    bf16* __restrict__ AOhi, bf16* __restrict__ AOlo,
    float* __restrict__ PO, float* __restrict__ PL)
{
    extern __shared__ char dsm[];
    const uint32_t sb = (uint32_t)__cvta_generic_to_shared(dsm);

    const int bid = blockIdx.x;
    const int unit = bid / (BATCH * NH);
    const int bh = bid % (BATCH * NH);
    const int qt = UQT[unit];
    const int hf = UHF[unit];
    const int qbase = qt * 128;
    int kstart, nktl;
    if (hf == 2) { kstart = 0; nktl = 2 * qt + 2; }
    else         { nktl = qt + 1; kstart = hf * nktl; }

    const int tid = threadIdx.x;
    const int lane = tid & 31;
    const int wid = tid >> 5;
    const int wr = wid * 16;

    const size_t hoff = (size_t)bh * SEQ * HD;
    const bf16* qsrc[2] = {Qhi_g + hoff, Qlo_g + hoff};
    const bf16* kvsrc[4] = {Khi_g + hoff, Klo_g + hoff, Vhi_g + hoff, Vlo_g + hoff};

#pragma unroll
    for (int i = 0; i < 8; i++) {
        int c = i * 256 + tid;
        int row = (c >> 3) & 127;
        int ch = (c & 7) * 8;
        cp16(sb + (uint32_t)(((i >> 2) * 128 + row) * STR + ch) * 2,
             qsrc[i >> 2] + (size_t)(qbase + row) * HD + ch);
    }
    asm volatile("cp.async.commit_group;");
    cp_wait<0>();
    __syncthreads();

    uint32_t qh[4][4], ql[4][4];
    {
        int arow = wr + (lane & 15);
        int acol = (lane >> 4) * 8;
#pragma unroll
        for (int ks = 0; ks < 4; ks++) {
            ldsm4(qh[ks][0], qh[ks][1], qh[ks][2], qh[ks][3],
                  sb + (uint32_t)(arow * STR + ks * 16 + acol) * 2);
            ldsm4(ql[ks][0], ql[ks][1], ql[ks][2], ql[ks][3],
                  sb + (uint32_t)((128 + arow) * STR + ks * 16 + acol) * 2);
        }
    }
    __syncthreads();

    float o[8][4];
#pragma unroll
    for (int i = 0; i < 8; i++)
#pragma unroll
        for (int j = 0; j < 4; j++) o[i][j] = 0.f;
    float rs0 = 0.f, rs1 = 0.f;

    kv_issue(sb, 0, kstart * 64, kvsrc, tid);
    kv_issue(sb, 1, (kstart + 1) * 64, kvsrc, tid);

    const int brow = (lane & 7) + ((lane >> 4) << 3);
    const int bcol = ((lane >> 3) & 1) * 8;
    const int vrow = (lane & 7) + (((lane >> 3) & 1) << 3);
    const int vcol = (lane >> 4) * 8;

    int st = 0;
    for (int kt = 0; kt < nktl; kt++) {
        if (kt + 1 < nktl) cp_wait<1>(); else cp_wait<0>();
        __syncthreads();
        if (kt + 2 < nktl) {
            int b2 = st + 2; if (b2 >= 3) b2 -= 3;
            kv_issue(sb, b2, (kstart + kt + 2) * 64, kvsrc, tid);
        }

        const uint32_t kvb = sb + (uint32_t)st * KV_STAGE_B;
        const uint32_t Khi_s = kvb;
        const uint32_t Klo_s = kvb + 64 * STR * 2;
        const uint32_t Vhi_s = kvb + 128 * STR * 2;
        const uint32_t Vlo_s = kvb + 192 * STR * 2;
        const int kbase = (kstart + kt) * 64;

        float s[8][4];
#pragma unroll
        for (int i = 0; i < 8; i++)
#pragma unroll
            for (int j = 0; j < 4; j++) s[i][j] = 0.f;

#pragma unroll
        for (int ks = 0; ks < 4; ks++) {
            uint32_t bb[4][4];
#pragma unroll
            for (int ng = 0; ng < 4; ng++)
                ldsm4(bb[ng][0], bb[ng][1], bb[ng][2], bb[ng][3],
                      Khi_s + (uint32_t)((16 * ng + brow) * STR + 16 * ks + bcol) * 2);
#pragma unroll
            for (int ng = 0; ng < 4; ng++) {
                mma16816(s[2 * ng], qh[ks], bb[ng][0], bb[ng][1]);
                mma16816(s[2 * ng + 1], qh[ks], bb[ng][2], bb[ng][3]);
                mma16816(s[2 * ng], ql[ks], bb[ng][0], bb[ng][1]);
                mma16816(s[2 * ng + 1], ql[ks], bb[ng][2], bb[ng][3]);
            }
#pragma unroll
            for (int ng = 0; ng < 4; ng++)
                ldsm4(bb[ng][0], bb[ng][1], bb[ng][2], bb[ng][3],
                      Klo_s + (uint32_t)((16 * ng + brow) * STR + 16 * ks + bcol) * 2);
#pragma unroll
            for (int ng = 0; ng < 4; ng++) {
                mma16816(s[2 * ng], qh[ks], bb[ng][0], bb[ng][1]);
                mma16816(s[2 * ng + 1], qh[ks], bb[ng][2], bb[ng][3]);
            }
        }

        const bool diag = (kbase + 63 > qbase + wr);
        const int row0q = qbase + wr + (lane >> 2);
        const int colbq = kbase + 2 * (lane & 3);

#pragma unroll
        for (int t = 0; t < 4; t++) {
            if (diag) {
#pragma unroll
                for (int h2 = 0; h2 < 2; h2++) {
                    int nt = 2 * t + h2;
                    int c0 = colbq + nt * 8;
                    if (c0 > row0q) s[nt][0] = -1e30f;
                    if (c0 + 1 > row0q) s[nt][1] = -1e30f;
                    if (c0 > row0q + 8) s[nt][2] = -1e30f;
                    if (c0 + 1 > row0q + 8) s[nt][3] = -1e30f;
                }
            }
            uint32_t phi[4], plo[4];
#pragma unroll
            for (int h2 = 0; h2 < 2; h2++) {
                float* sp = s[2 * t + h2];
                sp[0] = ex2f(sp[0]); rs0 += sp[0];
                sp[1] = ex2f(sp[1]); rs0 += sp[1];
                sp[2] = ex2f(sp[2]); rs1 += sp[2];
                sp[3] = ex2f(sp[3]); rs1 += sp[3];
                uint32_t h0 = cvt_bf2(sp[0], sp[1]);
                phi[h2 * 2] = h0;
                plo[h2 * 2] = cvt_bf2(sp[0] - bflo(h0), sp[1] - bfhi(h0));
                uint32_t h1 = cvt_bf2(sp[2], sp[3]);
                phi[h2 * 2 + 1] = h1;
                plo[h2 * 2 + 1] = cvt_bf2(sp[2] - bflo(h1), sp[3] - bfhi(h1));
            }
            uint32_t vb[4][4];
#pragma unroll
            for (int g = 0; g < 4; g++)
                ldsm4t(vb[g][0], vb[g][1], vb[g][2], vb[g][3],
                       Vhi_s + (uint32_t)((16 * t + vrow) * STR + 16 * g + vcol) * 2);
#pragma unroll
            for (int g = 0; g < 4; g++) {
                mma16816(o[2 * g], phi, vb[g][0], vb[g][1]);
                mma16816(o[2 * g + 1], phi, vb[g][2], vb[g][3]);
                mma16816(o[2 * g], plo, vb[g][0], vb[g][1]);
                mma16816(o[2 * g + 1], plo, vb[g][2], vb[g][3]);
            }
#pragma unroll
            for (int g = 0; g < 4; g++)
                ldsm4t(vb[g][0], vb[g][1], vb[g][2], vb[g][3],
                       Vlo_s + (uint32_t)((16 * t + vrow) * STR + 16 * g + vcol) * 2);
#pragma unroll
            for (int g = 0; g < 4; g++) {
                mma16816(o[2 * g], phi, vb[g][0], vb[g][1]);
                mma16816(o[2 * g + 1], phi, vb[g][2], vb[g][3]);
            }
        }

        st = (st + 1 == 3) ? 0 : st + 1;
    }

    rs0 += __shfl_xor_sync(0xffffffffu, rs0, 1);
    rs0 += __shfl_xor_sync(0xffffffffu, rs0, 2);
    rs1 += __shfl_xor_sync(0xffffffffu, rs1, 1);
    rs1 += __shfl_xor_sync(0xffffffffu, rs1, 2);

    if (hf != 2) {
        int sidx = (bh * 8 + (qt - 8)) * 2 + hf;
        float* po = PO + (size_t)sidx * (128 * 64);
        float* pl = PL + (size_t)sidx * 128;
        int rl = wr + (lane >> 2);
        int cb = 2 * (lane & 3);
#pragma unroll
        for (int nd = 0; nd < 8; nd++) {
            *(float2*)&po[rl * 64 + cb + nd * 8] = make_float2(o[nd][0], o[nd][1]);
            *(float2*)&po[(rl + 8) * 64 + cb + nd * 8] = make_float2(o[nd][2], o[nd][3]);
        }
        if ((lane & 3) == 0) { pl[rl] = rs0; pl[rl + 8] = rs1; }
        return;
    }

    float inv0 = 1.f / rs0, inv1 = 1.f / rs1;
    int b = bh / NH, h = bh % NH;
    int row0 = qbase + wr + (lane >> 2);
    size_t off0 = ((size_t)b * SEQ + row0) * EMB + h * HD + 2 * (lane & 3);
    size_t off1 = off0 + 8 * (size_t)EMB;
#pragma unroll
    for (int nd = 0; nd < 8; nd++) {
        float f0 = o[nd][0] * inv0, f1 = o[nd][1] * inv0;
        uint32_t hp = cvt_bf2(f0, f1);
        uint32_t lp = cvt_bf2(f0 - bflo(hp), f1 - bfhi(hp));
        *(uint32_t*)&AOhi[off0 + nd * 8] = hp;
        *(uint32_t*)&AOlo[off0 + nd * 8] = lp;
        float g0 = o[nd][2] * inv1, g1 = o[nd][3] * inv1;
        uint32_t hq = cvt_bf2(g0, g1);
        uint32_t lq = cvt_bf2(g0 - bflo(hq), g1 - bfhi(hq));
        *(uint32_t*)&AOhi[off1 + nd * 8] = hq;
        *(uint32_t*)&AOlo[off1 + nd * 8] = lq;
    }
}

// =================================================================
// combine split-KV partials
// =================================================================
__global__ __launch_bounds__(256) void attn_combine(
    const float* __restrict__ PO, const float* __restrict__ PL,
    bf16* __restrict__ AOhi, bf16* __restrict__ AOlo)
{
    int blk = blockIdx.x;
    int bh = blk >> 3;
    int qidx = blk & 7;
    int qt = qidx + 8;
    int qbase = qt * 128;
    int b = bh / NH, h = bh % NH;

    size_t s0 = ((size_t)(bh * 8 + qidx) * 2) * (128 * 64);
    const float* po0 = PO + s0;
    const float* po1 = po0 + 128 * 64;
    const float* pl0 = PL + ((size_t)(bh * 8 + qidx) * 2) * 128;
    const float* pl1 = pl0 + 128;

    int t = threadIdx.x;
    int r = t >> 1;
    int c0 = (t & 1) * 32;
    float inv = 1.f / (pl0[r] + pl1[r]);
    size_t go = ((size_t)b * SEQ + qbase + r) * EMB + h * HD + c0;
    int ro = r * 64 + c0;
#pragma unroll
    for (int c = 0; c < 32; c += 4) {
        float4 x0 = *(const float4*)&po0[ro + c];
        float4 x1 = *(const float4*)&po1[ro + c];
        float f0 = (x0.x + x1.x) * inv;
        float f1 = (x0.y + x1.y) * inv;
        float f2 = (x0.z + x1.z) * inv;
        float f3 = (x0.w + x1.w) * inv;
        uint32_t h0 = cvt_bf2(f0, f1), h1 = cvt_bf2(f2, f3);
        uint32_t l0 = cvt_bf2(f0 - bflo(h0), f1 - bfhi(h0));
        uint32_t l1 = cvt_bf2(f2 - bflo(h1), f3 - bfhi(h1));
        *(uint2*)&AOhi[go + c] = make_uint2(h0, h1);
        *(uint2*)&AOlo[go + c] = make_uint2(l0, l1);
    }
}

// =================================================================
// launch
// =================================================================
extern "C" void kernel_launch(void* const* d_in, const int* in_sizes, int n_in,
                              void* d_out, int out_size)
{
    const float* x    = (const float*)d_in[0];
    const float* wq_b = (const float*)d_in[2];
    const float* wk_b = (const float*)d_in[4];
    const float* wv_b = (const float*)d_in[6];
    const float* wo_b = (const float*)d_in[8];
    float* out = (float*)d_out;

    bf16 *xhi, *xlo;
    bf16 *qhi, *qlo, *khi, *klo, *vhi, *vlo, *aohi, *aolo;
    float *po, *pl;
    cudaGetSymbolAddress((void**)&xhi, g_xhi);
    cudaGetSymbolAddress((void**)&xlo, g_xlo);
    cudaGetSymbolAddress((void**)&qhi, g_qhi);
    cudaGetSymbolAddress((void**)&qlo, g_qlo);
    cudaGetSymbolAddress((void**)&khi, g_khi);
    cudaGetSymbolAddress((void**)&klo, g_klo);
    cudaGetSymbolAddress((void**)&vhi, g_vhi);
    cudaGetSymbolAddress((void**)&vlo, g_vlo);
    cudaGetSymbolAddress((void**)&aohi, g_aohi);
    cudaGetSymbolAddress((void**)&aolo, g_aolo);
    cudaGetSymbolAddress((void**)&po, g_po);
    cudaGetSymbolAddress((void**)&pl, g_pl);

    cudaFuncSetAttribute(attn_mma,
                         cudaFuncAttributeMaxDynamicSharedMemorySize, ATT_SMEM);
    cudaFuncSetAttribute(qkv_mma,
                         cudaFuncAttributeMaxDynamicSharedMemorySize, GEMM_SMEM);
    cudaFuncSetAttribute(out_mma,
                         cudaFuncAttributeMaxDynamicSharedMemorySize, GEMM_SMEM);

    // one fused split launch: z=0..3 weights, z=4 x (x needs 3072 x-blocks)
    dim3 gs((MROWS * EMB / 4 + 255) / 256, 1, 5);
    split_all_kernel<<<gs, 256>>>(x, (const float*)d_in[1], (const float*)d_in[3],
                                  (const float*)d_in[5], (const float*)d_in[7],
                                  xhi, xlo);

    dim3 gqkv(NQKV / BN, MROWS / 128);             // 18 x 32 = 576
    qkv_mma<<<gqkv, 256, GEMM_SMEM>>>(wq_b, wk_b, wv_b);

    attn_mma<<<24 * BATCH * NH, 256, ATT_SMEM>>>(
        qhi, qlo, khi, klo, vhi, vlo, aohi, aolo, po, pl);
    attn_combine<<<192, 256>>>(po, pl, aohi, aolo);

    dim3 go(EMB / BN, MROWS / 64);                 // 6 x 64 = 384 CTAs
    out_mma<<<go, 256, GEMM_SMEM>>>(wo_b, out);
}

// round 14
// speedup vs baseline: 1.8195x; 1.0243x over previous
#include <cuda_runtime.h>
#include <cuda_bf16.h>
#include <cstdint>

#define SEQ   2048
#define EMB   768
#define NH    12
#define HD    64
#define BATCH 2
#define MROWS (BATCH * SEQ)   // 4096
#define NQKV  (3 * EMB)       // 2304

typedef __nv_bfloat16 bf16;

// ---------------- scratch (static device arrays; no allocation) -------------
__device__ bf16 g_xhi[MROWS * EMB], g_xlo[MROWS * EMB];
__device__ bf16 g_whi[4][EMB * EMB], g_wlo[4][EMB * EMB];   // q,k,v,o
__device__ bf16 g_qhi[BATCH * NH * SEQ * HD], g_qlo[BATCH * NH * SEQ * HD];
__device__ bf16 g_khi[BATCH * NH * SEQ * HD], g_klo[BATCH * NH * SEQ * HD];
__device__ bf16 g_vhi[BATCH * NH * SEQ * HD], g_vlo[BATCH * NH * SEQ * HD];
__device__ bf16 g_aohi[MROWS * EMB], g_aolo[MROWS * EMB];
// split-KV partials: 24 bh x 8 split q-tiles x 2 halves
__device__ float g_po[24 * 8 * 2 * 128 * 64];
__device__ float g_pl[24 * 8 * 2 * 128];
__device__ int   g_cnt[24 * 8];   // zero-init tickets; reset to 0 each replay

// heavy-first unit schedule: 16 split halves (qt 8..15) + 8 unsplit (qt 0..7)
__constant__ int8_t UQT[24] = {15,15,7,14,14,13,13,6,12,12,11,11,5,10,10,9,9,4,8,8,3,2,1,0};
__constant__ int8_t UHF[24] = {0,1,2,0,1,0,1,2,0,1,0,1,2,0,1,0,1,2,0,1,2,2,2,2};

// ---------------- small helpers ----------------
__device__ __forceinline__ uint32_t cvt_bf2(float lo, float hi) {
    uint32_t r;
    asm("cvt.rn.bf16x2.f32 %0, %1, %2;" : "=r"(r) : "f"(hi), "f"(lo));
    return r;
}
__device__ __forceinline__ float bflo(uint32_t p) { return __uint_as_float(p << 16); }
__device__ __forceinline__ float bfhi(uint32_t p) { return __uint_as_float(p & 0xffff0000u); }
__device__ __forceinline__ float ex2f(float x) {
    float y;
    asm("ex2.approx.ftz.f32 %0, %1;" : "=f"(y) : "f"(x));
    return y;
}
__device__ __forceinline__ void ldsm4(uint32_t& r0, uint32_t& r1,
                                      uint32_t& r2, uint32_t& r3, uint32_t addr)
{
    asm volatile("ldmatrix.sync.aligned.m8n8.x4.shared.b16 {%0,%1,%2,%3}, [%4];"
                 : "=r"(r0), "=r"(r1), "=r"(r2), "=r"(r3) : "r"(addr));
}
__device__ __forceinline__ void ldsm4t(uint32_t& r0, uint32_t& r1,
                                       uint32_t& r2, uint32_t& r3, uint32_t addr)
{
    asm volatile("ldmatrix.sync.aligned.m8n8.x4.trans.shared.b16 {%0,%1,%2,%3}, [%4];"
                 : "=r"(r0), "=r"(r1), "=r"(r2), "=r"(r3) : "r"(addr));
}
__device__ __forceinline__ void mma16816(float c[4], const uint32_t a[4],
                                         uint32_t b0, uint32_t b1)
{
    asm volatile(
        "mma.sync.aligned.m16n8k16.row.col.f32.bf16.bf16.f32 "
        "{%0,%1,%2,%3}, {%4,%5,%6,%7}, {%8,%9}, {%0,%1,%2,%3};"
        : "+f"(c[0]), "+f"(c[1]), "+f"(c[2]), "+f"(c[3])
        : "r"(a[0]), "r"(a[1]), "r"(a[2]), "r"(a[3]), "r"(b0), "r"(b1));
}
__device__ __forceinline__ void cp16(uint32_t saddr, const void* gaddr)
{
    asm volatile("cp.async.cg.shared.global [%0], [%1], 16;"
                 :: "r"(saddr), "l"(gaddr));
}
template<int N>
__device__ __forceinline__ void cp_wait()
{
    asm volatile("cp.async.wait_group %0;" :: "n"(N));
}

// =================================================================
// fp32 -> bf16 hi/lo split: one flat 1D launch (no idle planes)
// blocks [0, 4*WB): weights; blocks [4*WB, 4*WB+XB): x
// =================================================================
#define WB ((EMB * EMB / 4 + 255) / 256)      // 576
#define XB ((MROWS * EMB / 4 + 255) / 256)    // 3072

__global__ __launch_bounds__(256) void split_all_kernel(
    const float* __restrict__ x,
    const float* __restrict__ wq, const float* __restrict__ wk,
    const float* __restrict__ wv, const float* __restrict__ wo,
    bf16* __restrict__ xhi, bf16* __restrict__ xlo)
{
    int bid = blockIdx.x;
    const float4* src;
    uint2 *hi, *lo;
    int i, n4;
    if (bid < 4 * WB) {
        int z = bid / WB;
        src = (const float4*)((z == 0) ? wq : (z == 1) ? wk :
                              (z == 2) ? wv : wo);
        hi = (uint2*)g_whi[z]; lo = (uint2*)g_wlo[z];
        i = (bid - z * WB) * 256 + threadIdx.x;
        n4 = EMB * EMB / 4;
    } else {
        src = (const float4*)x;
        hi = (uint2*)xhi; lo = (uint2*)xlo;
        i = (bid - 4 * WB) * 256 + threadIdx.x;
        n4 = MROWS * EMB / 4;
    }
    if (i < n4) {
        float4 v = src[i];
        uint32_t h0 = cvt_bf2(v.x, v.y);
        uint32_t h1 = cvt_bf2(v.z, v.w);
        uint32_t l0 = cvt_bf2(v.x - bflo(h0), v.y - bfhi(h0));
        uint32_t l1 = cvt_bf2(v.z - bflo(h1), v.w - bfhi(h1));
        hi[i] = make_uint2(h0, h1);
        lo[i] = make_uint2(l0, l1);
    }
}

// =================================================================
// FUSED bf16-split MMA GEMM. Single-sync 2-stage ring.
// Template MT = M-tiles per warp (4 -> BM=128, 2 -> BM=64).
// =================================================================
#define BN 128
#define BK 32
#define LDSK 40
#define NKB (EMB / BK)                 // 24 iterations
#define TILE_B (128 * LDSK * 2)        // 10240 bytes
#define GSTAGE_B (2 * TILE_B)          // 20480
#define GEMM_SMEM (4 * GSTAGE_B)       // 81920

template<int MT>
__device__ __forceinline__ void gemm_issue(
    int kb, int buf,
    const bf16* __restrict__ Ahi, const bf16* __restrict__ Alo,
    const bf16* __restrict__ Bhi, const bf16* __restrict__ Blo,
    uint32_t asb, uint32_t bsb, int m0, int n0, int srow, int schk)
{
    int k0 = kb * BK;
    uint32_t sa = asb + (uint32_t)buf * GSTAGE_B;
    uint32_t sb = bsb + (uint32_t)buf * GSTAGE_B;
    uint32_t o0 = (srow * LDSK + schk) * 2;
    uint32_t o1 = ((srow + 64) * LDSK + schk) * 2;
    size_t g0 = (size_t)(m0 + srow) * EMB + k0 + schk;
    size_t h0 = (size_t)(n0 + srow) * EMB + k0 + schk;
    size_t h1 = (size_t)(n0 + srow + 64) * EMB + k0 + schk;
    cp16(sa + o0, Ahi + g0);
    cp16(sa + TILE_B + o0, Alo + g0);
    if (MT == 4) {
        size_t g1 = (size_t)(m0 + srow + 64) * EMB + k0 + schk;
        cp16(sa + o1, Ahi + g1);
        cp16(sa + TILE_B + o1, Alo + g1);
    }
    cp16(sb + o0, Bhi + h0);
    cp16(sb + o1, Bhi + h1);
    cp16(sb + TILE_B + o0, Blo + h0);
    cp16(sb + TILE_B + o1, Blo + h1);
    asm volatile("cp.async.commit_group;");
}

template<int REMAP, int MT>
__device__ __forceinline__ void mma_gemm_body(
    const bf16* __restrict__ Ahi, const bf16* __restrict__ Alo,
    const bf16* __restrict__ Bhi, const bf16* __restrict__ Blo,
    const float* __restrict__ bias, float* __restrict__ C,
    bf16* __restrict__ Chi, bf16* __restrict__ Clo,
    int m0, int n0, float scale)
{
    extern __shared__ char dsm[];
    const uint32_t asb = (uint32_t)__cvta_generic_to_shared(dsm);
    const uint32_t bsb = asb + 2 * GSTAGE_B;

    const int tid = threadIdx.x;
    const int lane = tid & 31;
    const int wid = tid >> 5;
    const int wm = wid >> 2;
    const int wn = wid & 3;

    float acc[MT][4][4];
#pragma unroll
    for (int i = 0; i < MT; i++)
#pragma unroll
        for (int j = 0; j < 4; j++)
#pragma unroll
            for (int t = 0; t < 4; t++) acc[i][j][t] = 0.f;

    const int srow = tid >> 2;
    const int schk = (tid & 3) * 8;

    const int laRow = wm * (MT * 16) + (lane & 15);
    const int laCol = (lane >> 4) * 8;
    const int lbRow = wn * 32 + ((lane >> 4) << 3) + (lane & 7);
    const int lbCol = ((lane >> 3) & 1) * 8;

    gemm_issue<MT>(0, 0, Ahi, Alo, Bhi, Blo, asb, bsb, m0, n0, srow, schk);

    for (int it = 0; it < NKB; it++) {
        const int buf = it & 1;
        cp_wait<0>();
        __syncthreads();
        if (it + 1 < NKB)
            gemm_issue<MT>(it + 1, buf ^ 1, Ahi, Alo, Bhi, Blo, asb, bsb,
                           m0, n0, srow, schk);

        const uint32_t sa = asb + (uint32_t)buf * GSTAGE_B;
        const uint32_t sb = bsb + (uint32_t)buf * GSTAGE_B;

#pragma unroll
        for (int ks = 0; ks < 2; ks++) {
            const uint32_t aoff = (uint32_t)(ks * 16 + laCol) * 2;
            const uint32_t boff = (uint32_t)(ks * 16 + lbCol) * 2;
            uint32_t a[MT][4], a2[MT][4], b[2][4];
#pragma unroll
            for (int mt = 0; mt < MT; mt++)
                ldsm4(a[mt][0], a[mt][1], a[mt][2], a[mt][3],
                      sa + (uint32_t)((laRow + mt * 16) * LDSK) * 2 + aoff);
#pragma unroll
            for (int p = 0; p < 2; p++)
                ldsm4(b[p][0], b[p][1], b[p][2], b[p][3],
                      sb + (uint32_t)((lbRow + p * 16) * LDSK) * 2 + boff);
#pragma unroll
            for (int mt = 0; mt < MT; mt++)
#pragma unroll
                for (int nt = 0; nt < 4; nt++)
                    mma16816(acc[mt][nt], a[mt],
                             b[nt >> 1][(nt & 1) * 2], b[nt >> 1][(nt & 1) * 2 + 1]);
#pragma unroll
            for (int mt = 0; mt < MT; mt++)
                ldsm4(a2[mt][0], a2[mt][1], a2[mt][2], a2[mt][3],
                      sa + TILE_B + (uint32_t)((laRow + mt * 16) * LDSK) * 2 + aoff);
#pragma unroll
            for (int mt = 0; mt < MT; mt++)
#pragma unroll
                for (int nt = 0; nt < 4; nt++)
                    mma16816(acc[mt][nt], a2[mt],
                             b[nt >> 1][(nt & 1) * 2], b[nt >> 1][(nt & 1) * 2 + 1]);
#pragma unroll
            for (int p = 0; p < 2; p++)
                ldsm4(b[p][0], b[p][1], b[p][2], b[p][3],
                      sb + TILE_B + (uint32_t)((lbRow + p * 16) * LDSK) * 2 + boff);
#pragma unroll
            for (int mt = 0; mt < MT; mt++)
#pragma unroll
                for (int nt = 0; nt < 4; nt++)
                    mma16816(acc[mt][nt], a[mt],
                             b[nt >> 1][(nt & 1) * 2], b[nt >> 1][(nt & 1) * 2 + 1]);
        }
    }

    const int er = lane >> 2;
    const int ec = (lane & 3) * 2;
#pragma unroll
    for (int mt = 0; mt < MT; mt++) {
        int m = m0 + wm * (MT * 16) + mt * 16 + er;
#pragma unroll
        for (int nt = 0; nt < 4; nt++) {
            int n = n0 + wn * 32 + nt * 8 + ec;
            float b0 = bias[n], b1 = bias[n + 1];
            float v00 = (acc[mt][nt][0] + b0) * scale;
            float v01 = (acc[mt][nt][1] + b1) * scale;
            float v10 = (acc[mt][nt][2] + b0) * scale;
            float v11 = (acc[mt][nt][3] + b1) * scale;
            if (REMAP) {
                int h = n >> 6, d = n & 63;
                int bb0 = m >> 11, s0 = m & 2047;
                int bb1 = (m + 8) >> 11, s1 = (m + 8) & 2047;
                size_t p0 = (((size_t)(bb0 * NH + h)) * SEQ + s0) * HD + d;
                size_t p1 = (((size_t)(bb1 * NH + h)) * SEQ + s1) * HD + d;
                uint32_t hp = cvt_bf2(v00, v01);
                uint32_t lp = cvt_bf2(v00 - bflo(hp), v01 - bfhi(hp));
                *(uint32_t*)&Chi[p0] = hp;
                *(uint32_t*)&Clo[p0] = lp;
                hp = cvt_bf2(v10, v11);
                lp = cvt_bf2(v10 - bflo(hp), v11 - bfhi(hp));
                *(uint32_t*)&Chi[p1] = hp;
                *(uint32_t*)&Clo[p1] = lp;
            } else {
                *(float2*)&C[(size_t)m * EMB + n] = make_float2(v00, v01);
                *(float2*)&C[(size_t)(m + 8) * EMB + n] = make_float2(v10, v11);
            }
        }
    }
}

__global__ __launch_bounds__(256, 2) void qkv_mma(
    const float* __restrict__ bq, const float* __restrict__ bk,
    const float* __restrict__ bv)
{
    int m0 = blockIdx.y * 128;
    int ng = blockIdx.x * BN;
    int sel = ng / EMB;
    int n0 = ng - sel * EMB;
    const bf16* Bhi = g_whi[sel];
    const bf16* Blo = g_wlo[sel];
    const float* bias = (sel == 0) ? bq : (sel == 1) ? bk : bv;
    bf16* Chi = (sel == 0) ? g_qhi : (sel == 1) ? g_khi : g_vhi;
    bf16* Clo = (sel == 0) ? g_qlo : (sel == 1) ? g_klo : g_vlo;
    float scale = (sel == 0) ? 0.125f * 1.4426950408889634f : 1.0f;
    mma_gemm_body<1, 4>(g_xhi, g_xlo, Bhi, Blo, bias, nullptr, Chi, Clo,
                        m0, n0, scale);
}

__global__ __launch_bounds__(256, 2) void out_mma(
    const float* __restrict__ bo, float* __restrict__ out)
{
    mma_gemm_body<0, 2>(g_aohi, g_aolo, g_whi[3], g_wlo[3], bo, out,
                        nullptr, nullptr, blockIdx.y * 64, blockIdx.x * BN, 1.0f);
}

// =================================================================
// Tensor-core flash attention + split-KV with IN-KERNEL combine:
// second-finishing half of each split pair (threadfence+ticket)
// reads the peer's partial, adds (commutative -> deterministic),
// normalizes, writes ao. No separate combine launch.
// =================================================================
#define STR 72
#define KV_STAGE_B (256 * STR * 2)       // 36864
#define ATT_SMEM (3 * KV_STAGE_B)        // 110592

__device__ __forceinline__ void kv_issue(uint32_t sb, int buf, int kbase,
                                         const bf16* const kvsrc[4], int tid)
{
    uint32_t base = sb + (uint32_t)buf * KV_STAGE_B;
#pragma unroll
    for (int i = 0; i < 8; i++) {
        int c = i * 256 + tid;
        int row = (c >> 3) & 63;
        int ch = (c & 7) * 8;
        cp16(base + (uint32_t)(((i >> 1) * 64 + row) * STR + ch) * 2,
             kvsrc[i >> 1] + (size_t)(kbase + row) * HD + ch);
    }
    asm volatile("cp.async.commit_group;");
}

__global__ __launch_bounds__(256, 2) void attn_mma(
    const bf16* __restrict__ Qhi_g, const bf16* __restrict__ Qlo_g,
    const bf16* __restrict__ Khi_g, const bf16* __restrict__ Klo_g,
    const bf16* __restrict__ Vhi_g, const bf16* __restrict__ Vlo_g,
    bf16* __restrict__ AOhi, bf16* __restrict__ AOlo,
    float* __restrict__ PO, float* __restrict__ PL)
{
    extern __shared__ char dsm[];
    __shared__ int sflag;
    const uint32_t sb = (uint32_t)__cvta_generic_to_shared(dsm);

    const int bid = blockIdx.x;
    const int unit = bid / (BATCH * NH);
    const int bh = bid % (BATCH * NH);
    const int qt = UQT[unit];
    const int hf = UHF[unit];
    const int qbase = qt * 128;
    int kstart, nktl;
    if (hf == 2) { kstart = 0; nktl = 2 * qt + 2; }
    else         { nktl = qt + 1; kstart = hf * nktl; }

    const int tid = threadIdx.x;
    const int lane = tid & 31;
    const int wid = tid >> 5;
    const int wr = wid * 16;

    const size_t hoff = (size_t)bh * SEQ * HD;
    const bf16* qsrc[2] = {Qhi_g + hoff, Qlo_g + hoff};
    const bf16* kvsrc[4] = {Khi_g + hoff, Klo_g + hoff, Vhi_g + hoff, Vlo_g + hoff};

#pragma unroll
    for (int i = 0; i < 8; i++) {
        int c = i * 256 + tid;
        int row = (c >> 3) & 127;
        int ch = (c & 7) * 8;
        cp16(sb + (uint32_t)(((i >> 2) * 128 + row) * STR + ch) * 2,
             qsrc[i >> 2] + (size_t)(qbase + row) * HD + ch);
    }
    asm volatile("cp.async.commit_group;");
    cp_wait<0>();
    __syncthreads();

    uint32_t qh[4][4], ql[4][4];
    {
        int arow = wr + (lane & 15);
        int acol = (lane >> 4) * 8;
#pragma unroll
        for (int ks = 0; ks < 4; ks++) {
            ldsm4(qh[ks][0], qh[ks][1], qh[ks][2], qh[ks][3],
                  sb + (uint32_t)(arow * STR + ks * 16 + acol) * 2);
            ldsm4(ql[ks][0], ql[ks][1], ql[ks][2], ql[ks][3],
                  sb + (uint32_t)((128 + arow) * STR + ks * 16 + acol) * 2);
        }
    }
    __syncthreads();

    float o[8][4];
#pragma unroll
    for (int i = 0; i < 8; i++)
#pragma unroll
        for (int j = 0; j < 4; j++) o[i][j] = 0.f;
    float rs0 = 0.f, rs1 = 0.f;

    kv_issue(sb, 0, kstart * 64, kvsrc, tid);
    kv_issue(sb, 1, (kstart + 1) * 64, kvsrc, tid);

    const int brow = (lane & 7) + ((lane >> 4) << 3);
    const int bcol = ((lane >> 3) & 1) * 8;
    const int vrow = (lane & 7) + (((lane >> 3) & 1) << 3);
    const int vcol = (lane >> 4) * 8;

    int st = 0;
    for (int kt = 0; kt < nktl; kt++) {
        if (kt + 1 < nktl) cp_wait<1>(); else cp_wait<0>();
        __syncthreads();
        if (kt + 2 < nktl) {
            int b2 = st + 2; if (b2 >= 3) b2 -= 3;
            kv_issue(sb, b2, (kstart + kt + 2) * 64, kvsrc, tid);
        }

        const uint32_t kvb = sb + (uint32_t)st * KV_STAGE_B;
        const uint32_t Khi_s = kvb;
        const uint32_t Klo_s = kvb + 64 * STR * 2;
        const uint32_t Vhi_s = kvb + 128 * STR * 2;
        const uint32_t Vlo_s = kvb + 192 * STR * 2;
        const int kbase = (kstart + kt) * 64;

        float s[8][4];
#pragma unroll
        for (int i = 0; i < 8; i++)
#pragma unroll
            for (int j = 0; j < 4; j++) s[i][j] = 0.f;

#pragma unroll
        for (int ks = 0; ks < 4; ks++) {
            uint32_t bb[4][4];
#pragma unroll
            for (int ng = 0; ng < 4; ng++)
                ldsm4(bb[ng][0], bb[ng][1], bb[ng][2], bb[ng][3],
                      Khi_s + (uint32_t)((16 * ng + brow) * STR + 16 * ks + bcol) * 2);
#pragma unroll
            for (int ng = 0; ng < 4; ng++) {
                mma16816(s[2 * ng], qh[ks], bb[ng][0], bb[ng][1]);
                mma16816(s[2 * ng + 1], qh[ks], bb[ng][2], bb[ng][3]);
                mma16816(s[2 * ng], ql[ks], bb[ng][0], bb[ng][1]);
                mma16816(s[2 * ng + 1], ql[ks], bb[ng][2], bb[ng][3]);
            }
#pragma unroll
            for (int ng = 0; ng < 4; ng++)
                ldsm4(bb[ng][0], bb[ng][1], bb[ng][2], bb[ng][3],
                      Klo_s + (uint32_t)((16 * ng + brow) * STR + 16 * ks + bcol) * 2);
#pragma unroll
            for (int ng = 0; ng < 4; ng++) {
                mma16816(s[2 * ng], qh[ks], bb[ng][0], bb[ng][1]);
                mma16816(s[2 * ng + 1], qh[ks], bb[ng][2], bb[ng][3]);
            }
        }

        const bool diag = (kbase + 63 > qbase + wr);
        const int row0q = qbase + wr + (lane >> 2);
        const int colbq = kbase + 2 * (lane & 3);

#pragma unroll
        for (int t = 0; t < 4; t++) {
            if (diag) {
#pragma unroll
                for (int h2 = 0; h2 < 2; h2++) {
                    int nt = 2 * t + h2;
                    int c0 = colbq + nt * 8;
                    if (c0 > row0q) s[nt][0] = -1e30f;
                    if (c0 + 1 > row0q) s[nt][1] = -1e30f;
                    if (c0 > row0q + 8) s[nt][2] = -1e30f;
                    if (c0 + 1 > row0q + 8) s[nt][3] = -1e30f;
                }
            }
            uint32_t phi[4], plo[4];
#pragma unroll
            for (int h2 = 0; h2 < 2; h2++) {
                float* sp = s[2 * t + h2];
                sp[0] = ex2f(sp[0]); rs0 += sp[0];
                sp[1] = ex2f(sp[1]); rs0 += sp[1];
                sp[2] = ex2f(sp[2]); rs1 += sp[2];
                sp[3] = ex2f(sp[3]); rs1 += sp[3];
                uint32_t h0 = cvt_bf2(sp[0], sp[1]);
                phi[h2 * 2] = h0;
                plo[h2 * 2] = cvt_bf2(sp[0] - bflo(h0), sp[1] - bfhi(h0));
                uint32_t h1 = cvt_bf2(sp[2], sp[3]);
                phi[h2 * 2 + 1] = h1;
                plo[h2 * 2 + 1] = cvt_bf2(sp[2] - bflo(h1), sp[3] - bfhi(h1));
            }
            uint32_t vb[4][4];
#pragma unroll
            for (int g = 0; g < 4; g++)
                ldsm4t(vb[g][0], vb[g][1], vb[g][2], vb[g][3],
                       Vhi_s + (uint32_t)((16 * t + vrow) * STR + 16 * g + vcol) * 2);
#pragma unroll
            for (int g = 0; g < 4; g++) {
                mma16816(o[2 * g], phi, vb[g][0], vb[g][1]);
                mma16816(o[2 * g + 1], phi, vb[g][2], vb[g][3]);
                mma16816(o[2 * g], plo, vb[g][0], vb[g][1]);
                mma16816(o[2 * g + 1], plo, vb[g][2], vb[g][3]);
            }
#pragma unroll
            for (int g = 0; g < 4; g++)
                ldsm4t(vb[g][0], vb[g][1], vb[g][2], vb[g][3],
                       Vlo_s + (uint32_t)((16 * t + vrow) * STR + 16 * g + vcol) * 2);
#pragma unroll
            for (int g = 0; g < 4; g++) {
                mma16816(o[2 * g], phi, vb[g][0], vb[g][1]);
                mma16816(o[2 * g + 1], phi, vb[g][2], vb[g][3]);
            }
        }

        st = (st + 1 == 3) ? 0 : st + 1;
    }

    // l reduction within the 4-lane row group
    rs0 += __shfl_xor_sync(0xffffffffu, rs0, 1);
    rs0 += __shfl_xor_sync(0xffffffffu, rs0, 2);
    rs1 += __shfl_xor_sync(0xffffffffu, rs1, 1);
    rs1 += __shfl_xor_sync(0xffffffffu, rs1, 2);

    const int rl = wr + (lane >> 2);
    const int cb = 2 * (lane & 3);
    const int b = bh / NH, h = bh % NH;

    if (hf != 2) {
        const int tile = bh * 8 + (qt - 8);
        // ---- write own partial ----
        {
            int sidx = tile * 2 + hf;
            float* po = PO + (size_t)sidx * (128 * 64);
            float* pl = PL + (size_t)sidx * 128;
#pragma unroll
            for (int nd = 0; nd < 8; nd++) {
                *(float2*)&po[rl * 64 + cb + nd * 8] = make_float2(o[nd][0], o[nd][1]);
                *(float2*)&po[(rl + 8) * 64 + cb + nd * 8] = make_float2(o[nd][2], o[nd][3]);
            }
            if ((lane & 3) == 0) { pl[rl] = rs0; pl[rl + 8] = rs1; }
        }
        // ---- ticket: last arriver combines ----
        __syncthreads();
        if (tid == 0) {
            __threadfence();
            sflag = atomicAdd(&g_cnt[tile], 1);
        }
        __syncthreads();
        if (sflag == 0) return;           // first half: peer will combine
        if (tid == 0) g_cnt[tile] = 0;    // reset for next graph replay

        // read peer partial, add to registers (commutative -> deterministic)
        const int pidx = tile * 2 + (hf ^ 1);
        const float* qo = PO + (size_t)pidx * (128 * 64);
        const float* qls = PL + (size_t)pidx * 128;
        float inv0 = 1.f / (rs0 + qls[rl]);
        float inv1 = 1.f / (rs1 + qls[rl + 8]);
        size_t off0 = ((size_t)b * SEQ + qbase + rl) * EMB + h * HD + cb;
        size_t off1 = off0 + 8 * (size_t)EMB;
#pragma unroll
        for (int nd = 0; nd < 8; nd++) {
            float2 x0 = *(const float2*)&qo[rl * 64 + cb + nd * 8];
            float2 x1 = *(const float2*)&qo[(rl + 8) * 64 + cb + nd * 8];
            float f0 = (o[nd][0] + x0.x) * inv0, f1 = (o[nd][1] + x0.y) * inv0;
            uint32_t hp = cvt_bf2(f0, f1);
            uint32_t lp = cvt_bf2(f0 - bflo(hp), f1 - bfhi(hp));
            *(uint32_t*)&AOhi[off0 + nd * 8] = hp;
            *(uint32_t*)&AOlo[off0 + nd * 8] = lp;
            float g0 = (o[nd][2] + x1.x) * inv1, g1 = (o[nd][3] + x1.y) * inv1;
            uint32_t hq = cvt_bf2(g0, g1);
            uint32_t lq = cvt_bf2(g0 - bflo(hq), g1 - bfhi(hq));
            *(uint32_t*)&AOhi[off1 + nd * 8] = hq;
            *(uint32_t*)&AOlo[off1 + nd * 8] = lq;
        }
        return;
    }

    // ---- unsplit: normalize and write ao hi/lo directly ----
    float inv0 = 1.f / rs0, inv1 = 1.f / rs1;
    size_t off0 = ((size_t)b * SEQ + qbase + rl) * EMB + h * HD + cb;
    size_t off1 = off0 + 8 * (size_t)EMB;
#pragma unroll
    for (int nd = 0; nd < 8; nd++) {
        float f0 = o[nd][0] * inv0, f1 = o[nd][1] * inv0;
        uint32_t hp = cvt_bf2(f0, f1);
        uint32_t lp = cvt_bf2(f0 - bflo(hp), f1 - bfhi(hp));
        *(uint32_t*)&AOhi[off0 + nd * 8] = hp;
        *(uint32_t*)&AOlo[off0 + nd * 8] = lp;
        float g0 = o[nd][2] * inv1, g1 = o[nd][3] * inv1;
        uint32_t hq = cvt_bf2(g0, g1);
        uint32_t lq = cvt_bf2(g0 - bflo(hq), g1 - bfhi(hq));
        *(uint32_t*)&AOhi[off1 + nd * 8] = hq;
        *(uint32_t*)&AOlo[off1 + nd * 8] = lq;
    }
}

// =================================================================
// launch
// =================================================================
extern "C" void kernel_launch(void* const* d_in, const int* in_sizes, int n_in,
                              void* d_out, int out_size)
{
    const float* x    = (const float*)d_in[0];
    const float* wq_b = (const float*)d_in[2];
    const float* wk_b = (const float*)d_in[4];
    const float* wv_b = (const float*)d_in[6];
    const float* wo_b = (const float*)d_in[8];
    float* out = (float*)d_out;

    bf16 *xhi, *xlo;
    bf16 *qhi, *qlo, *khi, *klo, *vhi, *vlo, *aohi, *aolo;
    float *po, *pl;
    cudaGetSymbolAddress((void**)&xhi, g_xhi);
    cudaGetSymbolAddress((void**)&xlo, g_xlo);
    cudaGetSymbolAddress((void**)&qhi, g_qhi);
    cudaGetSymbolAddress((void**)&qlo, g_qlo);
    cudaGetSymbolAddress((void**)&khi, g_khi);
    cudaGetSymbolAddress((void**)&klo, g_klo);
    cudaGetSymbolAddress((void**)&vhi, g_vhi);
    cudaGetSymbolAddress((void**)&vlo, g_vlo);
    cudaGetSymbolAddress((void**)&aohi, g_aohi);
    cudaGetSymbolAddress((void**)&aolo, g_aolo);
    cudaGetSymbolAddress((void**)&po, g_po);
    cudaGetSymbolAddress((void**)&pl, g_pl);

    cudaFuncSetAttribute(attn_mma,
                         cudaFuncAttributeMaxDynamicSharedMemorySize, ATT_SMEM);
    cudaFuncSetAttribute(qkv_mma,
                         cudaFuncAttributeMaxDynamicSharedMemorySize, GEMM_SMEM);
    cudaFuncSetAttribute(out_mma,
                         cudaFuncAttributeMaxDynamicSharedMemorySize, GEMM_SMEM);

    split_all_kernel<<<4 * WB + XB, 256>>>(
        x, (const float*)d_in[1], (const float*)d_in[3],
        (const float*)d_in[5], (const float*)d_in[7], xhi, xlo);

    dim3 gqkv(NQKV / BN, MROWS / 128);             // 18 x 32 = 576
    qkv_mma<<<gqkv, 256, GEMM_SMEM>>>(wq_b, wk_b, wv_b);

    attn_mma<<<24 * BATCH * NH, 256, ATT_SMEM>>>(
        qhi, qlo, khi, klo, vhi, vlo, aohi, aolo, po, pl);

    dim3 go(EMB / BN, MROWS / 64);                 // 6 x 64 = 384 CTAs
    out_mma<<<go, 256, GEMM_SMEM>>>(wo_b, out);
}

// round 15
// speedup vs baseline: 1.8279x; 1.0046x over previous
#include <cuda_runtime.h>
#include <cuda_bf16.h>
#include <cstdint>

#define SEQ   2048
#define EMB   768
#define NH    12
#define HD    64
#define BATCH 2
#define MROWS (BATCH * SEQ)   // 4096
#define NQKV  (3 * EMB)       // 2304

typedef __nv_bfloat16 bf16;

// ---------------- scratch (static device arrays; no allocation) -------------
__device__ bf16 g_xhi[MROWS * EMB], g_xlo[MROWS * EMB];
__device__ bf16 g_whi[4][EMB * EMB], g_wlo[4][EMB * EMB];   // q,k,v,o
__device__ bf16 g_qhi[BATCH * NH * SEQ * HD], g_qlo[BATCH * NH * SEQ * HD];
__device__ bf16 g_khi[BATCH * NH * SEQ * HD], g_klo[BATCH * NH * SEQ * HD];
__device__ bf16 g_vhi[BATCH * NH * SEQ * HD], g_vlo[BATCH * NH * SEQ * HD];
__device__ bf16 g_aohi[MROWS * EMB], g_aolo[MROWS * EMB];
// split-KV partials: 24 bh x 8 split q-tiles x 2 halves
__device__ float g_po[24 * 8 * 2 * 128 * 64];
__device__ float g_pl[24 * 8 * 2 * 128];
__device__ int   g_cnt[24 * 8];   // zero-init tickets; reset each replay

// heavy-first unit schedule: 16 split halves (qt 8..15) + 8 unsplit (qt 0..7)
__constant__ int8_t UQT[24] = {15,15,7,14,14,13,13,6,12,12,11,11,5,10,10,9,9,4,8,8,3,2,1,0};
__constant__ int8_t UHF[24] = {0,1,2,0,1,0,1,2,0,1,0,1,2,0,1,0,1,2,0,1,2,2,2,2};

// ---------------- small helpers ----------------
__device__ __forceinline__ uint32_t cvt_bf2(float lo, float hi) {
    uint32_t r;
    asm("cvt.rn.bf16x2.f32 %0, %1, %2;" : "=r"(r) : "f"(hi), "f"(lo));
    return r;
}
__device__ __forceinline__ float bflo(uint32_t p) { return __uint_as_float(p << 16); }
__device__ __forceinline__ float bfhi(uint32_t p) { return __uint_as_float(p & 0xffff0000u); }
__device__ __forceinline__ float ex2f(float x) {
    float y;
    asm("ex2.approx.ftz.f32 %0, %1;" : "=f"(y) : "f"(x));
    return y;
}
__device__ __forceinline__ void ldsm4(uint32_t& r0, uint32_t& r1,
                                      uint32_t& r2, uint32_t& r3, uint32_t addr)
{
    asm volatile("ldmatrix.sync.aligned.m8n8.x4.shared.b16 {%0,%1,%2,%3}, [%4];"
                 : "=r"(r0), "=r"(r1), "=r"(r2), "=r"(r3) : "r"(addr));
}
__device__ __forceinline__ void ldsm4t(uint32_t& r0, uint32_t& r1,
                                       uint32_t& r2, uint32_t& r3, uint32_t addr)
{
    asm volatile("ldmatrix.sync.aligned.m8n8.x4.trans.shared.b16 {%0,%1,%2,%3}, [%4];"
                 : "=r"(r0), "=r"(r1), "=r"(r2), "=r"(r3) : "r"(addr));
}
__device__ __forceinline__ void mma16816(float c[4], const uint32_t a[4],
                                         uint32_t b0, uint32_t b1)
{
    asm volatile(
        "mma.sync.aligned.m16n8k16.row.col.f32.bf16.bf16.f32 "
        "{%0,%1,%2,%3}, {%4,%5,%6,%7}, {%8,%9}, {%0,%1,%2,%3};"
        : "+f"(c[0]), "+f"(c[1]), "+f"(c[2]), "+f"(c[3])
        : "r"(a[0]), "r"(a[1]), "r"(a[2]), "r"(a[3]), "r"(b0), "r"(b1));
}
__device__ __forceinline__ void cp16(uint32_t saddr, const void* gaddr)
{
    asm volatile("cp.async.cg.shared.global [%0], [%1], 16;"
                 :: "r"(saddr), "l"(gaddr));
}
template<int N>
__device__ __forceinline__ void cp_wait()
{
    asm volatile("cp.async.wait_group %0;" :: "n"(N));
}

// =================================================================
// fp32 -> bf16 hi/lo split: one flat 1D launch
// =================================================================
#define WB ((EMB * EMB / 4 + 255) / 256)      // 576
#define XB ((MROWS * EMB / 4 + 255) / 256)    // 3072

__global__ __launch_bounds__(256) void split_all_kernel(
    const float* __restrict__ x,
    const float* __restrict__ wq, const float* __restrict__ wk,
    const float* __restrict__ wv, const float* __restrict__ wo,
    bf16* __restrict__ xhi, bf16* __restrict__ xlo)
{
    int bid = blockIdx.x;
    const float4* src;
    uint2 *hi, *lo;
    int i, n4;
    if (bid < 4 * WB) {
        int z = bid / WB;
        src = (const float4*)((z == 0) ? wq : (z == 1) ? wk :
                              (z == 2) ? wv : wo);
        hi = (uint2*)g_whi[z]; lo = (uint2*)g_wlo[z];
        i = (bid - z * WB) * 256 + threadIdx.x;
        n4 = EMB * EMB / 4;
    } else {
        src = (const float4*)x;
        hi = (uint2*)xhi; lo = (uint2*)xlo;
        i = (bid - 4 * WB) * 256 + threadIdx.x;
        n4 = MROWS * EMB / 4;
    }
    if (i < n4) {
        float4 v = src[i];
        uint32_t h0 = cvt_bf2(v.x, v.y);
        uint32_t h1 = cvt_bf2(v.z, v.w);
        uint32_t l0 = cvt_bf2(v.x - bflo(h0), v.y - bfhi(h0));
        uint32_t l1 = cvt_bf2(v.z - bflo(h1), v.w - bfhi(h1));
        hi[i] = make_uint2(h0, h1);
        lo[i] = make_uint2(l0, l1);
    }
}

// =================================================================
// FUSED bf16-split MMA GEMM for QKV (BM=128, 2-stage, verified)
// =================================================================
#define BN 128
#define BK 32
#define LDSK 40
#define NKB (EMB / BK)                 // 24 iterations
#define TILE_B (128 * LDSK * 2)        // 10240 bytes
#define GSTAGE_B (2 * TILE_B)          // 20480
#define GEMM_SMEM (4 * GSTAGE_B)       // 81920

__device__ __forceinline__ void gemm_issue(
    int kb, int buf,
    const bf16* __restrict__ Ahi, const bf16* __restrict__ Alo,
    const bf16* __restrict__ Bhi, const bf16* __restrict__ Blo,
    uint32_t asb, uint32_t bsb, int m0, int n0, int srow, int schk)
{
    int k0 = kb * BK;
    uint32_t sa = asb + (uint32_t)buf * GSTAGE_B;
    uint32_t sb = bsb + (uint32_t)buf * GSTAGE_B;
    uint32_t o0 = (srow * LDSK + schk) * 2;
    uint32_t o1 = ((srow + 64) * LDSK + schk) * 2;
    size_t g0 = (size_t)(m0 + srow) * EMB + k0 + schk;
    size_t g1 = (size_t)(m0 + srow + 64) * EMB + k0 + schk;
    size_t h0 = (size_t)(n0 + srow) * EMB + k0 + schk;
    size_t h1 = (size_t)(n0 + srow + 64) * EMB + k0 + schk;
    cp16(sa + o0, Ahi + g0);
    cp16(sa + TILE_B + o0, Alo + g0);
    cp16(sa + o1, Ahi + g1);
    cp16(sa + TILE_B + o1, Alo + g1);
    cp16(sb + o0, Bhi + h0);
    cp16(sb + o1, Bhi + h1);
    cp16(sb + TILE_B + o0, Blo + h0);
    cp16(sb + TILE_B + o1, Blo + h1);
    asm volatile("cp.async.commit_group;");
}

__global__ __launch_bounds__(256, 2) void qkv_mma(
    const float* __restrict__ bq, const float* __restrict__ bk,
    const float* __restrict__ bv)
{
    extern __shared__ char dsm[];
    const uint32_t asb = (uint32_t)__cvta_generic_to_shared(dsm);
    const uint32_t bsb = asb + 2 * GSTAGE_B;

    int m0 = blockIdx.y * 128;
    int ng = blockIdx.x * BN;
    int sel = ng / EMB;
    int n0 = ng - sel * EMB;
    const bf16* Bhi = g_whi[sel];
    const bf16* Blo = g_wlo[sel];
    const float* bias = (sel == 0) ? bq : (sel == 1) ? bk : bv;
    bf16* Chi = (sel == 0) ? g_qhi : (sel == 1) ? g_khi : g_vhi;
    bf16* Clo = (sel == 0) ? g_qlo : (sel == 1) ? g_klo : g_vlo;
    float scale = (sel == 0) ? 0.125f * 1.4426950408889634f : 1.0f;

    const int tid = threadIdx.x;
    const int lane = tid & 31;
    const int wid = tid >> 5;
    const int wm = wid >> 2;
    const int wn = wid & 3;

    float acc[4][4][4];
#pragma unroll
    for (int i = 0; i < 4; i++)
#pragma unroll
        for (int j = 0; j < 4; j++)
#pragma unroll
            for (int t = 0; t < 4; t++) acc[i][j][t] = 0.f;

    const int srow = tid >> 2;
    const int schk = (tid & 3) * 8;

    const int laRow = wm * 64 + (lane & 15);
    const int laCol = (lane >> 4) * 8;
    const int lbRow = wn * 32 + ((lane >> 4) << 3) + (lane & 7);
    const int lbCol = ((lane >> 3) & 1) * 8;

    gemm_issue(0, 0, g_xhi, g_xlo, Bhi, Blo, asb, bsb, m0, n0, srow, schk);

    for (int it = 0; it < NKB; it++) {
        const int buf = it & 1;
        cp_wait<0>();
        __syncthreads();
        if (it + 1 < NKB)
            gemm_issue(it + 1, buf ^ 1, g_xhi, g_xlo, Bhi, Blo, asb, bsb,
                       m0, n0, srow, schk);

        const uint32_t sa = asb + (uint32_t)buf * GSTAGE_B;
        const uint32_t sb = bsb + (uint32_t)buf * GSTAGE_B;

#pragma unroll
        for (int ks = 0; ks < 2; ks++) {
            const uint32_t aoff = (uint32_t)(ks * 16 + laCol) * 2;
            const uint32_t boff = (uint32_t)(ks * 16 + lbCol) * 2;
            uint32_t a[4][4], a2[4][4], b[2][4];
#pragma unroll
            for (int mt = 0; mt < 4; mt++)
                ldsm4(a[mt][0], a[mt][1], a[mt][2], a[mt][3],
                      sa + (uint32_t)((laRow + mt * 16) * LDSK) * 2 + aoff);
#pragma unroll
            for (int p = 0; p < 2; p++)
                ldsm4(b[p][0], b[p][1], b[p][2], b[p][3],
                      sb + (uint32_t)((lbRow + p * 16) * LDSK) * 2 + boff);
#pragma unroll
            for (int mt = 0; mt < 4; mt++)
#pragma unroll
                for (int nt = 0; nt < 4; nt++)
                    mma16816(acc[mt][nt], a[mt],
                             b[nt >> 1][(nt & 1) * 2], b[nt >> 1][(nt & 1) * 2 + 1]);
#pragma unroll
            for (int mt = 0; mt < 4; mt++)
                ldsm4(a2[mt][0], a2[mt][1], a2[mt][2], a2[mt][3],
                      sa + TILE_B + (uint32_t)((laRow + mt * 16) * LDSK) * 2 + aoff);
#pragma unroll
            for (int mt = 0; mt < 4; mt++)
#pragma unroll
                for (int nt = 0; nt < 4; nt++)
                    mma16816(acc[mt][nt], a2[mt],
                             b[nt >> 1][(nt & 1) * 2], b[nt >> 1][(nt & 1) * 2 + 1]);
#pragma unroll
            for (int p = 0; p < 2; p++)
                ldsm4(b[p][0], b[p][1], b[p][2], b[p][3],
                      sb + TILE_B + (uint32_t)((lbRow + p * 16) * LDSK) * 2 + boff);
#pragma unroll
            for (int mt = 0; mt < 4; mt++)
#pragma unroll
                for (int nt = 0; nt < 4; nt++)
                    mma16816(acc[mt][nt], a[mt],
                             b[nt >> 1][(nt & 1) * 2], b[nt >> 1][(nt & 1) * 2 + 1]);
        }
    }

    const int er = lane >> 2;
    const int ec = (lane & 3) * 2;
#pragma unroll
    for (int mt = 0; mt < 4; mt++) {
        int m = m0 + wm * 64 + mt * 16 + er;
#pragma unroll
        for (int nt = 0; nt < 4; nt++) {
            int n = n0 + wn * 32 + nt * 8 + ec;
            float b0 = bias[n], b1 = bias[n + 1];
            float v00 = (acc[mt][nt][0] + b0) * scale;
            float v01 = (acc[mt][nt][1] + b1) * scale;
            float v10 = (acc[mt][nt][2] + b0) * scale;
            float v11 = (acc[mt][nt][3] + b1) * scale;
            int h = n >> 6, d = n & 63;
            int bb0 = m >> 11, s0 = m & 2047;
            int bb1 = (m + 8) >> 11, s1 = (m + 8) & 2047;
            size_t p0 = (((size_t)(bb0 * NH + h)) * SEQ + s0) * HD + d;
            size_t p1 = (((size_t)(bb1 * NH + h)) * SEQ + s1) * HD + d;
            uint32_t hp = cvt_bf2(v00, v01);
            uint32_t lp = cvt_bf2(v00 - bflo(hp), v01 - bfhi(hp));
            *(uint32_t*)&Chi[p0] = hp;
            *(uint32_t*)&Clo[p0] = lp;
            hp = cvt_bf2(v10, v11);
            lp = cvt_bf2(v10 - bflo(hp), v11 - bfhi(hp));
            *(uint32_t*)&Chi[p1] = hp;
            *(uint32_t*)&Clo[p1] = lp;
        }
    }
}

// =================================================================
// OUT projection: dedicated BM=64 kernel, compact 3-stage ring
// (prefetch distance 2), grid transposed (m fastest) for B L2 reuse.
// Stage layout: [Ahi 64r][Alo 64r][Bhi 128r][Blo 128r] = 30720 B.
// =================================================================
#define O_ASTAGE 5120u                  // 64 rows * 40 * 2B
#define O_AB     (2u * O_ASTAGE)        // 10240 (hi+lo A)
#define O_BSTAGE 10240u                 // 128 rows * 40 * 2B
#define O_STAGE  (O_AB + 2u * O_BSTAGE) // 30720
#define OUT_SMEM (3 * O_STAGE)          // 92160

__device__ __forceinline__ void out_issue(
    int kb, int st, uint32_t base, int m0, int n0, int srow, int schk)
{
    int k0 = kb * BK;
    uint32_t sa = base + (uint32_t)st * O_STAGE;
    uint32_t sb = sa + O_AB;
    uint32_t o0 = (srow * LDSK + schk) * 2;
    uint32_t o1 = ((srow + 64) * LDSK + schk) * 2;
    size_t g0 = (size_t)(m0 + srow) * EMB + k0 + schk;
    size_t h0 = (size_t)(n0 + srow) * EMB + k0 + schk;
    size_t h1 = (size_t)(n0 + srow + 64) * EMB + k0 + schk;
    cp16(sa + o0, g_aohi + g0);
    cp16(sa + O_ASTAGE + o0, g_aolo + g0);
    cp16(sb + o0, g_whi[3] + h0);
    cp16(sb + o1, g_whi[3] + h1);
    cp16(sb + O_BSTAGE + o0, g_wlo[3] + h0);
    cp16(sb + O_BSTAGE + o1, g_wlo[3] + h1);
    asm volatile("cp.async.commit_group;");
}

__global__ __launch_bounds__(256, 2) void out_mma(
    const float* __restrict__ bo, float* __restrict__ out)
{
    extern __shared__ char dsm[];
    const uint32_t base = (uint32_t)__cvta_generic_to_shared(dsm);

    const int m0 = blockIdx.x * 64;     // m fastest -> B-tile L2 locality
    const int n0 = blockIdx.y * BN;

    const int tid = threadIdx.x;
    const int lane = tid & 31;
    const int wid = tid >> 5;
    const int wm = wid >> 2;            // 0..1 (32 rows each)
    const int wn = wid & 3;

    float acc[2][4][4];
#pragma unroll
    for (int i = 0; i < 2; i++)
#pragma unroll
        for (int j = 0; j < 4; j++)
#pragma unroll
            for (int t = 0; t < 4; t++) acc[i][j][t] = 0.f;

    const int srow = tid >> 2;
    const int schk = (tid & 3) * 8;

    const int laRow = wm * 32 + (lane & 15);
    const int laCol = (lane >> 4) * 8;
    const int lbRow = wn * 32 + ((lane >> 4) << 3) + (lane & 7);
    const int lbCol = ((lane >> 3) & 1) * 8;

    out_issue(0, 0, base, m0, n0, srow, schk);
    out_issue(1, 1, base, m0, n0, srow, schk);

    int st = 0;
    for (int it = 0; it < NKB; it++) {
        if (it + 1 < NKB) cp_wait<1>(); else cp_wait<0>();
        __syncthreads();
        if (it + 2 < NKB) {
            int s2 = st + 2; if (s2 >= 3) s2 -= 3;
            out_issue(it + 2, s2, base, m0, n0, srow, schk);
        }

        const uint32_t sa = base + (uint32_t)st * O_STAGE;
        const uint32_t sb = sa + O_AB;

#pragma unroll
        for (int ks = 0; ks < 2; ks++) {
            const uint32_t aoff = (uint32_t)(ks * 16 + laCol) * 2;
            const uint32_t boff = (uint32_t)(ks * 16 + lbCol) * 2;
            uint32_t a[2][4], a2[2][4], b[2][4];
#pragma unroll
            for (int mt = 0; mt < 2; mt++)
                ldsm4(a[mt][0], a[mt][1], a[mt][2], a[mt][3],
                      sa + (uint32_t)((laRow + mt * 16) * LDSK) * 2 + aoff);
#pragma unroll
            for (int p = 0; p < 2; p++)
                ldsm4(b[p][0], b[p][1], b[p][2], b[p][3],
                      sb + (uint32_t)((lbRow + p * 16) * LDSK) * 2 + boff);
#pragma unroll
            for (int mt = 0; mt < 2; mt++)
#pragma unroll
                for (int nt = 0; nt < 4; nt++)
                    mma16816(acc[mt][nt], a[mt],
                             b[nt >> 1][(nt & 1) * 2], b[nt >> 1][(nt & 1) * 2 + 1]);
#pragma unroll
            for (int mt = 0; mt < 2; mt++)
                ldsm4(a2[mt][0], a2[mt][1], a2[mt][2], a2[mt][3],
                      sa + O_ASTAGE + (uint32_t)((laRow + mt * 16) * LDSK) * 2 + aoff);
#pragma unroll
            for (int mt = 0; mt < 2; mt++)
#pragma unroll
                for (int nt = 0; nt < 4; nt++)
                    mma16816(acc[mt][nt], a2[mt],
                             b[nt >> 1][(nt & 1) * 2], b[nt >> 1][(nt & 1) * 2 + 1]);
#pragma unroll
            for (int p = 0; p < 2; p++)
                ldsm4(b[p][0], b[p][1], b[p][2], b[p][3],
                      sb + O_BSTAGE + (uint32_t)((lbRow + p * 16) * LDSK) * 2 + boff);
#pragma unroll
            for (int mt = 0; mt < 2; mt++)
#pragma unroll
                for (int nt = 0; nt < 4; nt++)
                    mma16816(acc[mt][nt], a[mt],
                             b[nt >> 1][(nt & 1) * 2], b[nt >> 1][(nt & 1) * 2 + 1]);
        }
        st = (st + 1 == 3) ? 0 : st + 1;
    }

    const int er = lane >> 2;
    const int ec = (lane & 3) * 2;
#pragma unroll
    for (int mt = 0; mt < 2; mt++) {
        int m = m0 + wm * 32 + mt * 16 + er;
#pragma unroll
        for (int nt = 0; nt < 4; nt++) {
            int n = n0 + wn * 32 + nt * 8 + ec;
            float b0 = bo[n], b1 = bo[n + 1];
            *(float2*)&out[(size_t)m * EMB + n] =
                make_float2(acc[mt][nt][0] + b0, acc[mt][nt][1] + b1);
            *(float2*)&out[(size_t)(m + 8) * EMB + n] =
                make_float2(acc[mt][nt][2] + b0, acc[mt][nt][3] + b1);
        }
    }
}

// =================================================================
// Tensor-core flash attention + split-KV + in-kernel combine
// (round-14 config, byte-identical)
// =================================================================
#define STR 72
#define KV_STAGE_B (256 * STR * 2)       // 36864
#define ATT_SMEM (3 * KV_STAGE_B)        // 110592

__device__ __forceinline__ void kv_issue(uint32_t sb, int buf, int kbase,
                                         const bf16* const kvsrc[4], int tid)
{
    uint32_t base = sb + (uint32_t)buf * KV_STAGE_B;
#pragma unroll
    for (int i = 0; i < 8; i++) {
        int c = i * 256 + tid;
        int row = (c >> 3) & 63;
        int ch = (c & 7) * 8;
        cp16(base + (uint32_t)(((i >> 1) * 64 + row) * STR + ch) * 2,
             kvsrc[i >> 1] + (size_t)(kbase + row) * HD + ch);
    }
    asm volatile("cp.async.commit_group;");
}

__global__ __launch_bounds__(256, 2) void attn_mma(
    const bf16* __restrict__ Qhi_g, const bf16* __restrict__ Qlo_g,
    const bf16* __restrict__ Khi_g, const bf16* __restrict__ Klo_g,
    const bf16* __restrict__ Vhi_g, const bf16* __restrict__ Vlo_g,
    bf16* __restrict__ AOhi, bf16* __restrict__ AOlo,
    float* __restrict__ PO, float* __restrict__ PL)
{
    extern __shared__ char dsm[];
    __shared__ int sflag;
    const uint32_t sb = (uint32_t)__cvta_generic_to_shared(dsm);

    const int bid = blockIdx.x;
    const int unit = bid / (BATCH * NH);
    const int bh = bid % (BATCH * NH);
    const int qt = UQT[unit];
    const int hf = UHF[unit];
    const int qbase = qt * 128;
    int kstart, nktl;
    if (hf == 2) { kstart = 0; nktl = 2 * qt + 2; }
    else         { nktl = qt + 1; kstart = hf * nktl; }

    const int tid = threadIdx.x;
    const int lane = tid & 31;
    const int wid = tid >> 5;
    const int wr = wid * 16;

    const size_t hoff = (size_t)bh * SEQ * HD;
    const bf16* qsrc[2] = {Qhi_g + hoff, Qlo_g + hoff};
    const bf16* kvsrc[4] = {Khi_g + hoff, Klo_g + hoff, Vhi_g + hoff, Vlo_g + hoff};

#pragma unroll
    for (int i = 0; i < 8; i++) {
        int c = i * 256 + tid;
        int row = (c >> 3) & 127;
        int ch = (c & 7) * 8;
        cp16(sb + (uint32_t)(((i >> 2) * 128 + row) * STR + ch) * 2,
             qsrc[i >> 2] + (size_t)(qbase + row) * HD + ch);
    }
    asm volatile("cp.async.commit_group;");
    cp_wait<0>();
    __syncthreads();

    uint32_t qh[4][4], ql[4][4];
    {
        int arow = wr + (lane & 15);
        int acol = (lane >> 4) * 8;
#pragma unroll
        for (int ks = 0; ks < 4; ks++) {
            ldsm4(qh[ks][0], qh[ks][1], qh[ks][2], qh[ks][3],
                  sb + (uint32_t)(arow * STR + ks * 16 + acol) * 2);
            ldsm4(ql[ks][0], ql[ks][1], ql[ks][2], ql[ks][3],
                  sb + (uint32_t)((128 + arow) * STR + ks * 16 + acol) * 2);
        }
    }
    __syncthreads();

    float o[8][4];
#pragma unroll
    for (int i = 0; i < 8; i++)
#pragma unroll
        for (int j = 0; j < 4; j++) o[i][j] = 0.f;
    float rs0 = 0.f, rs1 = 0.f;

    kv_issue(sb, 0, kstart * 64, kvsrc, tid);
    kv_issue(sb, 1, (kstart + 1) * 64, kvsrc, tid);

    const int brow = (lane & 7) + ((lane >> 4) << 3);
    const int bcol = ((lane >> 3) & 1) * 8;
    const int vrow = (lane & 7) + (((lane >> 3) & 1) << 3);
    const int vcol = (lane >> 4) * 8;

    int st = 0;
    for (int kt = 0; kt < nktl; kt++) {
        if (kt + 1 < nktl) cp_wait<1>(); else cp_wait<0>();
        __syncthreads();
        if (kt + 2 < nktl) {
            int b2 = st + 2; if (b2 >= 3) b2 -= 3;
            kv_issue(sb, b2, (kstart + kt + 2) * 64, kvsrc, tid);
        }

        const uint32_t kvb = sb + (uint32_t)st * KV_STAGE_B;
        const uint32_t Khi_s = kvb;
        const uint32_t Klo_s = kvb + 64 * STR * 2;
        const uint32_t Vhi_s = kvb + 128 * STR * 2;
        const uint32_t Vlo_s = kvb + 192 * STR * 2;
        const int kbase = (kstart + kt) * 64;

        float s[8][4];
#pragma unroll
        for (int i = 0; i < 8; i++)
#pragma unroll
            for (int j = 0; j < 4; j++) s[i][j] = 0.f;

#pragma unroll
        for (int ks = 0; ks < 4; ks++) {
            uint32_t bb[4][4];
#pragma unroll
            for (int ng = 0; ng < 4; ng++)
                ldsm4(bb[ng][0], bb[ng][1], bb[ng][2], bb[ng][3],
                      Khi_s + (uint32_t)((16 * ng + brow) * STR + 16 * ks + bcol) * 2);
#pragma unroll
            for (int ng = 0; ng < 4; ng++) {
                mma16816(s[2 * ng], qh[ks], bb[ng][0], bb[ng][1]);
                mma16816(s[2 * ng + 1], qh[ks], bb[ng][2], bb[ng][3]);
                mma16816(s[2 * ng], ql[ks], bb[ng][0], bb[ng][1]);
                mma16816(s[2 * ng + 1], ql[ks], bb[ng][2], bb[ng][3]);
            }
#pragma unroll
            for (int ng = 0; ng < 4; ng++)
                ldsm4(bb[ng][0], bb[ng][1], bb[ng][2], bb[ng][3],
                      Klo_s + (uint32_t)((16 * ng + brow) * STR + 16 * ks + bcol) * 2);
#pragma unroll
            for (int ng = 0; ng < 4; ng++) {
                mma16816(s[2 * ng], qh[ks], bb[ng][0], bb[ng][1]);
                mma16816(s[2 * ng + 1], qh[ks], bb[ng][2], bb[ng][3]);
            }
        }

        const bool diag = (kbase + 63 > qbase + wr);
        const int row0q = qbase + wr + (lane >> 2);
        const int colbq = kbase + 2 * (lane & 3);

#pragma unroll
        for (int t = 0; t < 4; t++) {
            if (diag) {
#pragma unroll
                for (int h2 = 0; h2 < 2; h2++) {
                    int nt = 2 * t + h2;
                    int c0 = colbq + nt * 8;
                    if (c0 > row0q) s[nt][0] = -1e30f;
                    if (c0 + 1 > row0q) s[nt][1] = -1e30f;
                    if (c0 > row0q + 8) s[nt][2] = -1e30f;
                    if (c0 + 1 > row0q + 8) s[nt][3] = -1e30f;
                }
            }
            uint32_t phi[4], plo[4];
#pragma unroll
            for (int h2 = 0; h2 < 2; h2++) {
                float* sp = s[2 * t + h2];
                sp[0] = ex2f(sp[0]); rs0 += sp[0];
                sp[1] = ex2f(sp[1]); rs0 += sp[1];
                sp[2] = ex2f(sp[2]); rs1 += sp[2];
                sp[3] = ex2f(sp[3]); rs1 += sp[3];
                uint32_t h0 = cvt_bf2(sp[0], sp[1]);
                phi[h2 * 2] = h0;
                plo[h2 * 2] = cvt_bf2(sp[0] - bflo(h0), sp[1] - bfhi(h0));
                uint32_t h1 = cvt_bf2(sp[2], sp[3]);
                phi[h2 * 2 + 1] = h1;
                plo[h2 * 2 + 1] = cvt_bf2(sp[2] - bflo(h1), sp[3] - bfhi(h1));
            }
            uint32_t vb[4][4];
#pragma unroll
            for (int g = 0; g < 4; g++)
                ldsm4t(vb[g][0], vb[g][1], vb[g][2], vb[g][3],
                       Vhi_s + (uint32_t)((16 * t + vrow) * STR + 16 * g + vcol) * 2);
#pragma unroll
            for (int g = 0; g < 4; g++) {
                mma16816(o[2 * g], phi, vb[g][0], vb[g][1]);
                mma16816(o[2 * g + 1], phi, vb[g][2], vb[g][3]);
                mma16816(o[2 * g], plo, vb[g][0], vb[g][1]);
                mma16816(o[2 * g + 1], plo, vb[g][2], vb[g][3]);
            }
#pragma unroll
            for (int g = 0; g < 4; g++)
                ldsm4t(vb[g][0], vb[g][1], vb[g][2], vb[g][3],
                       Vlo_s + (uint32_t)((16 * t + vrow) * STR + 16 * g + vcol) * 2);
#pragma unroll
            for (int g = 0; g < 4; g++) {
                mma16816(o[2 * g], phi, vb[g][0], vb[g][1]);
                mma16816(o[2 * g + 1], phi, vb[g][2], vb[g][3]);
            }
        }

        st = (st + 1 == 3) ? 0 : st + 1;
    }

    rs0 += __shfl_xor_sync(0xffffffffu, rs0, 1);
    rs0 += __shfl_xor_sync(0xffffffffu, rs0, 2);
    rs1 += __shfl_xor_sync(0xffffffffu, rs1, 1);
    rs1 += __shfl_xor_sync(0xffffffffu, rs1, 2);

    const int rl = wr + (lane >> 2);
    const int cb = 2 * (lane & 3);
    const int b = bh / NH, h = bh % NH;

    if (hf != 2) {
        const int tile = bh * 8 + (qt - 8);
        {
            int sidx = tile * 2 + hf;
            float* po = PO + (size_t)sidx * (128 * 64);
            float* pl = PL + (size_t)sidx * 128;
#pragma unroll
            for (int nd = 0; nd < 8; nd++) {
                *(float2*)&po[rl * 64 + cb + nd * 8] = make_float2(o[nd][0], o[nd][1]);
                *(float2*)&po[(rl + 8) * 64 + cb + nd * 8] = make_float2(o[nd][2], o[nd][3]);
            }
            if ((lane & 3) == 0) { pl[rl] = rs0; pl[rl + 8] = rs1; }
        }
        __syncthreads();
        if (tid == 0) {
            __threadfence();
            sflag = atomicAdd(&g_cnt[tile], 1);
        }
        __syncthreads();
        if (sflag == 0) return;
        if (tid == 0) g_cnt[tile] = 0;

        const int pidx = tile * 2 + (hf ^ 1);
        const float* qo = PO + (size_t)pidx * (128 * 64);
        const float* qls = PL + (size_t)pidx * 128;
        float inv0 = 1.f / (rs0 + qls[rl]);
        float inv1 = 1.f / (rs1 + qls[rl + 8]);
        size_t off0 = ((size_t)b * SEQ + qbase + rl) * EMB + h * HD + cb;
        size_t off1 = off0 + 8 * (size_t)EMB;
#pragma unroll
        for (int nd = 0; nd < 8; nd++) {
            float2 x0 = *(const float2*)&qo[rl * 64 + cb + nd * 8];
            float2 x1 = *(const float2*)&qo[(rl + 8) * 64 + cb + nd * 8];
            float f0 = (o[nd][0] + x0.x) * inv0, f1 = (o[nd][1] + x0.y) * inv0;
            uint32_t hp = cvt_bf2(f0, f1);
            uint32_t lp = cvt_bf2(f0 - bflo(hp), f1 - bfhi(hp));
            *(uint32_t*)&AOhi[off0 + nd * 8] = hp;
            *(uint32_t*)&AOlo[off0 + nd * 8] = lp;
            float g0 = (o[nd][2] + x1.x) * inv1, g1 = (o[nd][3] + x1.y) * inv1;
            uint32_t hq = cvt_bf2(g0, g1);
            uint32_t lq = cvt_bf2(g0 - bflo(hq), g1 - bfhi(hq));
            *(uint32_t*)&AOhi[off1 + nd * 8] = hq;
            *(uint32_t*)&AOlo[off1 + nd * 8] = lq;
        }
        return;
    }

    float inv0 = 1.f / rs0, inv1 = 1.f / rs1;
    size_t off0 = ((size_t)b * SEQ + qbase + rl) * EMB + h * HD + cb;
    size_t off1 = off0 + 8 * (size_t)EMB;
#pragma unroll
    for (int nd = 0; nd < 8; nd++) {
        float f0 = o[nd][0] * inv0, f1 = o[nd][1] * inv0;
        uint32_t hp = cvt_bf2(f0, f1);
        uint32_t lp = cvt_bf2(f0 - bflo(hp), f1 - bfhi(hp));
        *(uint32_t*)&AOhi[off0 + nd * 8] = hp;
        *(uint32_t*)&AOlo[off0 + nd * 8] = lp;
        float g0 = o[nd][2] * inv1, g1 = o[nd][3] * inv1;
        uint32_t hq = cvt_bf2(g0, g1);
        uint32_t lq = cvt_bf2(g0 - bflo(hq), g1 - bfhi(hq));
        *(uint32_t*)&AOhi[off1 + nd * 8] = hq;
        *(uint32_t*)&AOlo[off1 + nd * 8] = lq;
    }
}

// =================================================================
// launch
// =================================================================
extern "C" void kernel_launch(void* const* d_in, const int* in_sizes, int n_in,
                              void* d_out, int out_size)
{
    const float* x    = (const float*)d_in[0];
    const float* wq_b = (const float*)d_in[2];
    const float* wk_b = (const float*)d_in[4];
    const float* wv_b = (const float*)d_in[6];
    const float* wo_b = (const float*)d_in[8];
    float* out = (float*)d_out;

    bf16 *xhi, *xlo;
    bf16 *qhi, *qlo, *khi, *klo, *vhi, *vlo, *aohi, *aolo;
    float *po, *pl;
    cudaGetSymbolAddress((void**)&xhi, g_xhi);
    cudaGetSymbolAddress((void**)&xlo, g_xlo);
    cudaGetSymbolAddress((void**)&qhi, g_qhi);
    cudaGetSymbolAddress((void**)&qlo, g_qlo);
    cudaGetSymbolAddress((void**)&khi, g_khi);
    cudaGetSymbolAddress((void**)&klo, g_klo);
    cudaGetSymbolAddress((void**)&vhi, g_vhi);
    cudaGetSymbolAddress((void**)&vlo, g_vlo);
    cudaGetSymbolAddress((void**)&aohi, g_aohi);
    cudaGetSymbolAddress((void**)&aolo, g_aolo);
    cudaGetSymbolAddress((void**)&po, g_po);
    cudaGetSymbolAddress((void**)&pl, g_pl);

    cudaFuncSetAttribute(attn_mma,
                         cudaFuncAttributeMaxDynamicSharedMemorySize, ATT_SMEM);
    cudaFuncSetAttribute(qkv_mma,
                         cudaFuncAttributeMaxDynamicSharedMemorySize, GEMM_SMEM);
    cudaFuncSetAttribute(out_mma,
                         cudaFuncAttributeMaxDynamicSharedMemorySize, OUT_SMEM);

    split_all_kernel<<<4 * WB + XB, 256>>>(
        x, (const float*)d_in[1], (const float*)d_in[3],
        (const float*)d_in[5], (const float*)d_in[7], xhi, xlo);

    dim3 gqkv(NQKV / BN, MROWS / 128);             // 18 x 32 = 576
    qkv_mma<<<gqkv, 256, GEMM_SMEM>>>(wq_b, wk_b, wv_b);

    attn_mma<<<24 * BATCH * NH, 256, ATT_SMEM>>>(
        qhi, qlo, khi, klo, vhi, vlo, aohi, aolo, po, pl);

    dim3 go(MROWS / 64, EMB / BN);                 // 64 x 6, m fastest
    out_mma<<<go, 256, OUT_SMEM>>>(wo_b, out);
}

// round 16
// speedup vs baseline: 1.8706x; 1.0234x over previous
#include <cuda_runtime.h>
#include <cuda_bf16.h>
#include <cstdint>

#define SEQ   2048
#define EMB   768
#define NH    12
#define HD    64
#define BATCH 2
#define MROWS (BATCH * SEQ)   // 4096
#define NQKV  (3 * EMB)       // 2304

typedef __nv_bfloat16 bf16;

// ---------------- scratch (static device arrays; no allocation) -------------
__device__ bf16 g_xhi[MROWS * EMB], g_xlo[MROWS * EMB];
__device__ bf16 g_whi[4][EMB * EMB], g_wlo[4][EMB * EMB];   // q,k,v,o
__device__ bf16 g_qhi[BATCH * NH * SEQ * HD], g_qlo[BATCH * NH * SEQ * HD];
__device__ bf16 g_khi[BATCH * NH * SEQ * HD], g_klo[BATCH * NH * SEQ * HD];
__device__ bf16 g_vhi[BATCH * NH * SEQ * HD], g_vlo[BATCH * NH * SEQ * HD];
__device__ bf16 g_aohi[MROWS * EMB], g_aolo[MROWS * EMB];
// split-KV partials: 24 bh x 8 split q-tiles x 2 halves
__device__ float g_po[24 * 8 * 2 * 128 * 64];
__device__ float g_pl[24 * 8 * 2 * 128];
__device__ int   g_cnt[24 * 8];   // zero-init tickets; reset each replay

// heavy-first unit schedule: 16 split halves (qt 8..15) + 8 unsplit (qt 0..7)
__constant__ int8_t UQT[24] = {15,15,7,14,14,13,13,6,12,12,11,11,5,10,10,9,9,4,8,8,3,2,1,0};
__constant__ int8_t UHF[24] = {0,1,2,0,1,0,1,2,0,1,0,1,2,0,1,0,1,2,0,1,2,2,2,2};

// ---------------- small helpers ----------------
__device__ __forceinline__ uint32_t cvt_bf2(float lo, float hi) {
    uint32_t r;
    asm("cvt.rn.bf16x2.f32 %0, %1, %2;" : "=r"(r) : "f"(hi), "f"(lo));
    return r;
}
__device__ __forceinline__ float bflo(uint32_t p) { return __uint_as_float(p << 16); }
__device__ __forceinline__ float bfhi(uint32_t p) { return __uint_as_float(p & 0xffff0000u); }
__device__ __forceinline__ float ex2f(float x) {
    float y;
    asm("ex2.approx.ftz.f32 %0, %1;" : "=f"(y) : "f"(x));
    return y;
}
__device__ __forceinline__ void ldsm4(uint32_t& r0, uint32_t& r1,
                                      uint32_t& r2, uint32_t& r3, uint32_t addr)
{
    asm volatile("ldmatrix.sync.aligned.m8n8.x4.shared.b16 {%0,%1,%2,%3}, [%4];"
                 : "=r"(r0), "=r"(r1), "=r"(r2), "=r"(r3) : "r"(addr));
}
__device__ __forceinline__ void ldsm4t(uint32_t& r0, uint32_t& r1,
                                       uint32_t& r2, uint32_t& r3, uint32_t addr)
{
    asm volatile("ldmatrix.sync.aligned.m8n8.x4.trans.shared.b16 {%0,%1,%2,%3}, [%4];"
                 : "=r"(r0), "=r"(r1), "=r"(r2), "=r"(r3) : "r"(addr));
}
__device__ __forceinline__ void mma16816(float c[4], const uint32_t a[4],
                                         uint32_t b0, uint32_t b1)
{
    asm volatile(
        "mma.sync.aligned.m16n8k16.row.col.f32.bf16.bf16.f32 "
        "{%0,%1,%2,%3}, {%4,%5,%6,%7}, {%8,%9}, {%0,%1,%2,%3};"
        : "+f"(c[0]), "+f"(c[1]), "+f"(c[2]), "+f"(c[3])
        : "r"(a[0]), "r"(a[1]), "r"(a[2]), "r"(a[3]), "r"(b0), "r"(b1));
}
__device__ __forceinline__ void cp16(uint32_t saddr, const void* gaddr)
{
    asm volatile("cp.async.cg.shared.global [%0], [%1], 16;"
                 :: "r"(saddr), "l"(gaddr));
}
template<int N>
__device__ __forceinline__ void cp_wait()
{
    asm volatile("cp.async.wait_group %0;" :: "n"(N));
}

// =================================================================
// fp32 -> bf16 hi/lo split: one flat 1D launch
// =================================================================
#define WB ((EMB * EMB / 4 + 255) / 256)      // 576
#define XB ((MROWS * EMB / 4 + 255) / 256)    // 3072

__global__ __launch_bounds__(256) void split_all_kernel(
    const float* __restrict__ x,
    const float* __restrict__ wq, const float* __restrict__ wk,
    const float* __restrict__ wv, const float* __restrict__ wo,
    bf16* __restrict__ xhi, bf16* __restrict__ xlo)
{
    int bid = blockIdx.x;
    const float4* src;
    uint2 *hi, *lo;
    int i, n4;
    if (bid < 4 * WB) {
        int z = bid / WB;
        src = (const float4*)((z == 0) ? wq : (z == 1) ? wk :
                              (z == 2) ? wv : wo);
        hi = (uint2*)g_whi[z]; lo = (uint2*)g_wlo[z];
        i = (bid - z * WB) * 256 + threadIdx.x;
        n4 = EMB * EMB / 4;
    } else {
        src = (const float4*)x;
        hi = (uint2*)xhi; lo = (uint2*)xlo;
        i = (bid - 4 * WB) * 256 + threadIdx.x;
        n4 = MROWS * EMB / 4;
    }
    if (i < n4) {
        float4 v = src[i];
        uint32_t h0 = cvt_bf2(v.x, v.y);
        uint32_t h1 = cvt_bf2(v.z, v.w);
        uint32_t l0 = cvt_bf2(v.x - bflo(h0), v.y - bfhi(h0));
        uint32_t l1 = cvt_bf2(v.z - bflo(h1), v.w - bfhi(h1));
        hi[i] = make_uint2(h0, h1);
        lo[i] = make_uint2(l0, l1);
    }
}

// =================================================================
// FUSED bf16-split MMA GEMM for QKV (BM=128, 2-stage, verified)
// =================================================================
#define BN 128
#define BK 32
#define LDSK 40
#define NKB (EMB / BK)                 // 24 iterations
#define TILE_B (128 * LDSK * 2)        // 10240 bytes
#define GSTAGE_B (2 * TILE_B)          // 20480
#define GEMM_SMEM (4 * GSTAGE_B)       // 81920

__device__ __forceinline__ void gemm_issue(
    int kb, int buf,
    const bf16* __restrict__ Ahi, const bf16* __restrict__ Alo,
    const bf16* __restrict__ Bhi, const bf16* __restrict__ Blo,
    uint32_t asb, uint32_t bsb, int m0, int n0, int srow, int schk)
{
    int k0 = kb * BK;
    uint32_t sa = asb + (uint32_t)buf * GSTAGE_B;
    uint32_t sb = bsb + (uint32_t)buf * GSTAGE_B;
    uint32_t o0 = (srow * LDSK + schk) * 2;
    uint32_t o1 = ((srow + 64) * LDSK + schk) * 2;
    size_t g0 = (size_t)(m0 + srow) * EMB + k0 + schk;
    size_t g1 = (size_t)(m0 + srow + 64) * EMB + k0 + schk;
    size_t h0 = (size_t)(n0 + srow) * EMB + k0 + schk;
    size_t h1 = (size_t)(n0 + srow + 64) * EMB + k0 + schk;
    cp16(sa + o0, Ahi + g0);
    cp16(sa + TILE_B + o0, Alo + g0);
    cp16(sa + o1, Ahi + g1);
    cp16(sa + TILE_B + o1, Alo + g1);
    cp16(sb + o0, Bhi + h0);
    cp16(sb + o1, Bhi + h1);
    cp16(sb + TILE_B + o0, Blo + h0);
    cp16(sb + TILE_B + o1, Blo + h1);
    asm volatile("cp.async.commit_group;");
}

__global__ __launch_bounds__(256, 2) void qkv_mma(
    const float* __restrict__ bq, const float* __restrict__ bk,
    const float* __restrict__ bv)
{
    extern __shared__ char dsm[];
    const uint32_t asb = (uint32_t)__cvta_generic_to_shared(dsm);
    const uint32_t bsb = asb + 2 * GSTAGE_B;

    int m0 = blockIdx.y * 128;
    int ng = blockIdx.x * BN;
    int sel = ng / EMB;
    int n0 = ng - sel * EMB;
    const bf16* Bhi = g_whi[sel];
    const bf16* Blo = g_wlo[sel];
    const float* bias = (sel == 0) ? bq : (sel == 1) ? bk : bv;
    bf16* Chi = (sel == 0) ? g_qhi : (sel == 1) ? g_khi : g_vhi;
    bf16* Clo = (sel == 0) ? g_qlo : (sel == 1) ? g_klo : g_vlo;
    float scale = (sel == 0) ? 0.125f * 1.4426950408889634f : 1.0f;

    const int tid = threadIdx.x;
    const int lane = tid & 31;
    const int wid = tid >> 5;
    const int wm = wid >> 2;
    const int wn = wid & 3;

    float acc[4][4][4];
#pragma unroll
    for (int i = 0; i < 4; i++)
#pragma unroll
        for (int j = 0; j < 4; j++)
#pragma unroll
            for (int t = 0; t < 4; t++) acc[i][j][t] = 0.f;

    const int srow = tid >> 2;
    const int schk = (tid & 3) * 8;

    const int laRow = wm * 64 + (lane & 15);
    const int laCol = (lane >> 4) * 8;
    const int lbRow = wn * 32 + ((lane >> 4) << 3) + (lane & 7);
    const int lbCol = ((lane >> 3) & 1) * 8;

    gemm_issue(0, 0, g_xhi, g_xlo, Bhi, Blo, asb, bsb, m0, n0, srow, schk);

    for (int it = 0; it < NKB; it++) {
        const int buf = it & 1;
        cp_wait<0>();
        __syncthreads();
        if (it + 1 < NKB)
            gemm_issue(it + 1, buf ^ 1, g_xhi, g_xlo, Bhi, Blo, asb, bsb,
                       m0, n0, srow, schk);

        const uint32_t sa = asb + (uint32_t)buf * GSTAGE_B;
        const uint32_t sb = bsb + (uint32_t)buf * GSTAGE_B;

#pragma unroll
        for (int ks = 0; ks < 2; ks++) {
            const uint32_t aoff = (uint32_t)(ks * 16 + laCol) * 2;
            const uint32_t boff = (uint32_t)(ks * 16 + lbCol) * 2;
            uint32_t a[4][4], a2[4][4], b[2][4];
#pragma unroll
            for (int mt = 0; mt < 4; mt++)
                ldsm4(a[mt][0], a[mt][1], a[mt][2], a[mt][3],
                      sa + (uint32_t)((laRow + mt * 16) * LDSK) * 2 + aoff);
#pragma unroll
            for (int p = 0; p < 2; p++)
                ldsm4(b[p][0], b[p][1], b[p][2], b[p][3],
                      sb + (uint32_t)((lbRow + p * 16) * LDSK) * 2 + boff);
#pragma unroll
            for (int mt = 0; mt < 4; mt++)
#pragma unroll
                for (int nt = 0; nt < 4; nt++)
                    mma16816(acc[mt][nt], a[mt],
                             b[nt >> 1][(nt & 1) * 2], b[nt >> 1][(nt & 1) * 2 + 1]);
#pragma unroll
            for (int mt = 0; mt < 4; mt++)
                ldsm4(a2[mt][0], a2[mt][1], a2[mt][2], a2[mt][3],
                      sa + TILE_B + (uint32_t)((laRow + mt * 16) * LDSK) * 2 + aoff);
#pragma unroll
            for (int mt = 0; mt < 4; mt++)
#pragma unroll
                for (int nt = 0; nt < 4; nt++)
                    mma16816(acc[mt][nt], a2[mt],
                             b[nt >> 1][(nt & 1) * 2], b[nt >> 1][(nt & 1) * 2 + 1]);
#pragma unroll
            for (int p = 0; p < 2; p++)
                ldsm4(b[p][0], b[p][1], b[p][2], b[p][3],
                      sb + TILE_B + (uint32_t)((lbRow + p * 16) * LDSK) * 2 + boff);
#pragma unroll
            for (int mt = 0; mt < 4; mt++)
#pragma unroll
                for (int nt = 0; nt < 4; nt++)
                    mma16816(acc[mt][nt], a[mt],
                             b[nt >> 1][(nt & 1) * 2], b[nt >> 1][(nt & 1) * 2 + 1]);
        }
    }

    const int er = lane >> 2;
    const int ec = (lane & 3) * 2;
#pragma unroll
    for (int mt = 0; mt < 4; mt++) {
        int m = m0 + wm * 64 + mt * 16 + er;
#pragma unroll
        for (int nt = 0; nt < 4; nt++) {
            int n = n0 + wn * 32 + nt * 8 + ec;
            float b0 = bias[n], b1 = bias[n + 1];
            float v00 = (acc[mt][nt][0] + b0) * scale;
            float v01 = (acc[mt][nt][1] + b1) * scale;
            float v10 = (acc[mt][nt][2] + b0) * scale;
            float v11 = (acc[mt][nt][3] + b1) * scale;
            int h = n >> 6, d = n & 63;
            int bb0 = m >> 11, s0 = m & 2047;
            int bb1 = (m + 8) >> 11, s1 = (m + 8) & 2047;
            size_t p0 = (((size_t)(bb0 * NH + h)) * SEQ + s0) * HD + d;
            size_t p1 = (((size_t)(bb1 * NH + h)) * SEQ + s1) * HD + d;
            uint32_t hp = cvt_bf2(v00, v01);
            uint32_t lp = cvt_bf2(v00 - bflo(hp), v01 - bfhi(hp));
            *(uint32_t*)&Chi[p0] = hp;
            *(uint32_t*)&Clo[p0] = lp;
            hp = cvt_bf2(v10, v11);
            lp = cvt_bf2(v10 - bflo(hp), v11 - bfhi(hp));
            *(uint32_t*)&Chi[p1] = hp;
            *(uint32_t*)&Clo[p1] = lp;
        }
    }
}

// =================================================================
// OUT projection: BM=128 x BN=96 -> 32x8 = 256 CTAs = ONE WAVE.
// 8 warps as 4m x 2n; warp tile 32x96 (MT=2 a-frags, 6 n-tiles).
// Stage: [Ahi 128r][Alo 128r][Bhi 96r][Blo 96r] = 35840 B, 2 stages.
// =================================================================
#define OBN 96
#define O_AT 10240u                    // 128 * 40 * 2
#define O_BT 7680u                     // 96 * 40 * 2
#define O_STAGE (2u * O_AT + 2u * O_BT)   // 35840
#define OUT_SMEM (2 * O_STAGE)         // 71680

__device__ __forceinline__ void out_issue(
    int kb, int buf, uint32_t base, int m0, int n0, int srow, int schk)
{
    int k0 = kb * BK;
    uint32_t sa = base + (uint32_t)buf * O_STAGE;
    uint32_t sb = sa + 2u * O_AT;
    uint32_t o0 = (srow * LDSK + schk) * 2;
    uint32_t o1 = ((srow + 64) * LDSK + schk) * 2;
    size_t g0 = (size_t)(m0 + srow) * EMB + k0 + schk;
    size_t g1 = (size_t)(m0 + srow + 64) * EMB + k0 + schk;
    size_t h0 = (size_t)(n0 + srow) * EMB + k0 + schk;
    cp16(sa + o0, g_aohi + g0);
    cp16(sa + O_AT + o0, g_aolo + g0);
    cp16(sa + o1, g_aohi + g1);
    cp16(sa + O_AT + o1, g_aolo + g1);
    cp16(sb + o0, g_whi[3] + h0);
    cp16(sb + O_BT + o0, g_wlo[3] + h0);
    if (srow < 32) {
        size_t h1 = (size_t)(n0 + srow + 64) * EMB + k0 + schk;
        cp16(sb + o1, g_whi[3] + h1);
        cp16(sb + O_BT + o1, g_wlo[3] + h1);
    }
    asm volatile("cp.async.commit_group;");
}

__global__ __launch_bounds__(256, 2) void out_mma(
    const float* __restrict__ bo, float* __restrict__ out)
{
    extern __shared__ char dsm[];
    const uint32_t base = (uint32_t)__cvta_generic_to_shared(dsm);

    const int m0 = blockIdx.x * 128;
    const int n0 = blockIdx.y * OBN;

    const int tid = threadIdx.x;
    const int lane = tid & 31;
    const int wid = tid >> 5;
    const int wm = wid >> 1;            // 0..3 (32 rows each)
    const int wn = wid & 1;             // 0..1 (48 cols each)

    float acc[2][6][4];
#pragma unroll
    for (int i = 0; i < 2; i++)
#pragma unroll
        for (int j = 0; j < 6; j++)
#pragma unroll
            for (int t = 0; t < 4; t++) acc[i][j][t] = 0.f;

    const int srow = tid >> 2;
    const int schk = (tid & 3) * 8;

    const int laRow = wm * 32 + (lane & 15);
    const int laCol = (lane >> 4) * 8;
    const int lbRowB = wn * 48 + ((lane >> 4) << 3) + (lane & 7);
    const int lbCol = ((lane >> 3) & 1) * 8;

    out_issue(0, 0, base, m0, n0, srow, schk);

    for (int it = 0; it < NKB; it++) {
        const int buf = it & 1;
        cp_wait<0>();
        __syncthreads();
        if (it + 1 < NKB)
            out_issue(it + 1, buf ^ 1, base, m0, n0, srow, schk);

        const uint32_t sa = base + (uint32_t)buf * O_STAGE;
        const uint32_t sb = sa + 2u * O_AT;

#pragma unroll
        for (int ks = 0; ks < 2; ks++) {
            const uint32_t aoff = (uint32_t)(ks * 16 + laCol) * 2;
            const uint32_t boff = (uint32_t)(ks * 16 + lbCol) * 2;
            uint32_t a[2][4], a2[2][4], b[3][4];
#pragma unroll
            for (int mt = 0; mt < 2; mt++)
                ldsm4(a[mt][0], a[mt][1], a[mt][2], a[mt][3],
                      sa + (uint32_t)((laRow + mt * 16) * LDSK) * 2 + aoff);
#pragma unroll
            for (int p = 0; p < 3; p++)
                ldsm4(b[p][0], b[p][1], b[p][2], b[p][3],
                      sb + (uint32_t)((lbRowB + p * 16) * LDSK) * 2 + boff);
#pragma unroll
            for (int mt = 0; mt < 2; mt++)
#pragma unroll
                for (int nt = 0; nt < 6; nt++)
                    mma16816(acc[mt][nt], a[mt],
                             b[nt >> 1][(nt & 1) * 2], b[nt >> 1][(nt & 1) * 2 + 1]);
#pragma unroll
            for (int mt = 0; mt < 2; mt++)
                ldsm4(a2[mt][0], a2[mt][1], a2[mt][2], a2[mt][3],
                      sa + O_AT + (uint32_t)((laRow + mt * 16) * LDSK) * 2 + aoff);
#pragma unroll
            for (int mt = 0; mt < 2; mt++)
#pragma unroll
                for (int nt = 0; nt < 6; nt++)
                    mma16816(acc[mt][nt], a2[mt],
                             b[nt >> 1][(nt & 1) * 2], b[nt >> 1][(nt & 1) * 2 + 1]);
#pragma unroll
            for (int p = 0; p < 3; p++)
                ldsm4(b[p][0], b[p][1], b[p][2], b[p][3],
                      sb + O_BT + (uint32_t)((lbRowB + p * 16) * LDSK) * 2 + boff);
#pragma unroll
            for (int mt = 0; mt < 2; mt++)
#pragma unroll
                for (int nt = 0; nt < 6; nt++)
                    mma16816(acc[mt][nt], a[mt],
                             b[nt >> 1][(nt & 1) * 2], b[nt >> 1][(nt & 1) * 2 + 1]);
        }
    }

    const int er = lane >> 2;
    const int ec = (lane & 3) * 2;
#pragma unroll
    for (int mt = 0; mt < 2; mt++) {
        int m = m0 + wm * 32 + mt * 16 + er;
#pragma unroll
        for (int nt = 0; nt < 6; nt++) {
            int n = n0 + wn * 48 + nt * 8 + ec;
            float b0 = bo[n], b1 = bo[n + 1];
            *(float2*)&out[(size_t)m * EMB + n] =
                make_float2(acc[mt][nt][0] + b0, acc[mt][nt][1] + b1);
            *(float2*)&out[(size_t)(m + 8) * EMB + n] =
                make_float2(acc[mt][nt][2] + b0, acc[mt][nt][3] + b1);
        }
    }
}

// =================================================================
// Tensor-core flash attention + split-KV + in-kernel combine
// (round-14 config, byte-identical)
// =================================================================
#define STR 72
#define KV_STAGE_B (256 * STR * 2)       // 36864
#define ATT_SMEM (3 * KV_STAGE_B)        // 110592

__device__ __forceinline__ void kv_issue(uint32_t sb, int buf, int kbase,
                                         const bf16* const kvsrc[4], int tid)
{
    uint32_t base = sb + (uint32_t)buf * KV_STAGE_B;
#pragma unroll
    for (int i = 0; i < 8; i++) {
        int c = i * 256 + tid;
        int row = (c >> 3) & 63;
        int ch = (c & 7) * 8;
        cp16(base + (uint32_t)(((i >> 1) * 64 + row) * STR + ch) * 2,
             kvsrc[i >> 1] + (size_t)(kbase + row) * HD + ch);
    }
    asm volatile("cp.async.commit_group;");
}

__global__ __launch_bounds__(256, 2) void attn_mma(
    const bf16* __restrict__ Qhi_g, const bf16* __restrict__ Qlo_g,
    const bf16* __restrict__ Khi_g, const bf16* __restrict__ Klo_g,
    const bf16* __restrict__ Vhi_g, const bf16* __restrict__ Vlo_g,
    bf16* __restrict__ AOhi, bf16* __restrict__ AOlo,
    float* __restrict__ PO, float* __restrict__ PL)
{
    extern __shared__ char dsm[];
    __shared__ int sflag;
    const uint32_t sb = (uint32_t)__cvta_generic_to_shared(dsm);

    const int bid = blockIdx.x;
    const int unit = bid / (BATCH * NH);
    const int bh = bid % (BATCH * NH);
    const int qt = UQT[unit];
    const int hf = UHF[unit];
    const int qbase = qt * 128;
    int kstart, nktl;
    if (hf == 2) { kstart = 0; nktl = 2 * qt + 2; }
    else         { nktl = qt + 1; kstart = hf * nktl; }

    const int tid = threadIdx.x;
    const int lane = tid & 31;
    const int wid = tid >> 5;
    const int wr = wid * 16;

    const size_t hoff = (size_t)bh * SEQ * HD;
    const bf16* qsrc[2] = {Qhi_g + hoff, Qlo_g + hoff};
    const bf16* kvsrc[4] = {Khi_g + hoff, Klo_g + hoff, Vhi_g + hoff, Vlo_g + hoff};

#pragma unroll
    for (int i = 0; i < 8; i++) {
        int c = i * 256 + tid;
        int row = (c >> 3) & 127;
        int ch = (c & 7) * 8;
        cp16(sb + (uint32_t)(((i >> 2) * 128 + row) * STR + ch) * 2,
             qsrc[i >> 2] + (size_t)(qbase + row) * HD + ch);
    }
    asm volatile("cp.async.commit_group;");
    cp_wait<0>();
    __syncthreads();

    uint32_t qh[4][4], ql[4][4];
    {
        int arow = wr + (lane & 15);
        int acol = (lane >> 4) * 8;
#pragma unroll
        for (int ks = 0; ks < 4; ks++) {
            ldsm4(qh[ks][0], qh[ks][1], qh[ks][2], qh[ks][3],
                  sb + (uint32_t)(arow * STR + ks * 16 + acol) * 2);
            ldsm4(ql[ks][0], ql[ks][1], ql[ks][2], ql[ks][3],
                  sb + (uint32_t)((128 + arow) * STR + ks * 16 + acol) * 2);
        }
    }
    __syncthreads();

    float o[8][4];
#pragma unroll
    for (int i = 0; i < 8; i++)
#pragma unroll
        for (int j = 0; j < 4; j++) o[i][j] = 0.f;
    float rs0 = 0.f, rs1 = 0.f;

    kv_issue(sb, 0, kstart * 64, kvsrc, tid);
    kv_issue(sb, 1, (kstart + 1) * 64, kvsrc, tid);

    const int brow = (lane & 7) + ((lane >> 4) << 3);
    const int bcol = ((lane >> 3) & 1) * 8;
    const int vrow = (lane & 7) + (((lane >> 3) & 1) << 3);
    const int vcol = (lane >> 4) * 8;

    int st = 0;
    for (int kt = 0; kt < nktl; kt++) {
        if (kt + 1 < nktl) cp_wait<1>(); else cp_wait<0>();
        __syncthreads();
        if (kt + 2 < nktl) {
            int b2 = st + 2; if (b2 >= 3) b2 -= 3;
            kv_issue(sb, b2, (kstart + kt + 2) * 64, kvsrc, tid);
        }

        const uint32_t kvb = sb + (uint32_t)st * KV_STAGE_B;
        const uint32_t Khi_s = kvb;
        const uint32_t Klo_s = kvb + 64 * STR * 2;
        const uint32_t Vhi_s = kvb + 128 * STR * 2;
        const uint32_t Vlo_s = kvb + 192 * STR * 2;
        const int kbase = (kstart + kt) * 64;

        float s[8][4];
#pragma unroll
        for (int i = 0; i < 8; i++)
#pragma unroll
            for (int j = 0; j < 4; j++) s[i][j] = 0.f;

#pragma unroll
        for (int ks = 0; ks < 4; ks++) {
            uint32_t bb[4][4];
#pragma unroll
            for (int ng = 0; ng < 4; ng++)
                ldsm4(bb[ng][0], bb[ng][1], bb[ng][2], bb[ng][3],
                      Khi_s + (uint32_t)((16 * ng + brow) * STR + 16 * ks + bcol) * 2);
#pragma unroll
            for (int ng = 0; ng < 4; ng++) {
                mma16816(s[2 * ng], qh[ks], bb[ng][0], bb[ng][1]);
                mma16816(s[2 * ng + 1], qh[ks], bb[ng][2], bb[ng][3]);
                mma16816(s[2 * ng], ql[ks], bb[ng][0], bb[ng][1]);
                mma16816(s[2 * ng + 1], ql[ks], bb[ng][2], bb[ng][3]);
            }
#pragma unroll
            for (int ng = 0; ng < 4; ng++)
                ldsm4(bb[ng][0], bb[ng][1], bb[ng][2], bb[ng][3],
                      Klo_s + (uint32_t)((16 * ng + brow) * STR + 16 * ks + bcol) * 2);
#pragma unroll
            for (int ng = 0; ng < 4; ng++) {
                mma16816(s[2 * ng], qh[ks], bb[ng][0], bb[ng][1]);
                mma16816(s[2 * ng + 1], qh[ks], bb[ng][2], bb[ng][3]);
            }
        }

        const bool diag = (kbase + 63 > qbase + wr);
        const int row0q = qbase + wr + (lane >> 2);
        const int colbq = kbase + 2 * (lane & 3);

#pragma unroll
        for (int t = 0; t < 4; t++) {
            if (diag) {
#pragma unroll
                for (int h2 = 0; h2 < 2; h2++) {
                    int nt = 2 * t + h2;
                    int c0 = colbq + nt * 8;
                    if (c0 > row0q) s[nt][0] = -1e30f;
                    if (c0 + 1 > row0q) s[nt][1] = -1e30f;
                    if (c0 > row0q + 8) s[nt][2] = -1e30f;
                    if (c0 + 1 > row0q + 8) s[nt][3] = -1e30f;
                }
            }
            uint32_t phi[4], plo[4];
#pragma unroll
            for (int h2 = 0; h2 < 2; h2++) {
                float* sp = s[2 * t + h2];
                sp[0] = ex2f(sp[0]); rs0 += sp[0];
                sp[1] = ex2f(sp[1]); rs0 += sp[1];
                sp[2] = ex2f(sp[2]); rs1 += sp[2];
                sp[3] = ex2f(sp[3]); rs1 += sp[3];
                uint32_t h0 = cvt_bf2(sp[0], sp[1]);
                phi[h2 * 2] = h0;
                plo[h2 * 2] = cvt_bf2(sp[0] - bflo(h0), sp[1] - bfhi(h0));
                uint32_t h1 = cvt_bf2(sp[2], sp[3]);
                phi[h2 * 2 + 1] = h1;
                plo[h2 * 2 + 1] = cvt_bf2(sp[2] - bflo(h1), sp[3] - bfhi(h1));
            }
            uint32_t vb[4][4];
#pragma unroll
            for (int g = 0; g < 4; g++)
                ldsm4t(vb[g][0], vb[g][1], vb[g][2], vb[g][3],
                       Vhi_s + (uint32_t)((16 * t + vrow) * STR + 16 * g + vcol) * 2);
#pragma unroll
            for (int g = 0; g < 4; g++) {
                mma16816(o[2 * g], phi, vb[g][0], vb[g][1]);
                mma16816(o[2 * g + 1], phi, vb[g][2], vb[g][3]);
                mma16816(o[2 * g], plo, vb[g][0], vb[g][1]);
                mma16816(o[2 * g + 1], plo, vb[g][2], vb[g][3]);
            }
#pragma unroll
            for (int g = 0; g < 4; g++)
                ldsm4t(vb[g][0], vb[g][1], vb[g][2], vb[g][3],
                       Vlo_s + (uint32_t)((16 * t + vrow) * STR + 16 * g + vcol) * 2);
#pragma unroll
            for (int g = 0; g < 4; g++) {
                mma16816(o[2 * g], phi, vb[g][0], vb[g][1]);
                mma16816(o[2 * g + 1], phi, vb[g][2], vb[g][3]);
            }
        }

        st = (st + 1 == 3) ? 0 : st + 1;
    }

    rs0 += __shfl_xor_sync(0xffffffffu, rs0, 1);
    rs0 += __shfl_xor_sync(0xffffffffu, rs0, 2);
    rs1 += __shfl_xor_sync(0xffffffffu, rs1, 1);
    rs1 += __shfl_xor_sync(0xffffffffu, rs1, 2);

    const int rl = wr + (lane >> 2);
    const int cb = 2 * (lane & 3);
    const int b = bh / NH, h = bh % NH;

    if (hf != 2) {
        const int tile = bh * 8 + (qt - 8);
        {
            int sidx = tile * 2 + hf;
            float* po = PO + (size_t)sidx * (128 * 64);
            float* pl = PL + (size_t)sidx * 128;
#pragma unroll
            for (int nd = 0; nd < 8; nd++) {
                *(float2*)&po[rl * 64 + cb + nd * 8] = make_float2(o[nd][0], o[nd][1]);
                *(float2*)&po[(rl + 8) * 64 + cb + nd * 8] = make_float2(o[nd][2], o[nd][3]);
            }
            if ((lane & 3) == 0) { pl[rl] = rs0; pl[rl + 8] = rs1; }
        }
        __syncthreads();
        if (tid == 0) {
            __threadfence();
            sflag = atomicAdd(&g_cnt[tile], 1);
        }
        __syncthreads();
        if (sflag == 0) return;
        if (tid == 0) g_cnt[tile] = 0;

        const int pidx = tile * 2 + (hf ^ 1);
        const float* qo = PO + (size_t)pidx * (128 * 64);
        const float* qls = PL + (size_t)pidx * 128;
        float inv0 = 1.f / (rs0 + qls[rl]);
        float inv1 = 1.f / (rs1 + qls[rl + 8]);
        size_t off0 = ((size_t)b * SEQ + qbase + rl) * EMB + h * HD + cb;
        size_t off1 = off0 + 8 * (size_t)EMB;
#pragma unroll
        for (int nd = 0; nd < 8; nd++) {
            float2 x0 = *(const float2*)&qo[rl * 64 + cb + nd * 8];
            float2 x1 = *(const float2*)&qo[(rl + 8) * 64 + cb + nd * 8];
            float f0 = (o[nd][0] + x0.x) * inv0, f1 = (o[nd][1] + x0.y) * inv0;
            uint32_t hp = cvt_bf2(f0, f1);
            uint32_t lp = cvt_bf2(f0 - bflo(hp), f1 - bfhi(hp));
            *(uint32_t*)&AOhi[off0 + nd * 8] = hp;
            *(uint32_t*)&AOlo[off0 + nd * 8] = lp;
            float g0 = (o[nd][2] + x1.x) * inv1, g1 = (o[nd][3] + x1.y) * inv1;
            uint32_t hq = cvt_bf2(g0, g1);
            uint32_t lq = cvt_bf2(g0 - bflo(hq), g1 - bfhi(hq));
            *(uint32_t*)&AOhi[off1 + nd * 8] = hq;
            *(uint32_t*)&AOlo[off1 + nd * 8] = lq;
        }
        return;
    }

    float inv0 = 1.f / rs0, inv1 = 1.f / rs1;
    size_t off0 = ((size_t)b * SEQ + qbase + rl) * EMB + h * HD + cb;
    size_t off1 = off0 + 8 * (size_t)EMB;
#pragma unroll
    for (int nd = 0; nd < 8; nd++) {
        float f0 = o[nd][0] * inv0, f1 = o[nd][1] * inv0;
        uint32_t hp = cvt_bf2(f0, f1);
        uint32_t lp = cvt_bf2(f0 - bflo(hp), f1 - bfhi(hp));
        *(uint32_t*)&AOhi[off0 + nd * 8] = hp;
        *(uint32_t*)&AOlo[off0 + nd * 8] = lp;
        float g0 = o[nd][2] * inv1, g1 = o[nd][3] * inv1;
        uint32_t hq = cvt_bf2(g0, g1);
        uint32_t lq = cvt_bf2(g0 - bflo(hq), g1 - bfhi(hq));
        *(uint32_t*)&AOhi[off1 + nd * 8] = hq;
        *(uint32_t*)&AOlo[off1 + nd * 8] = lq;
    }
}

// =================================================================
// launch
// =================================================================
extern "C" void kernel_launch(void* const* d_in, const int* in_sizes, int n_in,
                              void* d_out, int out_size)
{
    const float* x    = (const float*)d_in[0];
    const float* wq_b = (const float*)d_in[2];
    const float* wk_b = (const float*)d_in[4];
    const float* wv_b = (const float*)d_in[6];
    const float* wo_b = (const float*)d_in[8];
    float* out = (float*)d_out;

    bf16 *xhi, *xlo;
    bf16 *qhi, *qlo, *khi, *klo, *vhi, *vlo, *aohi, *aolo;
    float *po, *pl;
    cudaGetSymbolAddress((void**)&xhi, g_xhi);
    cudaGetSymbolAddress((void**)&xlo, g_xlo);
    cudaGetSymbolAddress((void**)&qhi, g_qhi);
    cudaGetSymbolAddress((void**)&qlo, g_qlo);
    cudaGetSymbolAddress((void**)&khi, g_khi);
    cudaGetSymbolAddress((void**)&klo, g_klo);
    cudaGetSymbolAddress((void**)&vhi, g_vhi);
    cudaGetSymbolAddress((void**)&vlo, g_vlo);
    cudaGetSymbolAddress((void**)&aohi, g_aohi);
    cudaGetSymbolAddress((void**)&aolo, g_aolo);
    cudaGetSymbolAddress((void**)&po, g_po);
    cudaGetSymbolAddress((void**)&pl, g_pl);

    cudaFuncSetAttribute(attn_mma,
                         cudaFuncAttributeMaxDynamicSharedMemorySize, ATT_SMEM);
    cudaFuncSetAttribute(qkv_mma,
                         cudaFuncAttributeMaxDynamicSharedMemorySize, GEMM_SMEM);
    cudaFuncSetAttribute(out_mma,
                         cudaFuncAttributeMaxDynamicSharedMemorySize, OUT_SMEM);

    split_all_kernel<<<4 * WB + XB, 256>>>(
        x, (const float*)d_in[1], (const float*)d_in[3],
        (const float*)d_in[5], (const float*)d_in[7], xhi, xlo);

    dim3 gqkv(NQKV / BN, MROWS / 128);             // 18 x 32 = 576
    qkv_mma<<<gqkv, 256, GEMM_SMEM>>>(wq_b, wk_b, wv_b);

    attn_mma<<<24 * BATCH * NH, 256, ATT_SMEM>>>(
        qhi, qlo, khi, klo, vhi, vlo, aohi, aolo, po, pl);

    dim3 go(MROWS / 128, EMB / OBN);               // 32 x 8 = 256 = one wave
    out_mma<<<go, 256, OUT_SMEM>>>(wo_b, out);
}